// round 1
// baseline (speedup 1.0000x reference)
#include <cuda_runtime.h>
#include <cuda_bf16.h>
#include <math.h>

// ---------------------------------------------------------------------------
// DiT block, fp32 baseline.
// B=4, N=1024, H=1024, heads=16, d=64, D_FF=4096
// ---------------------------------------------------------------------------

#define Bsz 4
#define Ntok 1024
#define Hdim 1024
#define NH 16
#define HD 64
#define DFF 4096
#define ROWS (Bsz * Ntok)      // 4096
#define CM_STRIDE (6 * Hdim)   // 6144

// ------------------------- scratch (device globals) ------------------------
__device__ float g_cm[Bsz * CM_STRIDE];          // 24K
__device__ float g_xm[ROWS * Hdim];              // 16MB
__device__ float g_qkv[ROWS * 3 * Hdim];         // 48MB
__device__ float g_scores[(size_t)Bsz * NH * Ntok * Ntok]; // 256MB
__device__ float g_attnout[ROWS * Hdim];         // 16MB
__device__ float g_x2[ROWS * Hdim];              // 16MB
__device__ float g_xm2[ROWS * Hdim];             // 16MB
__device__ float g_hid[ROWS * DFF];              // 64MB

// ------------------------- cond modulation ---------------------------------
// cm[b, j] = sum_k silu(c[b,k]) * w_mod[k, j] + b_mod[j]
__global__ void cond_mod_kernel(const float* __restrict__ c,
                                const float* __restrict__ w,
                                const float* __restrict__ bmod,
                                float* __restrict__ cm)
{
    int b = blockIdx.y;
    int j = blockIdx.x * 256 + threadIdx.x;   // gridDim.x = 24 -> j in [0,6144)
    __shared__ float sc[Hdim];
    for (int i = threadIdx.x; i < Hdim; i += 256) {
        float t = c[b * Hdim + i];
        sc[i] = t / (1.0f + expf(-t));
    }
    __syncthreads();
    float acc = 0.0f;
    #pragma unroll 4
    for (int k = 0; k < Hdim; k++)
        acc += sc[k] * w[(size_t)k * CM_STRIDE + j];
    cm[b * CM_STRIDE + j] = acc + bmod[j];
}

// ------------------------- LayerNorm + modulate ----------------------------
// out[row,:] = ln(x[row,:]) * (1 + scale[b,:]) + shift[b,:]
__global__ void ln_mod_kernel(const float* __restrict__ x,
                              const float* __restrict__ cm,
                              int shiftOff, int scaleOff,
                              float* __restrict__ out)
{
    int row = blockIdx.x;          // 0..4095
    int b = row >> 10;
    const float* xr = x + (size_t)row * Hdim;
    int tid = threadIdx.x;         // 256 threads
    float vals[4];
    float s = 0.0f, sq = 0.0f;
    #pragma unroll
    for (int i = 0; i < 4; i++) {
        float t = xr[tid + i * 256];
        vals[i] = t;
        s += t;
        sq += t * t;
    }
    #pragma unroll
    for (int o = 16; o > 0; o >>= 1) {
        s  += __shfl_down_sync(0xffffffffu, s,  o);
        sq += __shfl_down_sync(0xffffffffu, sq, o);
    }
    __shared__ float red[20];
    int warp = tid >> 5, lane = tid & 31;
    if (lane == 0) { red[warp] = s; red[warp + 8] = sq; }
    __syncthreads();
    if (tid == 0) {
        float S = 0.0f, SQ = 0.0f;
        #pragma unroll
        for (int w = 0; w < 8; w++) { S += red[w]; SQ += red[w + 8]; }
        float mu = S * (1.0f / Hdim);
        float var = SQ * (1.0f / Hdim) - mu * mu;
        red[16] = mu;
        red[17] = rsqrtf(var + 1e-5f);
    }
    __syncthreads();
    float mu = red[16], inv = red[17];
    const float* sh = cm + b * CM_STRIDE + shiftOff;
    const float* sc = cm + b * CM_STRIDE + scaleOff;
    #pragma unroll
    for (int i = 0; i < 4; i++) {
        int col = tid + i * 256;
        float xn = (vals[i] - mu) * inv;
        out[(size_t)row * Hdim + col] = xn * (1.0f + sc[col]) + sh[col];
    }
}

// ------------------------- generic SGEMM -----------------------------------
// C[M,N] = A[M,K] @ B[K,N] + bias, with fused epilogues.
// EPI 0: none; 1: exact GELU; 2: v*(1+gate); 3: resid + gate*v
#define BM 128
#define BN 128
#define BK 8
#define TM 8
#define TN 8

template<int EPI>
__global__ __launch_bounds__(256)
void sgemm_kernel(const float* __restrict__ A, const float* __restrict__ B,
                  const float* __restrict__ bias, float* __restrict__ C,
                  int M, int N, int K,
                  const float* __restrict__ gate,   // base already offset; gate[b*6144+col]
                  const float* __restrict__ resid)
{
    __shared__ float As[BK][BM];
    __shared__ float Bs[BK][BN];
    int tid = threadIdx.x;
    int tr = tid / (BN / TN);   // 0..15
    int tc = tid % (BN / TN);   // 0..15
    const int rowBase = blockIdx.y * BM;
    const int colBase = blockIdx.x * BN;

    int aRow = tid >> 1;            // 0..127
    int aCol = (tid & 1) * 4;       // 0 or 4
    int bRow = tid >> 5;            // 0..7
    int bCol = (tid & 31) * 4;      // 0..124

    float acc[TM][TN] = {};
    const float* Aptr = A + (size_t)rowBase * K;
    const float* Bptr = B + colBase;

    for (int kt = 0; kt < K; kt += BK) {
        float4 av = *(const float4*)(Aptr + (size_t)aRow * K + kt + aCol);
        As[aCol + 0][aRow] = av.x;
        As[aCol + 1][aRow] = av.y;
        As[aCol + 2][aRow] = av.z;
        As[aCol + 3][aRow] = av.w;
        float4 bv = *(const float4*)(Bptr + (size_t)(kt + bRow) * N + bCol);
        *(float4*)&Bs[bRow][bCol] = bv;
        __syncthreads();
        #pragma unroll
        for (int kk = 0; kk < BK; kk++) {
            float ra[TM], rb[TN];
            #pragma unroll
            for (int i = 0; i < TM; i++) ra[i] = As[kk][tr * TM + i];
            #pragma unroll
            for (int j = 0; j < TN; j++) rb[j] = Bs[kk][tc * TN + j];
            #pragma unroll
            for (int i = 0; i < TM; i++)
                #pragma unroll
                for (int j = 0; j < TN; j++)
                    acc[i][j] += ra[i] * rb[j];
        }
        __syncthreads();
    }

    #pragma unroll
    for (int i = 0; i < TM; i++) {
        int r = rowBase + tr * TM + i;
        int b = r >> 10;
        #pragma unroll
        for (int j = 0; j < TN; j++) {
            int cidx = colBase + tc * TN + j;
            float v = acc[i][j] + bias[cidx];
            if (EPI == 1) {
                v = 0.5f * v * (1.0f + erff(v * 0.70710678118654752f));
            } else if (EPI == 2) {
                float g = gate[b * CM_STRIDE + cidx];
                v = v * (1.0f + g);
            } else if (EPI == 3) {
                float g = gate[b * CM_STRIDE + cidx];
                v = resid[(size_t)r * N + cidx] + g * v;
            }
            C[(size_t)r * N + cidx] = v;
        }
    }
}

// ------------------------- attention: scores -------------------------------
// scores[bh, q, k] = (Q[bh,q,:] . K[bh,k,:]) / 8
__global__ __launch_bounds__(256)
void attn_scores_kernel(const float* __restrict__ qkv, float* __restrict__ scores)
{
    int bh = blockIdx.z;
    int b = bh >> 4, h = bh & 15;
    int q0 = blockIdx.y * 64;
    int k0 = blockIdx.x * 64;
    __shared__ float Qs[64 * 65]; // [d][q]
    __shared__ float Ks[64 * 65]; // [d][k]
    int tid = threadIdx.x;
    #pragma unroll
    for (int it = 0; it < 16; it++) {
        int idx = tid + it * 256;
        int r = idx >> 6, d = idx & 63;
        Qs[d * 65 + r] = qkv[((size_t)(b * Ntok + q0 + r) * 3 + 0) * Hdim + h * HD + d];
        Ks[d * 65 + r] = qkv[((size_t)(b * Ntok + k0 + r) * 3 + 1) * Hdim + h * HD + d];
    }
    __syncthreads();
    int tq = (tid / 16) * 4, tk = (tid % 16) * 4;
    float acc[4][4] = {};
    #pragma unroll 4
    for (int dd = 0; dd < 64; dd++) {
        float ra[4], rb[4];
        #pragma unroll
        for (int i = 0; i < 4; i++) ra[i] = Qs[dd * 65 + tq + i];
        #pragma unroll
        for (int j = 0; j < 4; j++) rb[j] = Ks[dd * 65 + tk + j];
        #pragma unroll
        for (int i = 0; i < 4; i++)
            #pragma unroll
            for (int j = 0; j < 4; j++)
                acc[i][j] += ra[i] * rb[j];
    }
    const float scale = 0.125f;
    #pragma unroll
    for (int i = 0; i < 4; i++)
        #pragma unroll
        for (int j = 0; j < 4; j++)
            scores[(size_t)bh * Ntok * Ntok + (size_t)(q0 + tq + i) * Ntok + k0 + tk + j]
                = acc[i][j] * scale;
}

// ------------------------- attention: softmax ------------------------------
__global__ __launch_bounds__(256)
void softmax_kernel(float* __restrict__ scores)
{
    size_t row = blockIdx.x;
    float* p = scores + row * Ntok;
    int tid = threadIdx.x;
    float v[4];
    float m = -1e30f;
    #pragma unroll
    for (int i = 0; i < 4; i++) { v[i] = p[tid + i * 256]; m = fmaxf(m, v[i]); }
    #pragma unroll
    for (int o = 16; o > 0; o >>= 1)
        m = fmaxf(m, __shfl_down_sync(0xffffffffu, m, o));
    __shared__ float red[18];
    int warp = tid >> 5, lane = tid & 31;
    if (lane == 0) red[warp] = m;
    __syncthreads();
    if (tid == 0) {
        float mm = red[0];
        #pragma unroll
        for (int w = 1; w < 8; w++) mm = fmaxf(mm, red[w]);
        red[16] = mm;
    }
    __syncthreads();
    m = red[16];
    float s = 0.0f;
    #pragma unroll
    for (int i = 0; i < 4; i++) { v[i] = expf(v[i] - m); s += v[i]; }
    #pragma unroll
    for (int o = 16; o > 0; o >>= 1)
        s += __shfl_down_sync(0xffffffffu, s, o);
    if (lane == 0) red[warp + 8] = s;
    __syncthreads();
    if (tid == 0) {
        float ss = 0.0f;
        #pragma unroll
        for (int w = 0; w < 8; w++) ss += red[w + 8];
        red[17] = 1.0f / ss;
    }
    __syncthreads();
    float inv = red[17];
    #pragma unroll
    for (int i = 0; i < 4; i++) p[tid + i * 256] = v[i] * inv;
}

// ------------------------- attention: P @ V --------------------------------
__global__ __launch_bounds__(256)
void attn_av_kernel(const float* __restrict__ scores, const float* __restrict__ qkv,
                    float* __restrict__ out)
{
    int bh = blockIdx.y;
    int b = bh >> 4, h = bh & 15;
    int q0 = blockIdx.x * 64;
    __shared__ float Ps[64 * 65];  // [k][q]
    __shared__ float Vs[64 * 65];  // [k][d]
    int tid = threadIdx.x;
    int tq = (tid / 16) * 4, td = (tid % 16) * 4;
    float acc[4][4] = {};
    for (int kt = 0; kt < Ntok; kt += 64) {
        #pragma unroll
        for (int it = 0; it < 16; it++) {
            int idx = tid + it * 256;
            int r = idx >> 6, cidx = idx & 63;
            Ps[cidx * 65 + r] = scores[(size_t)bh * Ntok * Ntok + (size_t)(q0 + r) * Ntok + kt + cidx];
            Vs[r * 65 + cidx] = qkv[((size_t)(b * Ntok + kt + r) * 3 + 2) * Hdim + h * HD + cidx];
        }
        __syncthreads();
        #pragma unroll 4
        for (int kk = 0; kk < 64; kk++) {
            float rp[4], rv[4];
            #pragma unroll
            for (int i = 0; i < 4; i++) rp[i] = Ps[kk * 65 + tq + i];
            #pragma unroll
            for (int j = 0; j < 4; j++) rv[j] = Vs[kk * 65 + td + j];
            #pragma unroll
            for (int i = 0; i < 4; i++)
                #pragma unroll
                for (int j = 0; j < 4; j++)
                    acc[i][j] += rp[i] * rv[j];
        }
        __syncthreads();
    }
    #pragma unroll
    for (int i = 0; i < 4; i++)
        #pragma unroll
        for (int j = 0; j < 4; j++)
            out[(size_t)(b * Ntok + q0 + tq + i) * Hdim + h * HD + td + j] = acc[i][j];
}

// ------------------------- launch ------------------------------------------
extern "C" void kernel_launch(void* const* d_in, const int* in_sizes, int n_in,
                              void* d_out, int out_size)
{
    const float* x      = (const float*)d_in[0];
    const float* c      = (const float*)d_in[1];
    const float* w_mod  = (const float*)d_in[2];
    const float* b_mod  = (const float*)d_in[3];
    const float* w_qkv  = (const float*)d_in[4];
    const float* b_qkv  = (const float*)d_in[5];
    const float* w_proj = (const float*)d_in[6];
    const float* b_proj = (const float*)d_in[7];
    const float* w1     = (const float*)d_in[8];
    const float* b1     = (const float*)d_in[9];
    const float* w2     = (const float*)d_in[10];
    const float* b2     = (const float*)d_in[11];
    float* out = (float*)d_out;

    float *cm, *xm, *qkv, *scores, *attnout, *x2, *xm2, *hid;
    cudaGetSymbolAddress((void**)&cm,      g_cm);
    cudaGetSymbolAddress((void**)&xm,      g_xm);
    cudaGetSymbolAddress((void**)&qkv,     g_qkv);
    cudaGetSymbolAddress((void**)&scores,  g_scores);
    cudaGetSymbolAddress((void**)&attnout, g_attnout);
    cudaGetSymbolAddress((void**)&x2,      g_x2);
    cudaGetSymbolAddress((void**)&xm2,     g_xm2);
    cudaGetSymbolAddress((void**)&hid,     g_hid);

    // 1. conditioning -> modulation params
    cond_mod_kernel<<<dim3(24, 4), 256>>>(c, w_mod, b_mod, cm);

    // 2. LN + modulate (msa)
    ln_mod_kernel<<<ROWS, 256>>>(x, cm, 0, Hdim, xm);

    // 3. qkv = xm @ w_qkv + b_qkv     [4096, 3072]
    sgemm_kernel<0><<<dim3(3 * Hdim / BN, ROWS / BM), 256>>>(
        xm, w_qkv, b_qkv, qkv, ROWS, 3 * Hdim, Hdim, nullptr, nullptr);

    // 4. scores = Q K^T / sqrt(d)
    attn_scores_kernel<<<dim3(16, 16, Bsz * NH), 256>>>(qkv, scores);

    // 5. softmax
    softmax_kernel<<<Bsz * NH * Ntok, 256>>>(scores);

    // 6. out = P @ V   -> [4096, 1024]
    attn_av_kernel<<<dim3(16, Bsz * NH), 256>>>(scores, qkv, attnout);

    // 7. x2 = (attnout @ w_proj + b_proj) * (1 + gate_msa)
    sgemm_kernel<2><<<dim3(Hdim / BN, ROWS / BM), 256>>>(
        attnout, w_proj, b_proj, x2, ROWS, Hdim, Hdim, cm + 2 * Hdim, nullptr);

    // 8. LN + modulate (mlp)
    ln_mod_kernel<<<ROWS, 256>>>(x2, cm, 3 * Hdim, 4 * Hdim, xm2);

    // 9. hid = gelu(xm2 @ w1 + b1)    [4096, 4096]
    sgemm_kernel<1><<<dim3(DFF / BN, ROWS / BM), 256>>>(
        xm2, w1, b1, hid, ROWS, DFF, Hdim, nullptr, nullptr);

    // 10. out = x2 + gate_mlp * (hid @ w2 + b2)
    sgemm_kernel<3><<<dim3(Hdim / BN, ROWS / BM), 256>>>(
        hid, w2, b2, out, ROWS, Hdim, DFF, cm + 5 * Hdim, x2);
}

// round 2
// speedup vs baseline: 2.4652x; 2.4652x over previous
#include <cuda_runtime.h>
#include <cuda_bf16.h>
#include <math.h>

// ---------------------------------------------------------------------------
// DiT block: tf32 tensor-core GEMMs + fused epilogues.
// B=4, N=1024, H=1024, heads=16, d=64, D_FF=4096
// ---------------------------------------------------------------------------

#define Bsz 4
#define Ntok 1024
#define Hdim 1024
#define NH 16
#define HD 64
#define DFF 4096
#define ROWS (Bsz * Ntok)      // 4096
#define CM_STRIDE (6 * Hdim)   // 6144

// ------------------------- scratch (device globals) ------------------------
__device__ float g_cm[Bsz * CM_STRIDE];
__device__ float g_xm[ROWS * Hdim];
__device__ float g_qkv[ROWS * 3 * Hdim];
__device__ float g_scores[(size_t)Bsz * NH * Ntok * Ntok]; // 256MB
__device__ float g_attnout[ROWS * Hdim];
__device__ float g_x2[ROWS * Hdim];
__device__ float g_xm2[ROWS * Hdim];
__device__ float g_hid[ROWS * DFF];

// ------------------------- tf32 mma helpers --------------------------------
__device__ __forceinline__ unsigned f2tf(float f) {
    unsigned u;
    asm("cvt.rna.tf32.f32 %0, %1;" : "=r"(u) : "f"(f));
    return u;
}

__device__ __forceinline__ void mma_tf32(float* d, const unsigned* a, const unsigned* b) {
    asm volatile(
        "mma.sync.aligned.m16n8k8.row.col.f32.tf32.tf32.f32 "
        "{%0,%1,%2,%3},{%4,%5,%6,%7},{%8,%9},{%0,%1,%2,%3};\n"
        : "+f"(d[0]), "+f"(d[1]), "+f"(d[2]), "+f"(d[3])
        : "r"(a[0]), "r"(a[1]), "r"(a[2]), "r"(a[3]), "r"(b[0]), "r"(b[1]));
}

#define GBM 128
#define GBN 128
#define GBK 16
#define ASTR 20    // As row stride (floats): 16 + 4 pad -> conflict-free frag loads
#define BSTR 136   // Bs row stride: 128 + 8 pad -> conflict-free frag loads

// ------------------------- cond modulation ---------------------------------
__global__ void cond_mod_kernel(const float* __restrict__ c,
                                const float* __restrict__ w,
                                const float* __restrict__ bmod,
                                float* __restrict__ cm)
{
    int b = blockIdx.y;
    int j = blockIdx.x * 256 + threadIdx.x;
    __shared__ float sc[Hdim];
    for (int i = threadIdx.x; i < Hdim; i += 256) {
        float t = c[b * Hdim + i];
        sc[i] = t / (1.0f + expf(-t));
    }
    __syncthreads();
    float acc = 0.0f;
    #pragma unroll 4
    for (int k = 0; k < Hdim; k++)
        acc += sc[k] * w[(size_t)k * CM_STRIDE + j];
    cm[b * CM_STRIDE + j] = acc + bmod[j];
}

// ------------------------- LayerNorm + modulate ----------------------------
__global__ void ln_mod_kernel(const float* __restrict__ x,
                              const float* __restrict__ cm,
                              int shiftOff, int scaleOff,
                              float* __restrict__ out)
{
    int row = blockIdx.x;
    int b = row >> 10;
    const float* xr = x + (size_t)row * Hdim;
    int tid = threadIdx.x;
    float vals[4];
    float s = 0.0f, sq = 0.0f;
    #pragma unroll
    for (int i = 0; i < 4; i++) {
        float t = xr[tid + i * 256];
        vals[i] = t; s += t; sq += t * t;
    }
    #pragma unroll
    for (int o = 16; o > 0; o >>= 1) {
        s  += __shfl_down_sync(0xffffffffu, s,  o);
        sq += __shfl_down_sync(0xffffffffu, sq, o);
    }
    __shared__ float red[20];
    int warp = tid >> 5, lane = tid & 31;
    if (lane == 0) { red[warp] = s; red[warp + 8] = sq; }
    __syncthreads();
    if (tid == 0) {
        float S = 0.0f, SQ = 0.0f;
        #pragma unroll
        for (int w = 0; w < 8; w++) { S += red[w]; SQ += red[w + 8]; }
        float mu = S * (1.0f / Hdim);
        float var = SQ * (1.0f / Hdim) - mu * mu;
        red[16] = mu;
        red[17] = rsqrtf(var + 1e-5f);
    }
    __syncthreads();
    float mu = red[16], inv = red[17];
    const float* sh = cm + b * CM_STRIDE + shiftOff;
    const float* sc = cm + b * CM_STRIDE + scaleOff;
    #pragma unroll
    for (int i = 0; i < 4; i++) {
        int col = tid + i * 256;
        float xn = (vals[i] - mu) * inv;
        out[(size_t)row * Hdim + col] = xn * (1.0f + sc[col]) + sh[col];
    }
}

// ------------------------- main tf32 GEMM ----------------------------------
// C[M,N] = A[M,K] @ B[K,N] + bias, fused epilogues.
// EPI 0: none; 1: exact GELU; 2: v*(1+gate); 3: resid + gate*v
template<int EPI>
__global__ __launch_bounds__(256)
void gemm_tf32(const float* __restrict__ A, const float* __restrict__ B,
               const float* __restrict__ bias, float* __restrict__ C,
               int M, int N, int K,
               const float* __restrict__ gate, const float* __restrict__ resid)
{
    __shared__ unsigned As[2][GBM * ASTR];
    __shared__ unsigned Bs[2][GBK * BSTR];
    int tid = threadIdx.x;
    int warp = tid >> 5, lane = tid & 31;
    int warpM = warp & 3, warpN = warp >> 2;       // 4x2 warp grid
    int g = lane >> 2, r = lane & 3;
    int rowBase = blockIdx.y * GBM, colBase = blockIdx.x * GBN;

    const float* Abase = A + (size_t)rowBase * K;
    const float* Bbase = B + colBase;

    float acc[2][8][4] = {};
    int ktiles = K / GBK;

    // prologue: tile 0
    #pragma unroll
    for (int i = 0; i < 2; i++) {
        int id = tid + i * 256;
        int ar = id >> 2, ak = (id & 3) * 4;
        float4 v = *(const float4*)(Abase + (size_t)ar * K + ak);
        unsigned* p = &As[0][ar * ASTR + ak];
        p[0] = f2tf(v.x); p[1] = f2tf(v.y); p[2] = f2tf(v.z); p[3] = f2tf(v.w);
        int bk = id >> 5, bn = (id & 31) * 4;
        float4 w = *(const float4*)(Bbase + (size_t)bk * N + bn);
        unsigned* q = &Bs[0][bk * BSTR + bn];
        q[0] = f2tf(w.x); q[1] = f2tf(w.y); q[2] = f2tf(w.z); q[3] = f2tf(w.w);
    }
    __syncthreads();

    for (int kt = 0; kt < ktiles; kt++) {
        int cur = kt & 1, nxt = cur ^ 1;
        float4 va[2], vb[2];
        if (kt + 1 < ktiles) {
            #pragma unroll
            for (int i = 0; i < 2; i++) {
                int id = tid + i * 256;
                int ar = id >> 2, ak = (id & 3) * 4;
                va[i] = *(const float4*)(Abase + (size_t)ar * K + (kt + 1) * GBK + ak);
                int bk = id >> 5, bn = (id & 31) * 4;
                vb[i] = *(const float4*)(Bbase + (size_t)((kt + 1) * GBK + bk) * N + bn);
            }
        }
        #pragma unroll
        for (int ks = 0; ks < 2; ks++) {
            int k0 = ks * 8;
            unsigned af[2][4], bf[8][2];
            #pragma unroll
            for (int mi = 0; mi < 2; mi++) {
                int row = warpM * 32 + mi * 16 + g;
                af[mi][0] = As[cur][row * ASTR + k0 + r];
                af[mi][1] = As[cur][(row + 8) * ASTR + k0 + r];
                af[mi][2] = As[cur][row * ASTR + k0 + r + 4];
                af[mi][3] = As[cur][(row + 8) * ASTR + k0 + r + 4];
            }
            #pragma unroll
            for (int nj = 0; nj < 8; nj++) {
                int col = warpN * 64 + nj * 8 + g;
                bf[nj][0] = Bs[cur][(k0 + r) * BSTR + col];
                bf[nj][1] = Bs[cur][(k0 + r + 4) * BSTR + col];
            }
            #pragma unroll
            for (int mi = 0; mi < 2; mi++)
                #pragma unroll
                for (int nj = 0; nj < 8; nj++)
                    mma_tf32(acc[mi][nj], af[mi], bf[nj]);
        }
        if (kt + 1 < ktiles) {
            #pragma unroll
            for (int i = 0; i < 2; i++) {
                int id = tid + i * 256;
                int ar = id >> 2, ak = (id & 3) * 4;
                unsigned* p = &As[nxt][ar * ASTR + ak];
                p[0] = f2tf(va[i].x); p[1] = f2tf(va[i].y);
                p[2] = f2tf(va[i].z); p[3] = f2tf(va[i].w);
                int bk = id >> 5, bn = (id & 31) * 4;
                unsigned* q = &Bs[nxt][bk * BSTR + bn];
                q[0] = f2tf(vb[i].x); q[1] = f2tf(vb[i].y);
                q[2] = f2tf(vb[i].z); q[3] = f2tf(vb[i].w);
            }
        }
        __syncthreads();
    }

    // epilogue
    #pragma unroll
    for (int mi = 0; mi < 2; mi++) {
        #pragma unroll
        for (int rr = 0; rr < 2; rr++) {
            int row = rowBase + warpM * 32 + mi * 16 + g + rr * 8;
            int b = row >> 10;
            #pragma unroll
            for (int nj = 0; nj < 8; nj++) {
                int col = colBase + warpN * 64 + nj * 8 + r * 2;
                float v0 = acc[mi][nj][rr * 2 + 0] + bias[col];
                float v1 = acc[mi][nj][rr * 2 + 1] + bias[col + 1];
                if (EPI == 1) {
                    v0 = 0.5f * v0 * (1.0f + erff(v0 * 0.70710678118654752f));
                    v1 = 0.5f * v1 * (1.0f + erff(v1 * 0.70710678118654752f));
                } else if (EPI == 2) {
                    v0 *= (1.0f + gate[b * CM_STRIDE + col]);
                    v1 *= (1.0f + gate[b * CM_STRIDE + col + 1]);
                } else if (EPI == 3) {
                    v0 = resid[(size_t)row * N + col]     + gate[b * CM_STRIDE + col]     * v0;
                    v1 = resid[(size_t)row * N + col + 1] + gate[b * CM_STRIDE + col + 1] * v1;
                }
                *(float2*)&C[(size_t)row * N + col] = make_float2(v0, v1);
            }
        }
    }
}

// ------------------------- attention scores (tf32 mma) ---------------------
// scores[bh, q, k] = (Q . K) / 8   ; 128x128 tile, K=64 (4 k-iters)
__global__ __launch_bounds__(256)
void attn_scores_mma(const float* __restrict__ qkv, float* __restrict__ scores)
{
    __shared__ unsigned As[2][GBM * ASTR];
    __shared__ unsigned Bs[2][GBK * BSTR];
    int tid = threadIdx.x;
    int warp = tid >> 5, lane = tid & 31;
    int warpM = warp & 3, warpN = warp >> 2;
    int g = lane >> 2, r = lane & 3;

    int bh = blockIdx.z;
    int b = bh >> 4, h = bh & 15;
    int q0 = blockIdx.y * 128;
    int n0 = blockIdx.x * 128;   // key tile

    float acc[2][8][4] = {};
    const int ktiles = HD / GBK;   // 4

    // loaders: A = Q[q0+ar][kt*16+ak]; B^T: Bs[d][key]
    #pragma unroll
    for (int i = 0; i < 2; i++) {
        int id = tid + i * 256;
        int ar = id >> 2, ak = (id & 3) * 4;
        const float* qp = qkv + ((size_t)(b * Ntok + q0 + ar) * 3) * Hdim + h * HD + ak;
        float4 v = *(const float4*)qp;
        unsigned* p = &As[0][ar * ASTR + ak];
        p[0] = f2tf(v.x); p[1] = f2tf(v.y); p[2] = f2tf(v.z); p[3] = f2tf(v.w);
        int key = id >> 2, dq = (id & 3) * 4;
        const float* kp = qkv + ((size_t)(b * Ntok + n0 + key) * 3 + 1) * Hdim + h * HD + dq;
        float4 w = *(const float4*)kp;
        Bs[0][(dq + 0) * BSTR + key] = f2tf(w.x);
        Bs[0][(dq + 1) * BSTR + key] = f2tf(w.y);
        Bs[0][(dq + 2) * BSTR + key] = f2tf(w.z);
        Bs[0][(dq + 3) * BSTR + key] = f2tf(w.w);
    }
    __syncthreads();

    for (int kt = 0; kt < ktiles; kt++) {
        int cur = kt & 1, nxt = cur ^ 1;
        float4 va[2], vb[2];
        if (kt + 1 < ktiles) {
            #pragma unroll
            for (int i = 0; i < 2; i++) {
                int id = tid + i * 256;
                int ar = id >> 2, ak = (id & 3) * 4;
                va[i] = *(const float4*)(qkv + ((size_t)(b * Ntok + q0 + ar) * 3) * Hdim
                                         + h * HD + (kt + 1) * GBK + ak);
                int key = id >> 2, dq = (id & 3) * 4;
                vb[i] = *(const float4*)(qkv + ((size_t)(b * Ntok + n0 + key) * 3 + 1) * Hdim
                                         + h * HD + (kt + 1) * GBK + dq);
            }
        }
        #pragma unroll
        for (int ks = 0; ks < 2; ks++) {
            int k0 = ks * 8;
            unsigned af[2][4], bf[8][2];
            #pragma unroll
            for (int mi = 0; mi < 2; mi++) {
                int row = warpM * 32 + mi * 16 + g;
                af[mi][0] = As[cur][row * ASTR + k0 + r];
                af[mi][1] = As[cur][(row + 8) * ASTR + k0 + r];
                af[mi][2] = As[cur][row * ASTR + k0 + r + 4];
                af[mi][3] = As[cur][(row + 8) * ASTR + k0 + r + 4];
            }
            #pragma unroll
            for (int nj = 0; nj < 8; nj++) {
                int col = warpN * 64 + nj * 8 + g;
                bf[nj][0] = Bs[cur][(k0 + r) * BSTR + col];
                bf[nj][1] = Bs[cur][(k0 + r + 4) * BSTR + col];
            }
            #pragma unroll
            for (int mi = 0; mi < 2; mi++)
                #pragma unroll
                for (int nj = 0; nj < 8; nj++)
                    mma_tf32(acc[mi][nj], af[mi], bf[nj]);
        }
        if (kt + 1 < ktiles) {
            #pragma unroll
            for (int i = 0; i < 2; i++) {
                int id = tid + i * 256;
                int ar = id >> 2, ak = (id & 3) * 4;
                unsigned* p = &As[nxt][ar * ASTR + ak];
                p[0] = f2tf(va[i].x); p[1] = f2tf(va[i].y);
                p[2] = f2tf(va[i].z); p[3] = f2tf(va[i].w);
                int key = id >> 2, dq = (id & 3) * 4;
                Bs[nxt][(dq + 0) * BSTR + key] = f2tf(vb[i].x);
                Bs[nxt][(dq + 1) * BSTR + key] = f2tf(vb[i].y);
                Bs[nxt][(dq + 2) * BSTR + key] = f2tf(vb[i].z);
                Bs[nxt][(dq + 3) * BSTR + key] = f2tf(vb[i].w);
            }
        }
        __syncthreads();
    }

    float* srow = scores + (size_t)bh * Ntok * Ntok;
    #pragma unroll
    for (int mi = 0; mi < 2; mi++) {
        #pragma unroll
        for (int rr = 0; rr < 2; rr++) {
            int row = q0 + warpM * 32 + mi * 16 + g + rr * 8;
            #pragma unroll
            for (int nj = 0; nj < 8; nj++) {
                int col = n0 + warpN * 64 + nj * 8 + r * 2;
                float v0 = acc[mi][nj][rr * 2 + 0] * 0.125f;
                float v1 = acc[mi][nj][rr * 2 + 1] * 0.125f;
                *(float2*)&srow[(size_t)row * Ntok + col] = make_float2(v0, v1);
            }
        }
    }
}

// ------------------------- softmax ------------------------------------------
__global__ __launch_bounds__(256)
void softmax_kernel(float* __restrict__ scores)
{
    size_t row = blockIdx.x;
    float* p = scores + row * Ntok;
    int tid = threadIdx.x;
    float v[4];
    float m = -1e30f;
    #pragma unroll
    for (int i = 0; i < 4; i++) { v[i] = p[tid + i * 256]; m = fmaxf(m, v[i]); }
    #pragma unroll
    for (int o = 16; o > 0; o >>= 1)
        m = fmaxf(m, __shfl_down_sync(0xffffffffu, m, o));
    __shared__ float red[18];
    int warp = tid >> 5, lane = tid & 31;
    if (lane == 0) red[warp] = m;
    __syncthreads();
    if (tid == 0) {
        float mm = red[0];
        #pragma unroll
        for (int w = 1; w < 8; w++) mm = fmaxf(mm, red[w]);
        red[16] = mm;
    }
    __syncthreads();
    m = red[16];
    float s = 0.0f;
    #pragma unroll
    for (int i = 0; i < 4; i++) { v[i] = expf(v[i] - m); s += v[i]; }
    #pragma unroll
    for (int o = 16; o > 0; o >>= 1)
        s += __shfl_down_sync(0xffffffffu, s, o);
    if (lane == 0) red[warp + 8] = s;
    __syncthreads();
    if (tid == 0) {
        float ss = 0.0f;
        #pragma unroll
        for (int w = 0; w < 8; w++) ss += red[w + 8];
        red[17] = 1.0f / ss;
    }
    __syncthreads();
    float inv = red[17];
    #pragma unroll
    for (int i = 0; i < 4; i++) p[tid + i * 256] = v[i] * inv;
}

// ------------------------- attention AV (tf32 mma) --------------------------
// out[q][d] = P[q][:] @ V[:][d]. M=128 (q tile), N=64 (d), K=1024 keys.
#define AVBN 64
#define AVBSTR 72   // 64 + 8 pad
__global__ __launch_bounds__(256)
void attn_av_mma(const float* __restrict__ scores, const float* __restrict__ qkv,
                 float* __restrict__ out)
{
    __shared__ unsigned As[2][GBM * ASTR];
    __shared__ unsigned Bs[2][GBK * AVBSTR];
    int tid = threadIdx.x;
    int warp = tid >> 5, lane = tid & 31;   // 8 warps along M
    int g = lane >> 2, r = lane & 3;

    int bh = blockIdx.y;
    int b = bh >> 4, h = bh & 15;
    int q0 = blockIdx.x * 128;

    const float* Abase = scores + (size_t)bh * Ntok * Ntok + (size_t)q0 * Ntok;

    float acc[8][4] = {};
    const int ktiles = Ntok / GBK;   // 64

    // A: 128x16 (2 f4/thr);  B: V 16x64 (1 f4/thr)
    #pragma unroll
    for (int i = 0; i < 2; i++) {
        int id = tid + i * 256;
        int ar = id >> 2, ak = (id & 3) * 4;
        float4 v = *(const float4*)(Abase + (size_t)ar * Ntok + ak);
        unsigned* p = &As[0][ar * ASTR + ak];
        p[0] = f2tf(v.x); p[1] = f2tf(v.y); p[2] = f2tf(v.z); p[3] = f2tf(v.w);
    }
    {
        int bk = tid >> 4, bn = (tid & 15) * 4;
        float4 w = *(const float4*)(qkv + ((size_t)(b * Ntok + bk) * 3 + 2) * Hdim + h * HD + bn);
        unsigned* q = &Bs[0][bk * AVBSTR + bn];
        q[0] = f2tf(w.x); q[1] = f2tf(w.y); q[2] = f2tf(w.z); q[3] = f2tf(w.w);
    }
    __syncthreads();

    for (int kt = 0; kt < ktiles; kt++) {
        int cur = kt & 1, nxt = cur ^ 1;
        float4 va[2], vb;
        if (kt + 1 < ktiles) {
            #pragma unroll
            for (int i = 0; i < 2; i++) {
                int id = tid + i * 256;
                int ar = id >> 2, ak = (id & 3) * 4;
                va[i] = *(const float4*)(Abase + (size_t)ar * Ntok + (kt + 1) * GBK + ak);
            }
            int bk = tid >> 4, bn = (tid & 15) * 4;
            vb = *(const float4*)(qkv + ((size_t)(b * Ntok + (kt + 1) * GBK + bk) * 3 + 2) * Hdim
                                  + h * HD + bn);
        }
        #pragma unroll
        for (int ks = 0; ks < 2; ks++) {
            int k0 = ks * 8;
            unsigned af[4], bf[8][2];
            int row = warp * 16 + g;
            af[0] = As[cur][row * ASTR + k0 + r];
            af[1] = As[cur][(row + 8) * ASTR + k0 + r];
            af[2] = As[cur][row * ASTR + k0 + r + 4];
            af[3] = As[cur][(row + 8) * ASTR + k0 + r + 4];
            #pragma unroll
            for (int nj = 0; nj < 8; nj++) {
                int col = nj * 8 + g;
                bf[nj][0] = Bs[cur][(k0 + r) * AVBSTR + col];
                bf[nj][1] = Bs[cur][(k0 + r + 4) * AVBSTR + col];
            }
            #pragma unroll
            for (int nj = 0; nj < 8; nj++)
                mma_tf32(acc[nj], af, bf[nj]);
        }
        if (kt + 1 < ktiles) {
            #pragma unroll
            for (int i = 0; i < 2; i++) {
                int id = tid + i * 256;
                int ar = id >> 2, ak = (id & 3) * 4;
                unsigned* p = &As[nxt][ar * ASTR + ak];
                p[0] = f2tf(va[i].x); p[1] = f2tf(va[i].y);
                p[2] = f2tf(va[i].z); p[3] = f2tf(va[i].w);
            }
            int bk = tid >> 4, bn = (tid & 15) * 4;
            unsigned* q = &Bs[nxt][bk * AVBSTR + bn];
            q[0] = f2tf(vb.x); q[1] = f2tf(vb.y); q[2] = f2tf(vb.z); q[3] = f2tf(vb.w);
        }
        __syncthreads();
    }

    #pragma unroll
    for (int rr = 0; rr < 2; rr++) {
        int row = q0 + warp * 16 + g + rr * 8;
        #pragma unroll
        for (int nj = 0; nj < 8; nj++) {
            int col = nj * 8 + r * 2;
            float v0 = acc[nj][rr * 2 + 0];
            float v1 = acc[nj][rr * 2 + 1];
            *(float2*)&out[(size_t)(b * Ntok + row) * Hdim + h * HD + col]
                = make_float2(v0, v1);
        }
    }
}

// ------------------------- launch ------------------------------------------
extern "C" void kernel_launch(void* const* d_in, const int* in_sizes, int n_in,
                              void* d_out, int out_size)
{
    const float* x      = (const float*)d_in[0];
    const float* c      = (const float*)d_in[1];
    const float* w_mod  = (const float*)d_in[2];
    const float* b_mod  = (const float*)d_in[3];
    const float* w_qkv  = (const float*)d_in[4];
    const float* b_qkv  = (const float*)d_in[5];
    const float* w_proj = (const float*)d_in[6];
    const float* b_proj = (const float*)d_in[7];
    const float* w1     = (const float*)d_in[8];
    const float* b1     = (const float*)d_in[9];
    const float* w2     = (const float*)d_in[10];
    const float* b2     = (const float*)d_in[11];
    float* out = (float*)d_out;

    float *cm, *xm, *qkv, *scores, *attnout, *x2, *xm2, *hid;
    cudaGetSymbolAddress((void**)&cm,      g_cm);
    cudaGetSymbolAddress((void**)&xm,      g_xm);
    cudaGetSymbolAddress((void**)&qkv,     g_qkv);
    cudaGetSymbolAddress((void**)&scores,  g_scores);
    cudaGetSymbolAddress((void**)&attnout, g_attnout);
    cudaGetSymbolAddress((void**)&x2,      g_x2);
    cudaGetSymbolAddress((void**)&xm2,     g_xm2);
    cudaGetSymbolAddress((void**)&hid,     g_hid);

    // 1. conditioning -> modulation params
    cond_mod_kernel<<<dim3(24, 4), 256>>>(c, w_mod, b_mod, cm);

    // 2. LN + modulate (msa)
    ln_mod_kernel<<<ROWS, 256>>>(x, cm, 0, Hdim, xm);

    // 3. qkv = xm @ w_qkv + b_qkv     [4096, 3072]
    gemm_tf32<0><<<dim3(3 * Hdim / GBN, ROWS / GBM), 256>>>(
        xm, w_qkv, b_qkv, qkv, ROWS, 3 * Hdim, Hdim, nullptr, nullptr);

    // 4. scores = Q K^T / 8
    attn_scores_mma<<<dim3(Ntok / 128, Ntok / 128, Bsz * NH), 256>>>(qkv, scores);

    // 5. softmax
    softmax_kernel<<<Bsz * NH * Ntok, 256>>>(scores);

    // 6. attnout = P @ V
    attn_av_mma<<<dim3(Ntok / 128, Bsz * NH), 256>>>(scores, qkv, attnout);

    // 7. x2 = (attnout @ w_proj + b_proj) * (1 + gate_msa)
    gemm_tf32<2><<<dim3(Hdim / GBN, ROWS / GBM), 256>>>(
        attnout, w_proj, b_proj, x2, ROWS, Hdim, Hdim, cm + 2 * Hdim, nullptr);

    // 8. LN + modulate (mlp)
    ln_mod_kernel<<<ROWS, 256>>>(x2, cm, 3 * Hdim, 4 * Hdim, xm2);

    // 9. hid = gelu(xm2 @ w1 + b1)    [4096, 4096]
    gemm_tf32<1><<<dim3(DFF / GBN, ROWS / GBM), 256>>>(
        xm2, w1, b1, hid, ROWS, DFF, Hdim, nullptr, nullptr);

    // 10. out = x2 + gate_mlp * (hid @ w2 + b2)
    gemm_tf32<3><<<dim3(Hdim / GBN, ROWS / GBM), 256>>>(
        hid, w2, b2, out, ROWS, Hdim, DFF, cm + 5 * Hdim, x2);
}

// round 3
// speedup vs baseline: 2.5950x; 1.0526x over previous
#include <cuda_runtime.h>
#include <cuda_bf16.h>
#include <math.h>

// ---------------------------------------------------------------------------
// DiT block: tf32 tensor-core GEMMs + fused flash attention.
// B=4, N=1024, H=1024, heads=16, d=64, D_FF=4096
// ---------------------------------------------------------------------------

#define Bsz 4
#define Ntok 1024
#define Hdim 1024
#define NH 16
#define HD 64
#define DFF 4096
#define ROWS (Bsz * Ntok)      // 4096
#define CM_STRIDE (6 * Hdim)   // 6144

// ------------------------- scratch (device globals) ------------------------
__device__ float g_cm[Bsz * CM_STRIDE];
__device__ float g_xm[ROWS * Hdim];
__device__ float g_qkv[ROWS * 3 * Hdim];
__device__ float g_attnout[ROWS * Hdim];
__device__ float g_x2[ROWS * Hdim];
__device__ float g_xm2[ROWS * Hdim];
__device__ float g_hid[ROWS * DFF];

// ------------------------- tf32 mma helpers --------------------------------
__device__ __forceinline__ unsigned f2tf(float f) {
    unsigned u;
    asm("cvt.rna.tf32.f32 %0, %1;" : "=r"(u) : "f"(f));
    return u;
}

__device__ __forceinline__ void mma_tf32(float* d, const unsigned* a, const unsigned* b) {
    asm volatile(
        "mma.sync.aligned.m16n8k8.row.col.f32.tf32.tf32.f32 "
        "{%0,%1,%2,%3},{%4,%5,%6,%7},{%8,%9},{%0,%1,%2,%3};\n"
        : "+f"(d[0]), "+f"(d[1]), "+f"(d[2]), "+f"(d[3])
        : "r"(a[0]), "r"(a[1]), "r"(a[2]), "r"(a[3]), "r"(b[0]), "r"(b[1]));
}

#define GBM 128
#define GBN 128
#define GBK 16
#define ASTR 20
#define BSTR 136

// ------------------------- cond modulation ---------------------------------
__global__ void cond_mod_kernel(const float* __restrict__ c,
                                const float* __restrict__ w,
                                const float* __restrict__ bmod,
                                float* __restrict__ cm)
{
    int b = blockIdx.y;
    int j = blockIdx.x * 256 + threadIdx.x;
    __shared__ float sc[Hdim];
    for (int i = threadIdx.x; i < Hdim; i += 256) {
        float t = c[b * Hdim + i];
        sc[i] = t / (1.0f + expf(-t));
    }
    __syncthreads();
    float acc = 0.0f;
    #pragma unroll 4
    for (int k = 0; k < Hdim; k++)
        acc += sc[k] * w[(size_t)k * CM_STRIDE + j];
    cm[b * CM_STRIDE + j] = acc + bmod[j];
}

// ------------------------- LayerNorm + modulate ----------------------------
__global__ void ln_mod_kernel(const float* __restrict__ x,
                              const float* __restrict__ cm,
                              int shiftOff, int scaleOff,
                              float* __restrict__ out)
{
    int row = blockIdx.x;
    int b = row >> 10;
    const float* xr = x + (size_t)row * Hdim;
    int tid = threadIdx.x;
    float vals[4];
    float s = 0.0f, sq = 0.0f;
    #pragma unroll
    for (int i = 0; i < 4; i++) {
        float t = xr[tid + i * 256];
        vals[i] = t; s += t; sq += t * t;
    }
    #pragma unroll
    for (int o = 16; o > 0; o >>= 1) {
        s  += __shfl_down_sync(0xffffffffu, s,  o);
        sq += __shfl_down_sync(0xffffffffu, sq, o);
    }
    __shared__ float red[20];
    int warp = tid >> 5, lane = tid & 31;
    if (lane == 0) { red[warp] = s; red[warp + 8] = sq; }
    __syncthreads();
    if (tid == 0) {
        float S = 0.0f, SQ = 0.0f;
        #pragma unroll
        for (int w = 0; w < 8; w++) { S += red[w]; SQ += red[w + 8]; }
        float mu = S * (1.0f / Hdim);
        float var = SQ * (1.0f / Hdim) - mu * mu;
        red[16] = mu;
        red[17] = rsqrtf(var + 1e-5f);
    }
    __syncthreads();
    float mu = red[16], inv = red[17];
    const float* sh = cm + b * CM_STRIDE + shiftOff;
    const float* sc = cm + b * CM_STRIDE + scaleOff;
    #pragma unroll
    for (int i = 0; i < 4; i++) {
        int col = tid + i * 256;
        float xn = (vals[i] - mu) * inv;
        out[(size_t)row * Hdim + col] = xn * (1.0f + sc[col]) + sh[col];
    }
}

// ------------------------- main tf32 GEMM ----------------------------------
// EPI 0: none; 1: exact GELU; 2: v*(1+gate); 3: resid + gate*v
template<int EPI>
__global__ __launch_bounds__(256)
void gemm_tf32(const float* __restrict__ A, const float* __restrict__ B,
               const float* __restrict__ bias, float* __restrict__ C,
               int M, int N, int K,
               const float* __restrict__ gate, const float* __restrict__ resid)
{
    __shared__ unsigned As[2][GBM * ASTR];
    __shared__ unsigned Bs[2][GBK * BSTR];
    int tid = threadIdx.x;
    int warp = tid >> 5, lane = tid & 31;
    int warpM = warp & 3, warpN = warp >> 2;
    int g = lane >> 2, r = lane & 3;
    int rowBase = blockIdx.y * GBM, colBase = blockIdx.x * GBN;

    const float* Abase = A + (size_t)rowBase * K;
    const float* Bbase = B + colBase;

    float acc[2][8][4] = {};
    int ktiles = K / GBK;

    #pragma unroll
    for (int i = 0; i < 2; i++) {
        int id = tid + i * 256;
        int ar = id >> 2, ak = (id & 3) * 4;
        float4 v = *(const float4*)(Abase + (size_t)ar * K + ak);
        unsigned* p = &As[0][ar * ASTR + ak];
        p[0] = f2tf(v.x); p[1] = f2tf(v.y); p[2] = f2tf(v.z); p[3] = f2tf(v.w);
        int bk = id >> 5, bn = (id & 31) * 4;
        float4 w = *(const float4*)(Bbase + (size_t)bk * N + bn);
        unsigned* q = &Bs[0][bk * BSTR + bn];
        q[0] = f2tf(w.x); q[1] = f2tf(w.y); q[2] = f2tf(w.z); q[3] = f2tf(w.w);
    }
    __syncthreads();

    for (int kt = 0; kt < ktiles; kt++) {
        int cur = kt & 1, nxt = cur ^ 1;
        float4 va[2], vb[2];
        if (kt + 1 < ktiles) {
            #pragma unroll
            for (int i = 0; i < 2; i++) {
                int id = tid + i * 256;
                int ar = id >> 2, ak = (id & 3) * 4;
                va[i] = *(const float4*)(Abase + (size_t)ar * K + (kt + 1) * GBK + ak);
                int bk = id >> 5, bn = (id & 31) * 4;
                vb[i] = *(const float4*)(Bbase + (size_t)((kt + 1) * GBK + bk) * N + bn);
            }
        }
        #pragma unroll
        for (int ks = 0; ks < 2; ks++) {
            int k0 = ks * 8;
            unsigned af[2][4], bf[8][2];
            #pragma unroll
            for (int mi = 0; mi < 2; mi++) {
                int row = warpM * 32 + mi * 16 + g;
                af[mi][0] = As[cur][row * ASTR + k0 + r];
                af[mi][1] = As[cur][(row + 8) * ASTR + k0 + r];
                af[mi][2] = As[cur][row * ASTR + k0 + r + 4];
                af[mi][3] = As[cur][(row + 8) * ASTR + k0 + r + 4];
            }
            #pragma unroll
            for (int nj = 0; nj < 8; nj++) {
                int col = warpN * 64 + nj * 8 + g;
                bf[nj][0] = Bs[cur][(k0 + r) * BSTR + col];
                bf[nj][1] = Bs[cur][(k0 + r + 4) * BSTR + col];
            }
            #pragma unroll
            for (int mi = 0; mi < 2; mi++)
                #pragma unroll
                for (int nj = 0; nj < 8; nj++)
                    mma_tf32(acc[mi][nj], af[mi], bf[nj]);
        }
        if (kt + 1 < ktiles) {
            #pragma unroll
            for (int i = 0; i < 2; i++) {
                int id = tid + i * 256;
                int ar = id >> 2, ak = (id & 3) * 4;
                unsigned* p = &As[nxt][ar * ASTR + ak];
                p[0] = f2tf(va[i].x); p[1] = f2tf(va[i].y);
                p[2] = f2tf(va[i].z); p[3] = f2tf(va[i].w);
                int bk = id >> 5, bn = (id & 31) * 4;
                unsigned* q = &Bs[nxt][bk * BSTR + bn];
                q[0] = f2tf(vb[i].x); q[1] = f2tf(vb[i].y);
                q[2] = f2tf(vb[i].z); q[3] = f2tf(vb[i].w);
            }
        }
        __syncthreads();
    }

    #pragma unroll
    for (int mi = 0; mi < 2; mi++) {
        #pragma unroll
        for (int rr = 0; rr < 2; rr++) {
            int row = rowBase + warpM * 32 + mi * 16 + g + rr * 8;
            int b = row >> 10;
            #pragma unroll
            for (int nj = 0; nj < 8; nj++) {
                int col = colBase + warpN * 64 + nj * 8 + r * 2;
                float v0 = acc[mi][nj][rr * 2 + 0] + bias[col];
                float v1 = acc[mi][nj][rr * 2 + 1] + bias[col + 1];
                if (EPI == 1) {
                    v0 = 0.5f * v0 * (1.0f + erff(v0 * 0.70710678118654752f));
                    v1 = 0.5f * v1 * (1.0f + erff(v1 * 0.70710678118654752f));
                } else if (EPI == 2) {
                    v0 *= (1.0f + gate[b * CM_STRIDE + col]);
                    v1 *= (1.0f + gate[b * CM_STRIDE + col + 1]);
                } else if (EPI == 3) {
                    v0 = resid[(size_t)row * N + col]     + gate[b * CM_STRIDE + col]     * v0;
                    v1 = resid[(size_t)row * N + col + 1] + gate[b * CM_STRIDE + col + 1] * v1;
                }
                *(float2*)&C[(size_t)row * N + col] = make_float2(v0, v1);
            }
        }
    }
}

// ------------------------- flash attention ---------------------------------
// One CTA: 128 q-rows x full key sweep for one (b,h). 8 warps, 16 q-rows each.
// Q (scaled by 1/8) lives in mma A-fragments; K/V tiles of 64 keys in smem;
// online softmax in registers; P re-staged warp-locally through smem.
#define FA_KT 64
#define KSTR 72   // [d][key] and [key][d], conflict-free for B-frag reads
#define PSTR 68   // [row][col], conflict-free for A-frag reads

__global__ __launch_bounds__(256)
void flash_attn(const float* __restrict__ qkv, float* __restrict__ out)
{
    __shared__ unsigned Ks[FA_KT * KSTR];   // K^T: [d][key]
    __shared__ unsigned Vs[FA_KT * KSTR];   // V:   [key][d]
    __shared__ unsigned Ps[128 * PSTR];     // Q staging, then P tiles

    int tid = threadIdx.x;
    int warp = tid >> 5, lane = tid & 31;
    int g = lane >> 2, r = lane & 3;
    int bh = blockIdx.y;
    int b = bh >> 4, h = bh & 15;
    int q0 = blockIdx.x * 128;

    // ---- stage Q (scaled) into Ps, coalesced ----
    #pragma unroll
    for (int i = 0; i < 8; i++) {
        int j = tid + i * 256;               // 2048 float4s
        int row = j >> 4, c4 = (j & 15) * 4;
        float4 v = *(const float4*)(qkv + ((size_t)(b * Ntok + q0 + row) * 3) * Hdim
                                    + h * HD + c4);
        unsigned* p = &Ps[row * PSTR + c4];
        p[0] = f2tf(v.x * 0.125f); p[1] = f2tf(v.y * 0.125f);
        p[2] = f2tf(v.z * 0.125f); p[3] = f2tf(v.w * 0.125f);
    }
    __syncthreads();

    int qrow = warp * 16 + g;
    unsigned qf[8][4];
    #pragma unroll
    for (int ks = 0; ks < 8; ks++) {
        int k0 = ks * 8;
        qf[ks][0] = Ps[qrow * PSTR + k0 + r];
        qf[ks][1] = Ps[(qrow + 8) * PSTR + k0 + r];
        qf[ks][2] = Ps[qrow * PSTR + k0 + r + 4];
        qf[ks][3] = Ps[(qrow + 8) * PSTR + k0 + r + 4];
    }
    __syncthreads();

    float oacc[8][4] = {};
    float m0 = -1e30f, m1 = -1e30f, l0 = 0.0f, l1 = 0.0f;

    for (int n0 = 0; n0 < Ntok; n0 += FA_KT) {
        // ---- load K (transposed) and V tiles ----
        #pragma unroll
        for (int i = 0; i < 4; i++) {
            int j = tid + i * 256;           // 1024 float4s
            int key = j >> 4, c4 = (j & 15) * 4;
            float4 kv = *(const float4*)(qkv + ((size_t)(b * Ntok + n0 + key) * 3 + 1) * Hdim
                                         + h * HD + c4);
            Ks[(c4 + 0) * KSTR + key] = f2tf(kv.x);
            Ks[(c4 + 1) * KSTR + key] = f2tf(kv.y);
            Ks[(c4 + 2) * KSTR + key] = f2tf(kv.z);
            Ks[(c4 + 3) * KSTR + key] = f2tf(kv.w);
            float4 vv = *(const float4*)(qkv + ((size_t)(b * Ntok + n0 + key) * 3 + 2) * Hdim
                                         + h * HD + c4);
            unsigned* q = &Vs[key * KSTR + c4];
            q[0] = f2tf(vv.x); q[1] = f2tf(vv.y); q[2] = f2tf(vv.z); q[3] = f2tf(vv.w);
        }
        __syncthreads();

        // ---- S = Q K^T  (16 x 64 per warp) ----
        float sacc[8][4] = {};
        #pragma unroll
        for (int ks = 0; ks < 8; ks++) {
            int k0 = ks * 8;
            #pragma unroll
            for (int nj = 0; nj < 8; nj++) {
                unsigned bf[2];
                bf[0] = Ks[(k0 + r) * KSTR + nj * 8 + g];
                bf[1] = Ks[(k0 + r + 4) * KSTR + nj * 8 + g];
                mma_tf32(sacc[nj], qf[ks], bf);
            }
        }

        // ---- online softmax (rows g and g+8) ----
        float mc0 = -1e30f, mc1 = -1e30f;
        #pragma unroll
        for (int nj = 0; nj < 8; nj++) {
            mc0 = fmaxf(mc0, fmaxf(sacc[nj][0], sacc[nj][1]));
            mc1 = fmaxf(mc1, fmaxf(sacc[nj][2], sacc[nj][3]));
        }
        mc0 = fmaxf(mc0, __shfl_xor_sync(0xffffffffu, mc0, 1));
        mc0 = fmaxf(mc0, __shfl_xor_sync(0xffffffffu, mc0, 2));
        mc1 = fmaxf(mc1, __shfl_xor_sync(0xffffffffu, mc1, 1));
        mc1 = fmaxf(mc1, __shfl_xor_sync(0xffffffffu, mc1, 2));
        float mn0 = fmaxf(m0, mc0), mn1 = fmaxf(m1, mc1);
        float a0 = __expf(m0 - mn0), a1 = __expf(m1 - mn1);
        float rs0 = 0.0f, rs1 = 0.0f;
        #pragma unroll
        for (int nj = 0; nj < 8; nj++) {
            float p0 = __expf(sacc[nj][0] - mn0);
            float p1 = __expf(sacc[nj][1] - mn0);
            float p2 = __expf(sacc[nj][2] - mn1);
            float p3 = __expf(sacc[nj][3] - mn1);
            rs0 += p0 + p1; rs1 += p2 + p3;
            Ps[qrow * PSTR + nj * 8 + 2 * r]           = f2tf(p0);
            Ps[qrow * PSTR + nj * 8 + 2 * r + 1]       = f2tf(p1);
            Ps[(qrow + 8) * PSTR + nj * 8 + 2 * r]     = f2tf(p2);
            Ps[(qrow + 8) * PSTR + nj * 8 + 2 * r + 1] = f2tf(p3);
        }
        rs0 += __shfl_xor_sync(0xffffffffu, rs0, 1);
        rs0 += __shfl_xor_sync(0xffffffffu, rs0, 2);
        rs1 += __shfl_xor_sync(0xffffffffu, rs1, 1);
        rs1 += __shfl_xor_sync(0xffffffffu, rs1, 2);
        l0 = l0 * a0 + rs0;
        l1 = l1 * a1 + rs1;
        m0 = mn0; m1 = mn1;
        #pragma unroll
        for (int nj = 0; nj < 8; nj++) {
            oacc[nj][0] *= a0; oacc[nj][1] *= a0;
            oacc[nj][2] *= a1; oacc[nj][3] *= a1;
        }
        __syncwarp();

        // ---- O += P V  (16 x 64 per warp, K = 64 keys) ----
        #pragma unroll
        for (int ks = 0; ks < 8; ks++) {
            int k0 = ks * 8;
            unsigned af[4];
            af[0] = Ps[qrow * PSTR + k0 + r];
            af[1] = Ps[(qrow + 8) * PSTR + k0 + r];
            af[2] = Ps[qrow * PSTR + k0 + r + 4];
            af[3] = Ps[(qrow + 8) * PSTR + k0 + r + 4];
            #pragma unroll
            for (int nj = 0; nj < 8; nj++) {
                unsigned bf[2];
                bf[0] = Vs[(k0 + r) * KSTR + nj * 8 + g];
                bf[1] = Vs[(k0 + r + 4) * KSTR + nj * 8 + g];
                mma_tf32(oacc[nj], af, bf);
            }
        }
        __syncthreads();
    }

    // ---- finalize: divide by l, write out ----
    float i0 = 1.0f / l0, i1 = 1.0f / l1;
    #pragma unroll
    for (int nj = 0; nj < 8; nj++) {
        int col = h * HD + nj * 8 + 2 * r;
        *(float2*)&out[(size_t)(b * Ntok + q0 + qrow) * Hdim + col]
            = make_float2(oacc[nj][0] * i0, oacc[nj][1] * i0);
        *(float2*)&out[(size_t)(b * Ntok + q0 + qrow + 8) * Hdim + col]
            = make_float2(oacc[nj][2] * i1, oacc[nj][3] * i1);
    }
}

// ------------------------- launch ------------------------------------------
extern "C" void kernel_launch(void* const* d_in, const int* in_sizes, int n_in,
                              void* d_out, int out_size)
{
    const float* x      = (const float*)d_in[0];
    const float* c      = (const float*)d_in[1];
    const float* w_mod  = (const float*)d_in[2];
    const float* b_mod  = (const float*)d_in[3];
    const float* w_qkv  = (const float*)d_in[4];
    const float* b_qkv  = (const float*)d_in[5];
    const float* w_proj = (const float*)d_in[6];
    const float* b_proj = (const float*)d_in[7];
    const float* w1     = (const float*)d_in[8];
    const float* b1     = (const float*)d_in[9];
    const float* w2     = (const float*)d_in[10];
    const float* b2     = (const float*)d_in[11];
    float* out = (float*)d_out;

    float *cm, *xm, *qkv, *attnout, *x2, *xm2, *hid;
    cudaGetSymbolAddress((void**)&cm,      g_cm);
    cudaGetSymbolAddress((void**)&xm,      g_xm);
    cudaGetSymbolAddress((void**)&qkv,     g_qkv);
    cudaGetSymbolAddress((void**)&attnout, g_attnout);
    cudaGetSymbolAddress((void**)&x2,      g_x2);
    cudaGetSymbolAddress((void**)&xm2,     g_xm2);
    cudaGetSymbolAddress((void**)&hid,     g_hid);

    // 1. conditioning -> modulation params
    cond_mod_kernel<<<dim3(24, 4), 256>>>(c, w_mod, b_mod, cm);

    // 2. LN + modulate (msa)
    ln_mod_kernel<<<ROWS, 256>>>(x, cm, 0, Hdim, xm);

    // 3. qkv = xm @ w_qkv + b_qkv     [4096, 3072]
    gemm_tf32<0><<<dim3(3 * Hdim / GBN, ROWS / GBM), 256>>>(
        xm, w_qkv, b_qkv, qkv, ROWS, 3 * Hdim, Hdim, nullptr, nullptr);

    // 4-6. fused flash attention -> attnout
    flash_attn<<<dim3(Ntok / 128, Bsz * NH), 256>>>(qkv, attnout);

    // 7. x2 = (attnout @ w_proj + b_proj) * (1 + gate_msa)
    gemm_tf32<2><<<dim3(Hdim / GBN, ROWS / GBM), 256>>>(
        attnout, w_proj, b_proj, x2, ROWS, Hdim, Hdim, cm + 2 * Hdim, nullptr);

    // 8. LN + modulate (mlp)
    ln_mod_kernel<<<ROWS, 256>>>(x2, cm, 3 * Hdim, 4 * Hdim, xm2);

    // 9. hid = gelu(xm2 @ w1 + b1)    [4096, 4096]
    gemm_tf32<1><<<dim3(DFF / GBN, ROWS / GBM), 256>>>(
        xm2, w1, b1, hid, ROWS, DFF, Hdim, nullptr, nullptr);

    // 10. out = x2 + gate_mlp * (hid @ w2 + b2)
    gemm_tf32<3><<<dim3(Hdim / GBN, ROWS / GBM), 256>>>(
        hid, w2, b2, out, ROWS, Hdim, DFF, cm + 5 * Hdim, x2);
}

// round 5
// speedup vs baseline: 4.4772x; 1.7253x over previous
#include <cuda_runtime.h>
#include <cuda_fp16.h>
#include <cuda_bf16.h>
#include <math.h>

// ---------------------------------------------------------------------------
// DiT block: fp16 tensor-core GEMMs (fp32 accum) + fused flash attention.
// B=4, N=1024, H=1024, heads=16, d=64, D_FF=4096
// ---------------------------------------------------------------------------

#define Bsz 4
#define Ntok 1024
#define Hdim 1024
#define NH 16
#define HD 64
#define DFF 4096
#define ROWS (Bsz * Ntok)      // 4096
#define CM_STRIDE (6 * Hdim)   // 6144

// ------------------------- scratch (device globals) ------------------------
__device__ float g_cm[Bsz * CM_STRIDE];
__device__ float g_xm[ROWS * Hdim];
__device__ float g_qkv[ROWS * 3 * Hdim];
__device__ float g_attnout[ROWS * Hdim];
__device__ float g_x2[ROWS * Hdim];
__device__ float g_xm2[ROWS * Hdim];
__device__ float g_hid[ROWS * DFF];

// ------------------------- fp16 mma helpers --------------------------------
__device__ __forceinline__ unsigned f2h2(float a, float b) {
    __half2 h = __floats2half2_rn(a, b);
    return *(unsigned*)&h;
}

// D += A*B, m16n8k16, f16 inputs, f32 accumulate
__device__ __forceinline__ void mma_f16(float* d, const unsigned* a, const unsigned* b) {
    asm volatile(
        "mma.sync.aligned.m16n8k16.row.col.f32.f16.f16.f32 "
        "{%0,%1,%2,%3},{%4,%5,%6,%7},{%8,%9},{%0,%1,%2,%3};\n"
        : "+f"(d[0]), "+f"(d[1]), "+f"(d[2]), "+f"(d[3])
        : "r"(a[0]), "r"(a[1]), "r"(a[2]), "r"(a[3]), "r"(b[0]), "r"(b[1]));
}

// GEMM tiles: 128x128, BK=16 (one mma k-step per tile)
#define GBM 128
#define GBN 128
#define AS2 12    // As row stride in half2 units (8 + 4 pad) -> conflict-free frags
#define BS2 136   // Bs row stride in half2 units (128 + 8)   -> conflict-free frags

// ------------------------- cond modulation ---------------------------------
__global__ void cond_mod_kernel(const float* __restrict__ c,
                                const float* __restrict__ w,
                                const float* __restrict__ bmod,
                                float* __restrict__ cm)
{
    int b = blockIdx.y;
    int j = blockIdx.x * 256 + threadIdx.x;
    __shared__ float sc[Hdim];
    for (int i = threadIdx.x; i < Hdim; i += 256) {
        float t = c[b * Hdim + i];
        sc[i] = t / (1.0f + expf(-t));
    }
    __syncthreads();
    float acc = 0.0f;
    #pragma unroll 4
    for (int k = 0; k < Hdim; k++)
        acc += sc[k] * w[(size_t)k * CM_STRIDE + j];
    cm[b * CM_STRIDE + j] = acc + bmod[j];
}

// ------------------------- LayerNorm + modulate ----------------------------
__global__ void ln_mod_kernel(const float* __restrict__ x,
                              const float* __restrict__ cm,
                              int shiftOff, int scaleOff,
                              float* __restrict__ out)
{
    int row = blockIdx.x;
    int b = row >> 10;
    const float* xr = x + (size_t)row * Hdim;
    int tid = threadIdx.x;
    float vals[4];
    float s = 0.0f, sq = 0.0f;
    #pragma unroll
    for (int i = 0; i < 4; i++) {
        float t = xr[tid + i * 256];
        vals[i] = t; s += t; sq += t * t;
    }
    #pragma unroll
    for (int o = 16; o > 0; o >>= 1) {
        s  += __shfl_down_sync(0xffffffffu, s,  o);
        sq += __shfl_down_sync(0xffffffffu, sq, o);
    }
    __shared__ float red[20];
    int warp = tid >> 5, lane = tid & 31;
    if (lane == 0) { red[warp] = s; red[warp + 8] = sq; }
    __syncthreads();
    if (tid == 0) {
        float S = 0.0f, SQ = 0.0f;
        #pragma unroll
        for (int w = 0; w < 8; w++) { S += red[w]; SQ += red[w + 8]; }
        float mu = S * (1.0f / Hdim);
        float var = SQ * (1.0f / Hdim) - mu * mu;
        red[16] = mu;
        red[17] = rsqrtf(var + 1e-5f);
    }
    __syncthreads();
    float mu = red[16], inv = red[17];
    const float* sh = cm + b * CM_STRIDE + shiftOff;
    const float* sc = cm + b * CM_STRIDE + scaleOff;
    #pragma unroll
    for (int i = 0; i < 4; i++) {
        int col = tid + i * 256;
        float xn = (vals[i] - mu) * inv;
        out[(size_t)row * Hdim + col] = xn * (1.0f + sc[col]) + sh[col];
    }
}

// ------------------------- main fp16 GEMM ----------------------------------
// C[M,N] = A[M,K] @ B[K,N] + bias, fused epilogues.
// EPI 0: none; 1: exact GELU; 2: v*(1+gate); 3: resid + gate*v
template<int EPI>
__global__ __launch_bounds__(256)
void gemm_f16(const float* __restrict__ A, const float* __restrict__ B,
              const float* __restrict__ bias, float* __restrict__ C,
              int M, int N, int K,
              const float* __restrict__ gate, const float* __restrict__ resid)
{
    __shared__ unsigned As2[2][GBM * AS2];   // [row][k2], half2 along K
    __shared__ unsigned Bs2[2][8 * BS2];     // [k2][col], half2 along K
    int tid = threadIdx.x;
    int warp = tid >> 5, lane = tid & 31;
    int warpM = warp & 3, warpN = warp >> 2;   // 4x2 warp grid
    int g = lane >> 2, r = lane & 3;
    int rowBase = blockIdx.y * GBM, colBase = blockIdx.x * GBN;

    const float* Abase = A + (size_t)rowBase * K;
    const float* Bbase = B + colBase;

    float acc[2][8][4] = {};
    int ktiles = K / 16;

    // prologue: tile 0
    {
        #pragma unroll
        for (int i = 0; i < 2; i++) {
            int j = tid + i * 256;
            int row = j >> 2, k4 = (j & 3) * 4;
            float4 v = *(const float4*)(Abase + (size_t)row * K + k4);
            As2[0][row * AS2 + (j & 3) * 2 + 0] = f2h2(v.x, v.y);
            As2[0][row * AS2 + (j & 3) * 2 + 1] = f2h2(v.z, v.w);
        }
        int k2 = tid >> 5, n4 = (tid & 31) * 4;
        float4 u = *(const float4*)(Bbase + (size_t)(2 * k2) * N + n4);
        float4 w = *(const float4*)(Bbase + (size_t)(2 * k2 + 1) * N + n4);
        unsigned* q = &Bs2[0][k2 * BS2 + n4];
        q[0] = f2h2(u.x, w.x); q[1] = f2h2(u.y, w.y);
        q[2] = f2h2(u.z, w.z); q[3] = f2h2(u.w, w.w);
    }
    __syncthreads();

    for (int kt = 0; kt < ktiles; kt++) {
        int cur = kt & 1, nxt = cur ^ 1;
        float4 va[2], vbu, vbw;
        if (kt + 1 < ktiles) {
            #pragma unroll
            for (int i = 0; i < 2; i++) {
                int j = tid + i * 256;
                int row = j >> 2, k4 = (j & 3) * 4;
                va[i] = *(const float4*)(Abase + (size_t)row * K + (kt + 1) * 16 + k4);
            }
            int k2 = tid >> 5, n4 = (tid & 31) * 4;
            vbu = *(const float4*)(Bbase + (size_t)((kt + 1) * 16 + 2 * k2) * N + n4);
            vbw = *(const float4*)(Bbase + (size_t)((kt + 1) * 16 + 2 * k2 + 1) * N + n4);
        }
        // fragments + mma (K = 16, one step)
        {
            unsigned af[2][4], bf[8][2];
            #pragma unroll
            for (int mi = 0; mi < 2; mi++) {
                int row = warpM * 32 + mi * 16 + g;
                af[mi][0] = As2[cur][row * AS2 + r];
                af[mi][1] = As2[cur][(row + 8) * AS2 + r];
                af[mi][2] = As2[cur][row * AS2 + r + 4];
                af[mi][3] = As2[cur][(row + 8) * AS2 + r + 4];
            }
            #pragma unroll
            for (int nj = 0; nj < 8; nj++) {
                int col = warpN * 64 + nj * 8 + g;
                bf[nj][0] = Bs2[cur][r * BS2 + col];
                bf[nj][1] = Bs2[cur][(r + 4) * BS2 + col];
            }
            #pragma unroll
            for (int mi = 0; mi < 2; mi++)
                #pragma unroll
                for (int nj = 0; nj < 8; nj++)
                    mma_f16(acc[mi][nj], af[mi], bf[nj]);
        }
        if (kt + 1 < ktiles) {
            #pragma unroll
            for (int i = 0; i < 2; i++) {
                int j = tid + i * 256;
                int row = j >> 2;
                As2[nxt][row * AS2 + (j & 3) * 2 + 0] = f2h2(va[i].x, va[i].y);
                As2[nxt][row * AS2 + (j & 3) * 2 + 1] = f2h2(va[i].z, va[i].w);
            }
            int k2 = tid >> 5, n4 = (tid & 31) * 4;
            unsigned* q = &Bs2[nxt][k2 * BS2 + n4];
            q[0] = f2h2(vbu.x, vbw.x); q[1] = f2h2(vbu.y, vbw.y);
            q[2] = f2h2(vbu.z, vbw.z); q[3] = f2h2(vbu.w, vbw.w);
        }
        __syncthreads();
    }

    // epilogue
    #pragma unroll
    for (int mi = 0; mi < 2; mi++) {
        #pragma unroll
        for (int rr = 0; rr < 2; rr++) {
            int row = rowBase + warpM * 32 + mi * 16 + g + rr * 8;
            int b = row >> 10;
            #pragma unroll
            for (int nj = 0; nj < 8; nj++) {
                int col = colBase + warpN * 64 + nj * 8 + r * 2;
                float v0 = acc[mi][nj][rr * 2 + 0] + bias[col];
                float v1 = acc[mi][nj][rr * 2 + 1] + bias[col + 1];
                if (EPI == 1) {
                    v0 = 0.5f * v0 * (1.0f + erff(v0 * 0.70710678118654752f));
                    v1 = 0.5f * v1 * (1.0f + erff(v1 * 0.70710678118654752f));
                } else if (EPI == 2) {
                    v0 *= (1.0f + gate[b * CM_STRIDE + col]);
                    v1 *= (1.0f + gate[b * CM_STRIDE + col + 1]);
                } else if (EPI == 3) {
                    v0 = resid[(size_t)row * N + col]     + gate[b * CM_STRIDE + col]     * v0;
                    v1 = resid[(size_t)row * N + col + 1] + gate[b * CM_STRIDE + col + 1] * v1;
                }
                *(float2*)&C[(size_t)row * N + col] = make_float2(v0, v1);
            }
        }
    }
}

// ------------------------- flash attention (fp16 mma) -----------------------
// One CTA: 128 q-rows x full key sweep for one (b,h). 8 warps, 16 q-rows each.
#define PSTR2 36   // P/Q staging: [row][col2]
#define KSTR2 36   // K: [key][d2]  (natural layout, pairs along d)
#define VSTR2 72   // V: [key2][d]  (64 d-columns + 8 pad)  <-- was 40: OOB bug

__global__ __launch_bounds__(256)
void flash_attn(const float* __restrict__ qkv, float* __restrict__ out)
{
    __shared__ unsigned Ps2[128 * PSTR2];  // Q staging then P tiles
    __shared__ unsigned Ks2[64 * KSTR2];
    __shared__ unsigned Vs2[32 * VSTR2];

    int tid = threadIdx.x;
    int warp = tid >> 5, lane = tid & 31;
    int g = lane >> 2, r = lane & 3;
    int bh = blockIdx.y;
    int b = bh >> 4, h = bh & 15;
    int q0 = blockIdx.x * 128;

    // ---- stage Q (scaled by 1/8) into Ps2 ----
    #pragma unroll
    for (int i = 0; i < 8; i++) {
        int j = tid + i * 256;               // 2048 float4-units
        int row = j >> 4, c4 = (j & 15) * 4;
        float4 v = *(const float4*)(qkv + ((size_t)(b * Ntok + q0 + row) * 3) * Hdim
                                    + h * HD + c4);
        Ps2[row * PSTR2 + (j & 15) * 2 + 0] = f2h2(v.x * 0.125f, v.y * 0.125f);
        Ps2[row * PSTR2 + (j & 15) * 2 + 1] = f2h2(v.z * 0.125f, v.w * 0.125f);
    }
    __syncthreads();

    int qrow = warp * 16 + g;
    unsigned qf[4][4];
    #pragma unroll
    for (int ks = 0; ks < 4; ks++) {
        qf[ks][0] = Ps2[qrow * PSTR2 + ks * 8 + r];
        qf[ks][1] = Ps2[(qrow + 8) * PSTR2 + ks * 8 + r];
        qf[ks][2] = Ps2[qrow * PSTR2 + ks * 8 + r + 4];
        qf[ks][3] = Ps2[(qrow + 8) * PSTR2 + ks * 8 + r + 4];
    }
    __syncthreads();

    float oacc[8][4] = {};
    float m0 = -1e30f, m1 = -1e30f, l0 = 0.0f, l1 = 0.0f;

    for (int n0 = 0; n0 < Ntok; n0 += 64) {
        // ---- load K tile: natural [key][d2] (pairs along d) ----
        #pragma unroll
        for (int i = 0; i < 4; i++) {
            int j = tid + i * 256;           // 1024 units
            int key = j >> 4, c4 = (j & 15) * 4;
            float4 kv = *(const float4*)(qkv + ((size_t)(b * Ntok + n0 + key) * 3 + 1) * Hdim
                                         + h * HD + c4);
            Ks2[key * KSTR2 + (j & 15) * 2 + 0] = f2h2(kv.x, kv.y);
            Ks2[key * KSTR2 + (j & 15) * 2 + 1] = f2h2(kv.z, kv.w);
        }
        // ---- load V tile: [key2][d] (pairs along key) ----
        #pragma unroll
        for (int i = 0; i < 2; i++) {
            int j = tid + i * 256;           // 512 units
            int k2 = j >> 4, c4 = (j & 15) * 4;
            float4 v0 = *(const float4*)(qkv + ((size_t)(b * Ntok + n0 + 2 * k2) * 3 + 2) * Hdim
                                         + h * HD + c4);
            float4 v1 = *(const float4*)(qkv + ((size_t)(b * Ntok + n0 + 2 * k2 + 1) * 3 + 2) * Hdim
                                         + h * HD + c4);
            unsigned* q = &Vs2[k2 * VSTR2 + c4];
            q[0] = f2h2(v0.x, v1.x); q[1] = f2h2(v0.y, v1.y);
            q[2] = f2h2(v0.z, v1.z); q[3] = f2h2(v0.w, v1.w);
        }
        __syncthreads();

        // ---- S = Q K^T  (16 x 64 per warp, d=64 -> 4 k-steps) ----
        float sacc[8][4] = {};
        #pragma unroll
        for (int ks = 0; ks < 4; ks++) {
            #pragma unroll
            for (int nj = 0; nj < 8; nj++) {
                int key = nj * 8 + g;
                unsigned bf[2];
                bf[0] = Ks2[key * KSTR2 + ks * 8 + r];
                bf[1] = Ks2[key * KSTR2 + ks * 8 + r + 4];
                mma_f16(sacc[nj], qf[ks], bf);
            }
        }

        // ---- online softmax (rows qrow, qrow+8) ----
        float mc0 = -1e30f, mc1 = -1e30f;
        #pragma unroll
        for (int nj = 0; nj < 8; nj++) {
            mc0 = fmaxf(mc0, fmaxf(sacc[nj][0], sacc[nj][1]));
            mc1 = fmaxf(mc1, fmaxf(sacc[nj][2], sacc[nj][3]));
        }
        mc0 = fmaxf(mc0, __shfl_xor_sync(0xffffffffu, mc0, 1));
        mc0 = fmaxf(mc0, __shfl_xor_sync(0xffffffffu, mc0, 2));
        mc1 = fmaxf(mc1, __shfl_xor_sync(0xffffffffu, mc1, 1));
        mc1 = fmaxf(mc1, __shfl_xor_sync(0xffffffffu, mc1, 2));
        float mn0 = fmaxf(m0, mc0), mn1 = fmaxf(m1, mc1);
        float a0 = __expf(m0 - mn0), a1 = __expf(m1 - mn1);
        float rs0 = 0.0f, rs1 = 0.0f;
        #pragma unroll
        for (int nj = 0; nj < 8; nj++) {
            float p0 = __expf(sacc[nj][0] - mn0);
            float p1 = __expf(sacc[nj][1] - mn0);
            float p2 = __expf(sacc[nj][2] - mn1);
            float p3 = __expf(sacc[nj][3] - mn1);
            rs0 += p0 + p1; rs1 += p2 + p3;
            Ps2[qrow * PSTR2 + nj * 4 + r]       = f2h2(p0, p1);
            Ps2[(qrow + 8) * PSTR2 + nj * 4 + r] = f2h2(p2, p3);
        }
        rs0 += __shfl_xor_sync(0xffffffffu, rs0, 1);
        rs0 += __shfl_xor_sync(0xffffffffu, rs0, 2);
        rs1 += __shfl_xor_sync(0xffffffffu, rs1, 1);
        rs1 += __shfl_xor_sync(0xffffffffu, rs1, 2);
        l0 = l0 * a0 + rs0;
        l1 = l1 * a1 + rs1;
        m0 = mn0; m1 = mn1;
        #pragma unroll
        for (int nj = 0; nj < 8; nj++) {
            oacc[nj][0] *= a0; oacc[nj][1] *= a0;
            oacc[nj][2] *= a1; oacc[nj][3] *= a1;
        }
        __syncwarp();

        // ---- O += P V  (64 keys -> 4 k-steps of 16 keys) ----
        #pragma unroll
        for (int ks = 0; ks < 4; ks++) {
            unsigned af[4];
            af[0] = Ps2[qrow * PSTR2 + ks * 8 + r];
            af[1] = Ps2[(qrow + 8) * PSTR2 + ks * 8 + r];
            af[2] = Ps2[qrow * PSTR2 + ks * 8 + r + 4];
            af[3] = Ps2[(qrow + 8) * PSTR2 + ks * 8 + r + 4];
            #pragma unroll
            for (int nj = 0; nj < 8; nj++) {
                unsigned bf[2];
                bf[0] = Vs2[(ks * 8 + r) * VSTR2 + nj * 8 + g];
                bf[1] = Vs2[(ks * 8 + r + 4) * VSTR2 + nj * 8 + g];
                mma_f16(oacc[nj], af, bf);
            }
        }
        __syncthreads();
    }

    // ---- finalize ----
    float i0 = 1.0f / l0, i1 = 1.0f / l1;
    #pragma unroll
    for (int nj = 0; nj < 8; nj++) {
        int col = h * HD + nj * 8 + 2 * r;
        *(float2*)&out[(size_t)(b * Ntok + q0 + qrow) * Hdim + col]
            = make_float2(oacc[nj][0] * i0, oacc[nj][1] * i0);
        *(float2*)&out[(size_t)(b * Ntok + q0 + qrow + 8) * Hdim + col]
            = make_float2(oacc[nj][2] * i1, oacc[nj][3] * i1);
    }
}

// ------------------------- launch ------------------------------------------
extern "C" void kernel_launch(void* const* d_in, const int* in_sizes, int n_in,
                              void* d_out, int out_size)
{
    const float* x      = (const float*)d_in[0];
    const float* c      = (const float*)d_in[1];
    const float* w_mod  = (const float*)d_in[2];
    const float* b_mod  = (const float*)d_in[3];
    const float* w_qkv  = (const float*)d_in[4];
    const float* b_qkv  = (const float*)d_in[5];
    const float* w_proj = (const float*)d_in[6];
    const float* b_proj = (const float*)d_in[7];
    const float* w1     = (const float*)d_in[8];
    const float* b1     = (const float*)d_in[9];
    const float* w2     = (const float*)d_in[10];
    const float* b2     = (const float*)d_in[11];
    float* out = (float*)d_out;

    float *cm, *xm, *qkv, *attnout, *x2, *xm2, *hid;
    cudaGetSymbolAddress((void**)&cm,      g_cm);
    cudaGetSymbolAddress((void**)&xm,      g_xm);
    cudaGetSymbolAddress((void**)&qkv,     g_qkv);
    cudaGetSymbolAddress((void**)&attnout, g_attnout);
    cudaGetSymbolAddress((void**)&x2,      g_x2);
    cudaGetSymbolAddress((void**)&xm2,     g_xm2);
    cudaGetSymbolAddress((void**)&hid,     g_hid);

    // 1. conditioning -> modulation params
    cond_mod_kernel<<<dim3(24, 4), 256>>>(c, w_mod, b_mod, cm);

    // 2. LN + modulate (msa)
    ln_mod_kernel<<<ROWS, 256>>>(x, cm, 0, Hdim, xm);

    // 3. qkv = xm @ w_qkv + b_qkv     [4096, 3072]
    gemm_f16<0><<<dim3(3 * Hdim / GBN, ROWS / GBM), 256>>>(
        xm, w_qkv, b_qkv, qkv, ROWS, 3 * Hdim, Hdim, nullptr, nullptr);

    // 4-6. fused flash attention -> attnout
    flash_attn<<<dim3(Ntok / 128, Bsz * NH), 256>>>(qkv, attnout);

    // 7. x2 = (attnout @ w_proj + b_proj) * (1 + gate_msa)
    gemm_f16<2><<<dim3(Hdim / GBN, ROWS / GBM), 256>>>(
        attnout, w_proj, b_proj, x2, ROWS, Hdim, Hdim, cm + 2 * Hdim, nullptr);

    // 8. LN + modulate (mlp)
    ln_mod_kernel<<<ROWS, 256>>>(x2, cm, 3 * Hdim, 4 * Hdim, xm2);

    // 9. hid = gelu(xm2 @ w1 + b1)    [4096, 4096]
    gemm_f16<1><<<dim3(DFF / GBN, ROWS / GBM), 256>>>(
        xm2, w1, b1, hid, ROWS, DFF, Hdim, nullptr, nullptr);

    // 10. out = x2 + gate_mlp * (hid @ w2 + b2)
    gemm_f16<3><<<dim3(Hdim / GBN, ROWS / GBM), 256>>>(
        hid, w2, b2, out, ROWS, Hdim, DFF, cm + 5 * Hdim, x2);
}

// round 6
// speedup vs baseline: 4.8231x; 1.0772x over previous
#include <cuda_runtime.h>
#include <cuda_fp16.h>
#include <math.h>

// ---------------------------------------------------------------------------
// DiT block: fp16-storage tensor-core GEMMs (fp32 accum) + fused flash attn.
// B=4, N=1024, H=1024, heads=16, d=64, D_FF=4096
// ---------------------------------------------------------------------------

#define Bsz 4
#define Ntok 1024
#define Hdim 1024
#define NH 16
#define HD 64
#define DFF 4096
#define ROWS (Bsz * Ntok)      // 4096
#define CM_STRIDE (6 * Hdim)   // 6144

// ------------------------- scratch (device globals) ------------------------
__device__ float    g_cm[Bsz * CM_STRIDE];
__device__ __half   g_xmh[ROWS * Hdim];
__device__ __half   g_qkvh[ROWS * 3 * Hdim];
__device__ __half   g_attnh[ROWS * Hdim];
__device__ float    g_x2[ROWS * Hdim];
__device__ __half   g_xm2h[ROWS * Hdim];
__device__ __half   g_hidh[ROWS * DFF];
// pair-interleaved half2 weights: [K/2][N], elem = (w[2k][n], w[2k+1][n])
__device__ unsigned g_wqkvh[(Hdim / 2) * 3 * Hdim];
__device__ unsigned g_w1h[(Hdim / 2) * DFF];
__device__ unsigned g_w2h[(DFF / 2) * Hdim];
__device__ unsigned g_wph[(Hdim / 2) * Hdim];

// ------------------------- helpers -----------------------------------------
__device__ __forceinline__ unsigned f2h2(float a, float b) {
    __half2 h = __floats2half2_rn(a, b);
    return *(unsigned*)&h;
}

__device__ __forceinline__ void mma_f16(float* d, const unsigned* a, const unsigned* b) {
    asm volatile(
        "mma.sync.aligned.m16n8k16.row.col.f32.f16.f16.f32 "
        "{%0,%1,%2,%3},{%4,%5,%6,%7},{%8,%9},{%0,%1,%2,%3};\n"
        : "+f"(d[0]), "+f"(d[1]), "+f"(d[2]), "+f"(d[3])
        : "r"(a[0]), "r"(a[1]), "r"(a[2]), "r"(a[3]), "r"(b[0]), "r"(b[1]));
}

// ------------------------- weight -> half2 pair-interleave ------------------
__global__ void wpair_kernel(const float* __restrict__ w, unsigned* __restrict__ o, int N)
{
    int n = blockIdx.x * 256 + threadIdx.x;
    int k2 = blockIdx.y;
    o[(size_t)k2 * N + n] = f2h2(w[(size_t)(2 * k2) * N + n],
                                 w[(size_t)(2 * k2 + 1) * N + n]);
}

// ------------------------- cond modulation ---------------------------------
__global__ void cond_mod_kernel(const float* __restrict__ c,
                                const float* __restrict__ w,
                                const float* __restrict__ bmod,
                                float* __restrict__ cm)
{
    int b = blockIdx.y;
    int j = blockIdx.x * 256 + threadIdx.x;
    __shared__ float sc[Hdim];
    for (int i = threadIdx.x; i < Hdim; i += 256) {
        float t = c[b * Hdim + i];
        sc[i] = t / (1.0f + expf(-t));
    }
    __syncthreads();
    float acc = 0.0f;
    #pragma unroll 4
    for (int k = 0; k < Hdim; k++)
        acc += sc[k] * w[(size_t)k * CM_STRIDE + j];
    cm[b * CM_STRIDE + j] = acc + bmod[j];
}

// ------------------------- LayerNorm + modulate -> half ---------------------
__global__ void ln_mod_h_kernel(const float* __restrict__ x,
                                const float* __restrict__ cm,
                                int shiftOff, int scaleOff,
                                __half* __restrict__ out)
{
    int row = blockIdx.x;
    int b = row >> 10;
    const float* xr = x + (size_t)row * Hdim;
    int tid = threadIdx.x;
    int col4 = tid * 4;
    float4 t = *(const float4*)(xr + col4);
    float s  = t.x + t.y + t.z + t.w;
    float sq = t.x * t.x + t.y * t.y + t.z * t.z + t.w * t.w;
    #pragma unroll
    for (int o = 16; o > 0; o >>= 1) {
        s  += __shfl_down_sync(0xffffffffu, s,  o);
        sq += __shfl_down_sync(0xffffffffu, sq, o);
    }
    __shared__ float red[20];
    int warp = tid >> 5, lane = tid & 31;
    if (lane == 0) { red[warp] = s; red[warp + 8] = sq; }
    __syncthreads();
    if (tid == 0) {
        float S = 0.0f, SQ = 0.0f;
        #pragma unroll
        for (int w = 0; w < 8; w++) { S += red[w]; SQ += red[w + 8]; }
        float mu = S * (1.0f / Hdim);
        float var = SQ * (1.0f / Hdim) - mu * mu;
        red[16] = mu;
        red[17] = rsqrtf(var + 1e-5f);
    }
    __syncthreads();
    float mu = red[16], inv = red[17];
    const float* sh = cm + b * CM_STRIDE + shiftOff;
    const float* sc = cm + b * CM_STRIDE + scaleOff;
    float4 shv = *(const float4*)(sh + col4);
    float4 scv = *(const float4*)(sc + col4);
    float v0 = (t.x - mu) * inv * (1.0f + scv.x) + shv.x;
    float v1 = (t.y - mu) * inv * (1.0f + scv.y) + shv.y;
    float v2 = (t.z - mu) * inv * (1.0f + scv.z) + shv.z;
    float v3 = (t.w - mu) * inv * (1.0f + scv.w) + shv.w;
    uint2 o2 = make_uint2(f2h2(v0, v1), f2h2(v2, v3));
    *(uint2*)&out[(size_t)row * Hdim + col4] = o2;
}

// ------------------------- fp16 GEMM (half storage) ------------------------
// C[M,N] = A[M,K](half) @ Bp[K/2,N](half2 pairs) + bias.
// EPI 0: qkv (half out, scale cols<Hdim by 0.125)
// EPI 1: exact GELU (half out)
// EPI 2: v*(1+gate)     (float out)
// EPI 3: resid + gate*v (float out)
#define AS2 20    // As row stride in half2 units (16 + 4)
#define BS2 136   // Bs row stride (128 + 8)

template<int EPI>
__global__ __launch_bounds__(256)
void gemm_h(const __half* __restrict__ A, const unsigned* __restrict__ Bp,
            const float* __restrict__ bias, void* __restrict__ Cout,
            int M, int N, int K,
            const float* __restrict__ gate, const float* __restrict__ resid)
{
    __shared__ unsigned As2[2][128 * AS2];   // [row][k2]
    __shared__ unsigned Bs2[2][16 * BS2];    // [k2][col]
    int tid = threadIdx.x;
    int warp = tid >> 5, lane = tid & 31;
    int warpM = warp & 3, warpN = warp >> 2;
    int g = lane >> 2, r = lane & 3;
    int rowBase = blockIdx.y * 128, colBase = blockIdx.x * 128;

    float acc[2][8][4] = {};
    int ktiles = K / 32;

    int aRow = tid >> 2, aK4 = (tid & 3) * 4;       // +128 rows for i=1
    int bK2 = tid >> 5, bN4 = (tid & 31) * 4;       // +8 k2 for i=1

    // prologue
    #pragma unroll
    for (int i = 0; i < 2; i++) {
        int row = aRow, off = i * 64;                // rows 0..127 via (tid>>2) + i*64
        row = (tid >> 2) + i * 64;
        uint4 va = *(const uint4*)(A + (size_t)(rowBase + row) * K + aK4 * 2);
        *(uint4*)&As2[0][row * AS2 + aK4] = va;
        int k2 = bK2 + i * 8;
        uint4 vb = *(const uint4*)(Bp + (size_t)k2 * N + colBase + bN4);
        *(uint4*)&Bs2[0][k2 * BS2 + bN4] = vb;
    }
    __syncthreads();

    for (int kt = 0; kt < ktiles; kt++) {
        int cur = kt & 1, nxt = cur ^ 1;
        uint4 va[2], vb[2];
        if (kt + 1 < ktiles) {
            #pragma unroll
            for (int i = 0; i < 2; i++) {
                int row = (tid >> 2) + i * 64;
                va[i] = *(const uint4*)(A + (size_t)(rowBase + row) * K
                                        + (kt + 1) * 32 + aK4 * 2);
                int k2 = bK2 + i * 8;
                vb[i] = *(const uint4*)(Bp + (size_t)((kt + 1) * 16 + k2) * N + colBase + bN4);
            }
        }
        #pragma unroll
        for (int ks = 0; ks < 2; ks++) {
            unsigned af[2][4], bf[8][2];
            #pragma unroll
            for (int mi = 0; mi < 2; mi++) {
                int row = warpM * 32 + mi * 16 + g;
                af[mi][0] = As2[cur][row * AS2 + ks * 8 + r];
                af[mi][1] = As2[cur][(row + 8) * AS2 + ks * 8 + r];
                af[mi][2] = As2[cur][row * AS2 + ks * 8 + r + 4];
                af[mi][3] = As2[cur][(row + 8) * AS2 + ks * 8 + r + 4];
            }
            #pragma unroll
            for (int nj = 0; nj < 8; nj++) {
                int col = warpN * 64 + nj * 8 + g;
                bf[nj][0] = Bs2[cur][(ks * 8 + r) * BS2 + col];
                bf[nj][1] = Bs2[cur][(ks * 8 + r + 4) * BS2 + col];
            }
            #pragma unroll
            for (int mi = 0; mi < 2; mi++)
                #pragma unroll
                for (int nj = 0; nj < 8; nj++)
                    mma_f16(acc[mi][nj], af[mi], bf[nj]);
        }
        if (kt + 1 < ktiles) {
            #pragma unroll
            for (int i = 0; i < 2; i++) {
                int row = (tid >> 2) + i * 64;
                *(uint4*)&As2[nxt][row * AS2 + aK4] = va[i];
                int k2 = bK2 + i * 8;
                *(uint4*)&Bs2[nxt][k2 * BS2 + bN4] = vb[i];
            }
        }
        __syncthreads();
    }

    // epilogue
    #pragma unroll
    for (int mi = 0; mi < 2; mi++) {
        #pragma unroll
        for (int rr = 0; rr < 2; rr++) {
            int row = rowBase + warpM * 32 + mi * 16 + g + rr * 8;
            int b = row >> 10;
            #pragma unroll
            for (int nj = 0; nj < 8; nj++) {
                int col = colBase + warpN * 64 + nj * 8 + r * 2;
                float v0 = acc[mi][nj][rr * 2 + 0] + bias[col];
                float v1 = acc[mi][nj][rr * 2 + 1] + bias[col + 1];
                if (EPI == 0) {
                    float s = (col < Hdim) ? 0.125f : 1.0f;   // fold 1/sqrt(d) into Q
                    ((unsigned*)0, 0);
                    __half* Ch = (__half*)Cout;
                    *(unsigned*)&Ch[(size_t)row * N + col] = f2h2(v0 * s, v1 * s);
                } else if (EPI == 1) {
                    v0 = 0.5f * v0 * (1.0f + erff(v0 * 0.70710678118654752f));
                    v1 = 0.5f * v1 * (1.0f + erff(v1 * 0.70710678118654752f));
                    __half* Ch = (__half*)Cout;
                    *(unsigned*)&Ch[(size_t)row * N + col] = f2h2(v0, v1);
                } else if (EPI == 2) {
                    v0 *= (1.0f + gate[b * CM_STRIDE + col]);
                    v1 *= (1.0f + gate[b * CM_STRIDE + col + 1]);
                    *(float2*)&((float*)Cout)[(size_t)row * N + col] = make_float2(v0, v1);
                } else {
                    v0 = resid[(size_t)row * N + col]     + gate[b * CM_STRIDE + col]     * v0;
                    v1 = resid[(size_t)row * N + col + 1] + gate[b * CM_STRIDE + col + 1] * v1;
                    *(float2*)&((float*)Cout)[(size_t)row * N + col] = make_float2(v0, v1);
                }
            }
        }
    }
}

// ------------------------- flash attention (half storage) -------------------
#define PSTR2 36   // Q/P staging: [row][idx2], 32 + 4 pad
#define KSTR2 36   // K: [key][d2]
#define VSTR2 72   // V: [key2][d], 64 + 8 pad

__global__ __launch_bounds__(256)
void flash_attn(const __half* __restrict__ qkv, __half* __restrict__ out)
{
    __shared__ unsigned Ps2[128 * PSTR2];
    __shared__ unsigned Ks2[64 * KSTR2];
    __shared__ unsigned Vs2[32 * VSTR2];

    int tid = threadIdx.x;
    int warp = tid >> 5, lane = tid & 31;
    int g = lane >> 2, r = lane & 3;
    int bh = blockIdx.y;
    int b = bh >> 4, h = bh & 15;
    int q0 = blockIdx.x * 128;

    // ---- stage Q (pre-scaled in qkv epilogue) ----
    #pragma unroll
    for (int i = 0; i < 4; i++) {
        int j = tid + i * 256;                 // 1024 uint4
        int row = j >> 3, d8 = (j & 7) * 8;
        uint4 v = *(const uint4*)(qkv + (size_t)(b * Ntok + q0 + row) * 3 * Hdim
                                  + h * HD + d8);
        *(uint4*)&Ps2[row * PSTR2 + (j & 7) * 4] = v;
    }
    __syncthreads();

    int qrow = warp * 16 + g;
    unsigned qf[4][4];
    #pragma unroll
    for (int ks = 0; ks < 4; ks++) {
        qf[ks][0] = Ps2[qrow * PSTR2 + ks * 8 + r];
        qf[ks][1] = Ps2[(qrow + 8) * PSTR2 + ks * 8 + r];
        qf[ks][2] = Ps2[qrow * PSTR2 + ks * 8 + r + 4];
        qf[ks][3] = Ps2[(qrow + 8) * PSTR2 + ks * 8 + r + 4];
    }
    __syncthreads();

    float oacc[8][4] = {};
    float m0 = -1e30f, m1 = -1e30f, l0 = 0.0f, l1 = 0.0f;

    for (int n0 = 0; n0 < Ntok; n0 += 64) {
        // ---- K tile: [key][d2], natural pairs along d ----
        #pragma unroll
        for (int i = 0; i < 2; i++) {
            int j = tid + i * 256;             // 512 uint4
            int key = j >> 3, d8 = (j & 7) * 8;
            uint4 v = *(const uint4*)(qkv + (size_t)(b * Ntok + n0 + key) * 3 * Hdim
                                      + Hdim + h * HD + d8);
            *(uint4*)&Ks2[key * KSTR2 + (j & 7) * 4] = v;
        }
        // ---- V tile: [key2][d], PRMT interleave of two key rows ----
        {
            int k2 = tid >> 3, d8 = (tid & 7) * 8;
            const __half* vp = qkv + (size_t)(b * Ntok + n0 + 2 * k2) * 3 * Hdim
                               + 2 * Hdim + h * HD + d8;
            uint4 a = *(const uint4*)vp;
            uint4 c = *(const uint4*)(vp + 3 * Hdim);
            unsigned* q = &Vs2[k2 * VSTR2 + d8];
            q[0] = __byte_perm(a.x, c.x, 0x5410); q[1] = __byte_perm(a.x, c.x, 0x7632);
            q[2] = __byte_perm(a.y, c.y, 0x5410); q[3] = __byte_perm(a.y, c.y, 0x7632);
            q[4] = __byte_perm(a.z, c.z, 0x5410); q[5] = __byte_perm(a.z, c.z, 0x7632);
            q[6] = __byte_perm(a.w, c.w, 0x5410); q[7] = __byte_perm(a.w, c.w, 0x7632);
        }
        __syncthreads();

        // ---- S = Q K^T ----
        float sacc[8][4] = {};
        #pragma unroll
        for (int ks = 0; ks < 4; ks++) {
            #pragma unroll
            for (int nj = 0; nj < 8; nj++) {
                int key = nj * 8 + g;
                unsigned bf[2];
                bf[0] = Ks2[key * KSTR2 + ks * 8 + r];
                bf[1] = Ks2[key * KSTR2 + ks * 8 + r + 4];
                mma_f16(sacc[nj], qf[ks], bf);
            }
        }

        // ---- online softmax ----
        float mc0 = -1e30f, mc1 = -1e30f;
        #pragma unroll
        for (int nj = 0; nj < 8; nj++) {
            mc0 = fmaxf(mc0, fmaxf(sacc[nj][0], sacc[nj][1]));
            mc1 = fmaxf(mc1, fmaxf(sacc[nj][2], sacc[nj][3]));
        }
        mc0 = fmaxf(mc0, __shfl_xor_sync(0xffffffffu, mc0, 1));
        mc0 = fmaxf(mc0, __shfl_xor_sync(0xffffffffu, mc0, 2));
        mc1 = fmaxf(mc1, __shfl_xor_sync(0xffffffffu, mc1, 1));
        mc1 = fmaxf(mc1, __shfl_xor_sync(0xffffffffu, mc1, 2));
        float mn0 = fmaxf(m0, mc0), mn1 = fmaxf(m1, mc1);
        float a0 = __expf(m0 - mn0), a1 = __expf(m1 - mn1);
        float rs0 = 0.0f, rs1 = 0.0f;
        #pragma unroll
        for (int nj = 0; nj < 8; nj++) {
            float p0 = __expf(sacc[nj][0] - mn0);
            float p1 = __expf(sacc[nj][1] - mn0);
            float p2 = __expf(sacc[nj][2] - mn1);
            float p3 = __expf(sacc[nj][3] - mn1);
            rs0 += p0 + p1; rs1 += p2 + p3;
            Ps2[qrow * PSTR2 + nj * 4 + r]       = f2h2(p0, p1);
            Ps2[(qrow + 8) * PSTR2 + nj * 4 + r] = f2h2(p2, p3);
        }
        rs0 += __shfl_xor_sync(0xffffffffu, rs0, 1);
        rs0 += __shfl_xor_sync(0xffffffffu, rs0, 2);
        rs1 += __shfl_xor_sync(0xffffffffu, rs1, 1);
        rs1 += __shfl_xor_sync(0xffffffffu, rs1, 2);
        l0 = l0 * a0 + rs0;
        l1 = l1 * a1 + rs1;
        m0 = mn0; m1 = mn1;
        #pragma unroll
        for (int nj = 0; nj < 8; nj++) {
            oacc[nj][0] *= a0; oacc[nj][1] *= a0;
            oacc[nj][2] *= a1; oacc[nj][3] *= a1;
        }
        __syncwarp();

        // ---- O += P V ----
        #pragma unroll
        for (int ks = 0; ks < 4; ks++) {
            unsigned af[4];
            af[0] = Ps2[qrow * PSTR2 + ks * 8 + r];
            af[1] = Ps2[(qrow + 8) * PSTR2 + ks * 8 + r];
            af[2] = Ps2[qrow * PSTR2 + ks * 8 + r + 4];
            af[3] = Ps2[(qrow + 8) * PSTR2 + ks * 8 + r + 4];
            #pragma unroll
            for (int nj = 0; nj < 8; nj++) {
                unsigned bf[2];
                bf[0] = Vs2[(ks * 8 + r) * VSTR2 + nj * 8 + g];
                bf[1] = Vs2[(ks * 8 + r + 4) * VSTR2 + nj * 8 + g];
                mma_f16(oacc[nj], af, bf);
            }
        }
        __syncthreads();
    }

    // ---- finalize: half output ----
    float i0 = 1.0f / l0, i1 = 1.0f / l1;
    #pragma unroll
    for (int nj = 0; nj < 8; nj++) {
        int col = h * HD + nj * 8 + 2 * r;
        *(unsigned*)&out[(size_t)(b * Ntok + q0 + qrow) * Hdim + col]
            = f2h2(oacc[nj][0] * i0, oacc[nj][1] * i0);
        *(unsigned*)&out[(size_t)(b * Ntok + q0 + qrow + 8) * Hdim + col]
            = f2h2(oacc[nj][2] * i1, oacc[nj][3] * i1);
    }
}

// ------------------------- launch ------------------------------------------
extern "C" void kernel_launch(void* const* d_in, const int* in_sizes, int n_in,
                              void* d_out, int out_size)
{
    const float* x      = (const float*)d_in[0];
    const float* c      = (const float*)d_in[1];
    const float* w_mod  = (const float*)d_in[2];
    const float* b_mod  = (const float*)d_in[3];
    const float* w_qkv  = (const float*)d_in[4];
    const float* b_qkv  = (const float*)d_in[5];
    const float* w_proj = (const float*)d_in[6];
    const float* b_proj = (const float*)d_in[7];
    const float* w1     = (const float*)d_in[8];
    const float* b1     = (const float*)d_in[9];
    const float* w2     = (const float*)d_in[10];
    const float* b2     = (const float*)d_in[11];
    float* out = (float*)d_out;

    float *cm, *x2;
    __half *xmh, *qkvh, *attnh, *xm2h, *hidh;
    unsigned *wqkvh, *w1h, *w2h, *wph;
    cudaGetSymbolAddress((void**)&cm,    g_cm);
    cudaGetSymbolAddress((void**)&xmh,   g_xmh);
    cudaGetSymbolAddress((void**)&qkvh,  g_qkvh);
    cudaGetSymbolAddress((void**)&attnh, g_attnh);
    cudaGetSymbolAddress((void**)&x2,    g_x2);
    cudaGetSymbolAddress((void**)&xm2h,  g_xm2h);
    cudaGetSymbolAddress((void**)&hidh,  g_hidh);
    cudaGetSymbolAddress((void**)&wqkvh, g_wqkvh);
    cudaGetSymbolAddress((void**)&w1h,   g_w1h);
    cudaGetSymbolAddress((void**)&w2h,   g_w2h);
    cudaGetSymbolAddress((void**)&wph,   g_wph);

    // 0. weight conversions (pair-interleaved half2)
    wpair_kernel<<<dim3(3 * Hdim / 256, Hdim / 2), 256>>>(w_qkv, wqkvh, 3 * Hdim);
    wpair_kernel<<<dim3(DFF / 256, Hdim / 2), 256>>>(w1, w1h, DFF);
    wpair_kernel<<<dim3(Hdim / 256, DFF / 2), 256>>>(w2, w2h, Hdim);
    wpair_kernel<<<dim3(Hdim / 256, Hdim / 2), 256>>>(w_proj, wph, Hdim);

    // 1. conditioning -> modulation params
    cond_mod_kernel<<<dim3(24, 4), 256>>>(c, w_mod, b_mod, cm);

    // 2. LN + modulate (msa) -> half
    ln_mod_h_kernel<<<ROWS, 256>>>(x, cm, 0, Hdim, xmh);

    // 3. qkv (half out, Q pre-scaled by 1/8)
    gemm_h<0><<<dim3(3 * Hdim / 128, ROWS / 128), 256>>>(
        xmh, wqkvh, b_qkv, qkvh, ROWS, 3 * Hdim, Hdim, nullptr, nullptr);

    // 4. flash attention -> half attnout
    flash_attn<<<dim3(Ntok / 128, Bsz * NH), 256>>>(qkvh, attnh);

    // 5. x2 = (attnout @ w_proj + b_proj) * (1 + gate_msa)   (float out)
    gemm_h<2><<<dim3(Hdim / 128, ROWS / 128), 256>>>(
        attnh, wph, b_proj, x2, ROWS, Hdim, Hdim, cm + 2 * Hdim, nullptr);

    // 6. LN + modulate (mlp) -> half
    ln_mod_h_kernel<<<ROWS, 256>>>(x2, cm, 3 * Hdim, 4 * Hdim, xm2h);

    // 7. hid = gelu(xm2 @ w1 + b1)  (half out)
    gemm_h<1><<<dim3(DFF / 128, ROWS / 128), 256>>>(
        xm2h, w1h, b1, hidh, ROWS, DFF, Hdim, nullptr, nullptr);

    // 8. out = x2 + gate_mlp * (hid @ w2 + b2)  (float out)
    gemm_h<3><<<dim3(Hdim / 128, ROWS / 128), 256>>>(
        hidh, w2h, b2, out, ROWS, Hdim, DFF, cm + 5 * Hdim, x2);
}

// round 9
// speedup vs baseline: 5.4339x; 1.1266x over previous
#include <cuda_runtime.h>
#include <cuda_fp16.h>
#include <cstdint>
#include <math.h>

// ---------------------------------------------------------------------------
// DiT block: fp16 mma.sync GEMMs (cp.async 3-stage, 64x64 warp tiles)
//            + fused flash attention. B=4, N=1024, H=1024, heads=16, d=64.
// ---------------------------------------------------------------------------

#define Bsz 4
#define Ntok 1024
#define Hdim 1024
#define NH 16
#define HD 64
#define DFF 4096
#define ROWS (Bsz * Ntok)      // 4096
#define CM_STRIDE (6 * Hdim)   // 6144

// ------------------------- scratch (device globals) ------------------------
__device__ float    g_cm[Bsz * CM_STRIDE];
__device__ __half   g_xmh[ROWS * Hdim];
__device__ __half   g_qkvh[ROWS * 3 * Hdim];
__device__ __half   g_attnh[ROWS * Hdim];
__device__ float    g_x2[ROWS * Hdim];
__device__ __half   g_xm2h[ROWS * Hdim];
__device__ __half   g_hidh[ROWS * DFF];
// pair-interleaved half2 weights: [K/2][N], elem = (w[2k][n], w[2k+1][n])
__device__ unsigned g_wqkvh[(Hdim / 2) * 3 * Hdim];
__device__ unsigned g_w1h[(Hdim / 2) * DFF];
__device__ unsigned g_w2h[(DFF / 2) * Hdim];
__device__ unsigned g_wph[(Hdim / 2) * Hdim];

// ------------------------- helpers -----------------------------------------
__device__ __forceinline__ unsigned f2h2(float a, float b) {
    __half2 h = __floats2half2_rn(a, b);
    return *(unsigned*)&h;
}

__device__ __forceinline__ uint32_t smem_u32(const void* p) {
    uint32_t a;
    asm("{ .reg .u64 t; cvta.to.shared.u64 t, %1; cvt.u32.u64 %0, t; }"
        : "=r"(a) : "l"(p));
    return a;
}

__device__ __forceinline__ void mma_f16(float* d, const unsigned* a, const unsigned* b) {
    asm volatile(
        "mma.sync.aligned.m16n8k16.row.col.f32.f16.f16.f32 "
        "{%0,%1,%2,%3},{%4,%5,%6,%7},{%8,%9},{%0,%1,%2,%3};\n"
        : "+f"(d[0]), "+f"(d[1]), "+f"(d[2]), "+f"(d[3])
        : "r"(a[0]), "r"(a[1]), "r"(a[2]), "r"(a[3]), "r"(b[0]), "r"(b[1]));
}

#define CP_ASYNC16(saddr, gptr) \
    asm volatile("cp.async.cg.shared.global [%0], [%1], 16;" \
                 :: "r"(saddr), "l"(gptr) : "memory")
#define CP_COMMIT() asm volatile("cp.async.commit_group;" ::: "memory")
#define CP_WAIT1()  asm volatile("cp.async.wait_group 1;" ::: "memory")

// ------------------------- weight -> half2 pair-interleave ------------------
__global__ void wpair_kernel(const float* __restrict__ w, unsigned* __restrict__ o, int N)
{
    int n = blockIdx.x * 256 + threadIdx.x;
    int k2 = blockIdx.y;
    o[(size_t)k2 * N + n] = f2h2(w[(size_t)(2 * k2) * N + n],
                                 w[(size_t)(2 * k2 + 1) * N + n]);
}

// ------------------------- cond modulation ---------------------------------
__global__ void cond_mod_kernel(const float* __restrict__ c,
                                const float* __restrict__ w,
                                const float* __restrict__ bmod,
                                float* __restrict__ cm)
{
    int b = blockIdx.y;
    int j = blockIdx.x * 256 + threadIdx.x;
    __shared__ float sc[Hdim];
    for (int i = threadIdx.x; i < Hdim; i += 256) {
        float t = c[b * Hdim + i];
        sc[i] = t / (1.0f + expf(-t));
    }
    __syncthreads();
    float acc = 0.0f;
    #pragma unroll 4
    for (int k = 0; k < Hdim; k++)
        acc += sc[k] * w[(size_t)k * CM_STRIDE + j];
    cm[b * CM_STRIDE + j] = acc + bmod[j];
}

// ------------------------- LayerNorm + modulate -> half ---------------------
__global__ void ln_mod_h_kernel(const float* __restrict__ x,
                                const float* __restrict__ cm,
                                int shiftOff, int scaleOff,
                                __half* __restrict__ out)
{
    int row = blockIdx.x;
    int b = row >> 10;
    const float* xr = x + (size_t)row * Hdim;
    int tid = threadIdx.x;
    int col4 = tid * 4;
    float4 t = *(const float4*)(xr + col4);
    float s  = t.x + t.y + t.z + t.w;
    float sq = t.x * t.x + t.y * t.y + t.z * t.z + t.w * t.w;
    #pragma unroll
    for (int o = 16; o > 0; o >>= 1) {
        s  += __shfl_down_sync(0xffffffffu, s,  o);
        sq += __shfl_down_sync(0xffffffffu, sq, o);
    }
    __shared__ float red[20];
    int warp = tid >> 5, lane = tid & 31;
    if (lane == 0) { red[warp] = s; red[warp + 8] = sq; }
    __syncthreads();
    if (tid == 0) {
        float S = 0.0f, SQ = 0.0f;
        #pragma unroll
        for (int w = 0; w < 8; w++) { S += red[w]; SQ += red[w + 8]; }
        float mu = S * (1.0f / Hdim);
        float var = SQ * (1.0f / Hdim) - mu * mu;
        red[16] = mu;
        red[17] = rsqrtf(var + 1e-5f);
    }
    __syncthreads();
    float mu = red[16], inv = red[17];
    const float* sh = cm + b * CM_STRIDE + shiftOff;
    const float* sc = cm + b * CM_STRIDE + scaleOff;
    float4 shv = *(const float4*)(sh + col4);
    float4 scv = *(const float4*)(sc + col4);
    float v0 = (t.x - mu) * inv * (1.0f + scv.x) + shv.x;
    float v1 = (t.y - mu) * inv * (1.0f + scv.y) + shv.y;
    float v2 = (t.z - mu) * inv * (1.0f + scv.z) + shv.z;
    float v3 = (t.w - mu) * inv * (1.0f + scv.w) + shv.w;
    uint2 o2 = make_uint2(f2h2(v0, v1), f2h2(v2, v3));
    *(uint2*)&out[(size_t)row * Hdim + col4] = o2;
}

// ------------------------- fp16 GEMM: 128x256 block, cp.async 3-stage -------
// C[M,N] = A[M,K](half) @ Bp[K/2,N](half2 pairs) + bias.
// EPI 0: qkv (half out, scale cols<Hdim by 0.125); 1: GELU (half out);
// EPI 2: v*(1+gate) (float out); 3: resid + gate*v (float out)
#define AS2 20      // A stage row stride (half2 units): 16 + 4 pad
#define BSTR2 264   // B stage row stride: 256 + 8 pad
#define STAGE_U32 (128 * AS2 + 16 * BSTR2)   // 2560 + 4224 = 6784
#define GSMEM2 (3 * STAGE_U32 * 4)           // 81408 bytes

template<int EPI>
__global__ __launch_bounds__(256, 1)
void gemm_h(const __half* __restrict__ A, const unsigned* __restrict__ Bp,
            const float* __restrict__ bias, void* __restrict__ Cout,
            int M, int N, int K,
            const float* __restrict__ gate, const float* __restrict__ resid)
{
    extern __shared__ unsigned sm[];
    int tid = threadIdx.x;
    int warp = tid >> 5, lane = tid & 31;
    int warpM = warp >> 2, warpN = warp & 3;   // 2x4 warp grid, 64x64 warp tile
    int g = lane >> 2, r = lane & 3;
    int rowBase = blockIdx.y * 128, colBase = blockIdx.x * 256;
    int kts = K / 32;

    uint32_t smBase = smem_u32(sm);

    // stage loader: A 128x32 halves (512 uint4), B 16 k2-rows x 256 (1024 uint4)
    auto loadStage = [&](int stage, int kt) {
        uint32_t sA = smBase + stage * STAGE_U32 * 4;
        uint32_t sB = sA + 128 * AS2 * 4;
        const __half* Ag = A + (size_t)rowBase * K + kt * 32;
        const unsigned* Bg = Bp + (size_t)(kt * 16) * N + colBase;
        #pragma unroll
        for (int i = 0; i < 2; i++) {
            int j = tid + i * 256;
            int row = j >> 2, c = (j & 3) * 4;               // c in half2 units
            CP_ASYNC16(sA + (row * AS2 + c) * 4, Ag + (size_t)row * K + c * 2);
        }
        #pragma unroll
        for (int i = 0; i < 4; i++) {
            int j = tid + i * 256;
            int k2 = j >> 6, c4 = (j & 63) * 4;
            CP_ASYNC16(sB + (k2 * BSTR2 + c4) * 4, Bg + (size_t)k2 * N + c4);
        }
    };

    float acc[4][8][4] = {};

    loadStage(0, 0); CP_COMMIT();
    loadStage(1, 1); CP_COMMIT();

    for (int kt = 0; kt < kts; kt++) {
        CP_WAIT1();
        __syncthreads();
        if (kt + 2 < kts) loadStage((kt + 2) % 3, kt + 2);
        CP_COMMIT();

        unsigned* sA = sm + (kt % 3) * STAGE_U32;
        unsigned* sB = sA + 128 * AS2;
        #pragma unroll
        for (int ks = 0; ks < 2; ks++) {
            unsigned af[4][4], bf[8][2];
            #pragma unroll
            for (int mi = 0; mi < 4; mi++) {
                int row = warpM * 64 + mi * 16 + g;
                af[mi][0] = sA[row * AS2 + ks * 8 + r];
                af[mi][1] = sA[(row + 8) * AS2 + ks * 8 + r];
                af[mi][2] = sA[row * AS2 + ks * 8 + r + 4];
                af[mi][3] = sA[(row + 8) * AS2 + ks * 8 + r + 4];
            }
            #pragma unroll
            for (int nj = 0; nj < 8; nj++) {
                int col = warpN * 64 + nj * 8 + g;
                bf[nj][0] = sB[(ks * 8 + r) * BSTR2 + col];
                bf[nj][1] = sB[(ks * 8 + r + 4) * BSTR2 + col];
            }
            #pragma unroll
            for (int mi = 0; mi < 4; mi++)
                #pragma unroll
                for (int nj = 0; nj < 8; nj++)
                    mma_f16(acc[mi][nj], af[mi], bf[nj]);
        }
    }

    // epilogue
    #pragma unroll
    for (int mi = 0; mi < 4; mi++) {
        #pragma unroll
        for (int rr = 0; rr < 2; rr++) {
            int row = rowBase + warpM * 64 + mi * 16 + g + rr * 8;
            int b = row >> 10;
            #pragma unroll
            for (int nj = 0; nj < 8; nj++) {
                int col = colBase + warpN * 64 + nj * 8 + r * 2;
                float v0 = acc[mi][nj][rr * 2 + 0] + __ldg(&bias[col]);
                float v1 = acc[mi][nj][rr * 2 + 1] + __ldg(&bias[col + 1]);
                if (EPI == 0) {
                    float sc = (col < Hdim) ? 0.125f : 1.0f;   // fold 1/sqrt(d) into Q
                    __half* Ch = (__half*)Cout;
                    *(unsigned*)&Ch[(size_t)row * N + col] = f2h2(v0 * sc, v1 * sc);
                } else if (EPI == 1) {
                    v0 = 0.5f * v0 * (1.0f + erff(v0 * 0.70710678118654752f));
                    v1 = 0.5f * v1 * (1.0f + erff(v1 * 0.70710678118654752f));
                    __half* Ch = (__half*)Cout;
                    *(unsigned*)&Ch[(size_t)row * N + col] = f2h2(v0, v1);
                } else if (EPI == 2) {
                    v0 *= (1.0f + __ldg(&gate[b * CM_STRIDE + col]));
                    v1 *= (1.0f + __ldg(&gate[b * CM_STRIDE + col + 1]));
                    *(float2*)&((float*)Cout)[(size_t)row * N + col] = make_float2(v0, v1);
                } else {
                    v0 = resid[(size_t)row * N + col]     + __ldg(&gate[b * CM_STRIDE + col])     * v0;
                    v1 = resid[(size_t)row * N + col + 1] + __ldg(&gate[b * CM_STRIDE + col + 1]) * v1;
                    *(float2*)&((float*)Cout)[(size_t)row * N + col] = make_float2(v0, v1);
                }
            }
        }
    }
}

// ------------------------- flash attention (half storage) -------------------
#define PSTR2 36
#define KSTR2 36
#define VSTR2 72

__global__ __launch_bounds__(256)
void flash_attn(const __half* __restrict__ qkv, __half* __restrict__ out)
{
    __shared__ unsigned Ps2[128 * PSTR2];
    __shared__ unsigned Ks2[64 * KSTR2];
    __shared__ unsigned Vs2[32 * VSTR2];

    int tid = threadIdx.x;
    int warp = tid >> 5, lane = tid & 31;
    int g = lane >> 2, r = lane & 3;
    int bh = blockIdx.y;
    int b = bh >> 4, h = bh & 15;
    int q0 = blockIdx.x * 128;

    #pragma unroll
    for (int i = 0; i < 4; i++) {
        int j = tid + i * 256;
        int row = j >> 3, d8 = (j & 7) * 8;
        uint4 v = *(const uint4*)(qkv + (size_t)(b * Ntok + q0 + row) * 3 * Hdim
                                  + h * HD + d8);
        *(uint4*)&Ps2[row * PSTR2 + (j & 7) * 4] = v;
    }
    __syncthreads();

    int qrow = warp * 16 + g;
    unsigned qf[4][4];
    #pragma unroll
    for (int ks = 0; ks < 4; ks++) {
        qf[ks][0] = Ps2[qrow * PSTR2 + ks * 8 + r];
        qf[ks][1] = Ps2[(qrow + 8) * PSTR2 + ks * 8 + r];
        qf[ks][2] = Ps2[qrow * PSTR2 + ks * 8 + r + 4];
        qf[ks][3] = Ps2[(qrow + 8) * PSTR2 + ks * 8 + r + 4];
    }
    __syncthreads();

    float oacc[8][4] = {};
    float m0 = -1e30f, m1 = -1e30f, l0 = 0.0f, l1 = 0.0f;

    for (int n0 = 0; n0 < Ntok; n0 += 64) {
        #pragma unroll
        for (int i = 0; i < 2; i++) {
            int j = tid + i * 256;
            int key = j >> 3, d8 = (j & 7) * 8;
            uint4 v = *(const uint4*)(qkv + (size_t)(b * Ntok + n0 + key) * 3 * Hdim
                                      + Hdim + h * HD + d8);
            *(uint4*)&Ks2[key * KSTR2 + (j & 7) * 4] = v;
        }
        {
            int k2 = tid >> 3, d8 = (tid & 7) * 8;
            const __half* vp = qkv + (size_t)(b * Ntok + n0 + 2 * k2) * 3 * Hdim
                               + 2 * Hdim + h * HD + d8;
            uint4 a = *(const uint4*)vp;
            uint4 c = *(const uint4*)(vp + 3 * Hdim);
            unsigned* q = &Vs2[k2 * VSTR2 + d8];
            q[0] = __byte_perm(a.x, c.x, 0x5410); q[1] = __byte_perm(a.x, c.x, 0x7632);
            q[2] = __byte_perm(a.y, c.y, 0x5410); q[3] = __byte_perm(a.y, c.y, 0x7632);
            q[4] = __byte_perm(a.z, c.z, 0x5410); q[5] = __byte_perm(a.z, c.z, 0x7632);
            q[6] = __byte_perm(a.w, c.w, 0x5410); q[7] = __byte_perm(a.w, c.w, 0x7632);
        }
        __syncthreads();

        float sacc[8][4] = {};
        #pragma unroll
        for (int ks = 0; ks < 4; ks++) {
            #pragma unroll
            for (int nj = 0; nj < 8; nj++) {
                int key = nj * 8 + g;
                unsigned bf[2];
                bf[0] = Ks2[key * KSTR2 + ks * 8 + r];
                bf[1] = Ks2[key * KSTR2 + ks * 8 + r + 4];
                mma_f16(sacc[nj], qf[ks], bf);
            }
        }

        float mc0 = -1e30f, mc1 = -1e30f;
        #pragma unroll
        for (int nj = 0; nj < 8; nj++) {
            mc0 = fmaxf(mc0, fmaxf(sacc[nj][0], sacc[nj][1]));
            mc1 = fmaxf(mc1, fmaxf(sacc[nj][2], sacc[nj][3]));
        }
        mc0 = fmaxf(mc0, __shfl_xor_sync(0xffffffffu, mc0, 1));
        mc0 = fmaxf(mc0, __shfl_xor_sync(0xffffffffu, mc0, 2));
        mc1 = fmaxf(mc1, __shfl_xor_sync(0xffffffffu, mc1, 1));
        mc1 = fmaxf(mc1, __shfl_xor_sync(0xffffffffu, mc1, 2));
        float mn0 = fmaxf(m0, mc0), mn1 = fmaxf(m1, mc1);
        float a0 = __expf(m0 - mn0), a1 = __expf(m1 - mn1);
        float rs0 = 0.0f, rs1 = 0.0f;
        #pragma unroll
        for (int nj = 0; nj < 8; nj++) {
            float p0 = __expf(sacc[nj][0] - mn0);
            float p1 = __expf(sacc[nj][1] - mn0);
            float p2 = __expf(sacc[nj][2] - mn1);
            float p3 = __expf(sacc[nj][3] - mn1);
            rs0 += p0 + p1; rs1 += p2 + p3;
            Ps2[qrow * PSTR2 + nj * 4 + r]       = f2h2(p0, p1);
            Ps2[(qrow + 8) * PSTR2 + nj * 4 + r] = f2h2(p2, p3);
        }
        rs0 += __shfl_xor_sync(0xffffffffu, rs0, 1);
        rs0 += __shfl_xor_sync(0xffffffffu, rs0, 2);
        rs1 += __shfl_xor_sync(0xffffffffu, rs1, 1);
        rs1 += __shfl_xor_sync(0xffffffffu, rs1, 2);
        l0 = l0 * a0 + rs0;
        l1 = l1 * a1 + rs1;
        m0 = mn0; m1 = mn1;
        #pragma unroll
        for (int nj = 0; nj < 8; nj++) {
            oacc[nj][0] *= a0; oacc[nj][1] *= a0;
            oacc[nj][2] *= a1; oacc[nj][3] *= a1;
        }
        __syncwarp();

        #pragma unroll
        for (int ks = 0; ks < 4; ks++) {
            unsigned af[4];
            af[0] = Ps2[qrow * PSTR2 + ks * 8 + r];
            af[1] = Ps2[(qrow + 8) * PSTR2 + ks * 8 + r];
            af[2] = Ps2[qrow * PSTR2 + ks * 8 + r + 4];
            af[3] = Ps2[(qrow + 8) * PSTR2 + ks * 8 + r + 4];
            #pragma unroll
            for (int nj = 0; nj < 8; nj++) {
                unsigned bf[2];
                bf[0] = Vs2[(ks * 8 + r) * VSTR2 + nj * 8 + g];
                bf[1] = Vs2[(ks * 8 + r + 4) * VSTR2 + nj * 8 + g];
                mma_f16(oacc[nj], af, bf);
            }
        }
        __syncthreads();
    }

    float i0 = 1.0f / l0, i1 = 1.0f / l1;
    #pragma unroll
    for (int nj = 0; nj < 8; nj++) {
        int col = h * HD + nj * 8 + 2 * r;
        *(unsigned*)&out[(size_t)(b * Ntok + q0 + qrow) * Hdim + col]
            = f2h2(oacc[nj][0] * i0, oacc[nj][1] * i0);
        *(unsigned*)&out[(size_t)(b * Ntok + q0 + qrow + 8) * Hdim + col]
            = f2h2(oacc[nj][2] * i1, oacc[nj][3] * i1);
    }
}

// ------------------------- launch ------------------------------------------
extern "C" void kernel_launch(void* const* d_in, const int* in_sizes, int n_in,
                              void* d_out, int out_size)
{
    const float* x      = (const float*)d_in[0];
    const float* c      = (const float*)d_in[1];
    const float* w_mod  = (const float*)d_in[2];
    const float* b_mod  = (const float*)d_in[3];
    const float* w_qkv  = (const float*)d_in[4];
    const float* b_qkv  = (const float*)d_in[5];
    const float* w_proj = (const float*)d_in[6];
    const float* b_proj = (const float*)d_in[7];
    const float* w1     = (const float*)d_in[8];
    const float* b1     = (const float*)d_in[9];
    const float* w2     = (const float*)d_in[10];
    const float* b2     = (const float*)d_in[11];
    float* out = (float*)d_out;

    float *cm, *x2;
    __half *xmh, *qkvh, *attnh, *xm2h, *hidh;
    unsigned *wqkvh, *w1h, *w2h, *wph;
    cudaGetSymbolAddress((void**)&cm,    g_cm);
    cudaGetSymbolAddress((void**)&xmh,   g_xmh);
    cudaGetSymbolAddress((void**)&qkvh,  g_qkvh);
    cudaGetSymbolAddress((void**)&attnh, g_attnh);
    cudaGetSymbolAddress((void**)&x2,    g_x2);
    cudaGetSymbolAddress((void**)&xm2h,  g_xm2h);
    cudaGetSymbolAddress((void**)&hidh,  g_hidh);
    cudaGetSymbolAddress((void**)&wqkvh, g_wqkvh);
    cudaGetSymbolAddress((void**)&w1h,   g_w1h);
    cudaGetSymbolAddress((void**)&w2h,   g_w2h);
    cudaGetSymbolAddress((void**)&wph,   g_wph);

    cudaFuncSetAttribute(gemm_h<0>, cudaFuncAttributeMaxDynamicSharedMemorySize, GSMEM2);
    cudaFuncSetAttribute(gemm_h<1>, cudaFuncAttributeMaxDynamicSharedMemorySize, GSMEM2);
    cudaFuncSetAttribute(gemm_h<2>, cudaFuncAttributeMaxDynamicSharedMemorySize, GSMEM2);
    cudaFuncSetAttribute(gemm_h<3>, cudaFuncAttributeMaxDynamicSharedMemorySize, GSMEM2);

    // 0. weight conversions (pair-interleaved half2)
    wpair_kernel<<<dim3(3 * Hdim / 256, Hdim / 2), 256>>>(w_qkv, wqkvh, 3 * Hdim);
    wpair_kernel<<<dim3(DFF / 256, Hdim / 2), 256>>>(w1, w1h, DFF);
    wpair_kernel<<<dim3(Hdim / 256, DFF / 2), 256>>>(w2, w2h, Hdim);
    wpair_kernel<<<dim3(Hdim / 256, Hdim / 2), 256>>>(w_proj, wph, Hdim);

    // 1. conditioning -> modulation params
    cond_mod_kernel<<<dim3(24, 4), 256>>>(c, w_mod, b_mod, cm);

    // 2. LN + modulate (msa) -> half
    ln_mod_h_kernel<<<ROWS, 256>>>(x, cm, 0, Hdim, xmh);

    // 3. qkv (half out, Q pre-scaled by 1/8)
    gemm_h<0><<<dim3(3 * Hdim / 256, ROWS / 128), 256, GSMEM2>>>(
        xmh, wqkvh, b_qkv, qkvh, ROWS, 3 * Hdim, Hdim, nullptr, nullptr);

    // 4. flash attention -> half attnout
    flash_attn<<<dim3(Ntok / 128, Bsz * NH), 256>>>(qkvh, attnh);

    // 5. x2 = (attnout @ w_proj + b_proj) * (1 + gate_msa)   (float out)
    gemm_h<2><<<dim3(Hdim / 256, ROWS / 128), 256, GSMEM2>>>(
        attnh, wph, b_proj, x2, ROWS, Hdim, Hdim, cm + 2 * Hdim, nullptr);

    // 6. LN + modulate (mlp) -> half
    ln_mod_h_kernel<<<ROWS, 256>>>(x2, cm, 3 * Hdim, 4 * Hdim, xm2h);

    // 7. hid = gelu(xm2 @ w1 + b1)  (half out)
    gemm_h<1><<<dim3(DFF / 256, ROWS / 128), 256, GSMEM2>>>(
        xm2h, w1h, b1, hidh, ROWS, DFF, Hdim, nullptr, nullptr);

    // 8. out = x2 + gate_mlp * (hid @ w2 + b2)  (float out)
    gemm_h<3><<<dim3(Hdim / 256, ROWS / 128), 256, GSMEM2>>>(
        hidh, w2h, b2, out, ROWS, Hdim, DFF, cm + 5 * Hdim, x2);
}

// round 10
// speedup vs baseline: 6.5433x; 1.2042x over previous
#include <cuda_runtime.h>
#include <cuda_fp16.h>
#include <cstdint>
#include <math.h>

// ---------------------------------------------------------------------------
// DiT block: fp16 mma.sync GEMMs (cp.async 3-stage) + double-buffered flash
// attention + split-K cond modulation. B=4, N=1024, H=1024, heads=16, d=64.
// ---------------------------------------------------------------------------

#define Bsz 4
#define Ntok 1024
#define Hdim 1024
#define NH 16
#define HD 64
#define DFF 4096
#define ROWS (Bsz * Ntok)      // 4096
#define CM_STRIDE (6 * Hdim)   // 6144

// ------------------------- scratch (device globals) ------------------------
__device__ float    g_cm[Bsz * CM_STRIDE];
__device__ float    g_cpart[Bsz * 8 * CM_STRIDE];
__device__ __half   g_xmh[ROWS * Hdim];
__device__ __half   g_qkvh[ROWS * 3 * Hdim];
__device__ __half   g_attnh[ROWS * Hdim];
__device__ float    g_x2[ROWS * Hdim];
__device__ __half   g_xm2h[ROWS * Hdim];
__device__ __half   g_hidh[ROWS * DFF];
// pair-interleaved half2 weights: [K/2][N], elem = (w[2k][n], w[2k+1][n])
__device__ unsigned g_wqkvh[(Hdim / 2) * 3 * Hdim];
__device__ unsigned g_w1h[(Hdim / 2) * DFF];
__device__ unsigned g_w2h[(DFF / 2) * Hdim];
__device__ unsigned g_wph[(Hdim / 2) * Hdim];

// ------------------------- helpers -----------------------------------------
__device__ __forceinline__ unsigned f2h2(float a, float b) {
    __half2 h = __floats2half2_rn(a, b);
    return *(unsigned*)&h;
}

__device__ __forceinline__ uint32_t smem_u32(const void* p) {
    uint32_t a;
    asm("{ .reg .u64 t; cvta.to.shared.u64 t, %1; cvt.u32.u64 %0, t; }"
        : "=r"(a) : "l"(p));
    return a;
}

__device__ __forceinline__ void mma_f16(float* d, const unsigned* a, const unsigned* b) {
    asm volatile(
        "mma.sync.aligned.m16n8k16.row.col.f32.f16.f16.f32 "
        "{%0,%1,%2,%3},{%4,%5,%6,%7},{%8,%9},{%0,%1,%2,%3};\n"
        : "+f"(d[0]), "+f"(d[1]), "+f"(d[2]), "+f"(d[3])
        : "r"(a[0]), "r"(a[1]), "r"(a[2]), "r"(a[3]), "r"(b[0]), "r"(b[1]));
}

#define CP_ASYNC16(saddr, gptr) \
    asm volatile("cp.async.cg.shared.global [%0], [%1], 16;" \
                 :: "r"(saddr), "l"(gptr) : "memory")
#define CP_COMMIT() asm volatile("cp.async.commit_group;" ::: "memory")
#define CP_WAIT1()  asm volatile("cp.async.wait_group 1;" ::: "memory")

// ------------------------- weight -> half2 pair-interleave ------------------
__global__ void wpair_kernel(const float* __restrict__ w, unsigned* __restrict__ o, int N)
{
    int n = blockIdx.x * 256 + threadIdx.x;
    int k2 = blockIdx.y;
    o[(size_t)k2 * N + n] = f2h2(w[(size_t)(2 * k2) * N + n],
                                 w[(size_t)(2 * k2 + 1) * N + n]);
}

// ------------------------- cond modulation (split-K) ------------------------
__global__ void cond_part_kernel(const float* __restrict__ c,
                                 const float* __restrict__ w,
                                 float* __restrict__ part)
{
    // grid (24, 4, 8)
    int j = blockIdx.x * 256 + threadIdx.x;
    int b = blockIdx.y, kc = blockIdx.z;
    __shared__ float sc[128];
    if (threadIdx.x < 128) {
        float t = c[b * Hdim + kc * 128 + threadIdx.x];
        sc[threadIdx.x] = t / (1.0f + expf(-t));
    }
    __syncthreads();
    float acc = 0.0f;
    const float* wp = w + (size_t)(kc * 128) * CM_STRIDE + j;
    #pragma unroll 8
    for (int k = 0; k < 128; k++)
        acc += sc[k] * wp[(size_t)k * CM_STRIDE];
    part[(size_t)(b * 8 + kc) * CM_STRIDE + j] = acc;
}

__global__ void cond_reduce_kernel(const float* __restrict__ part,
                                   const float* __restrict__ bmod,
                                   float* __restrict__ cm)
{
    int j = blockIdx.x * 256 + threadIdx.x;   // grid (24, 4)
    int b = blockIdx.y;
    float acc = bmod[j];
    #pragma unroll
    for (int s = 0; s < 8; s++)
        acc += part[(size_t)(b * 8 + s) * CM_STRIDE + j];
    cm[b * CM_STRIDE + j] = acc;
}

// ------------------------- LayerNorm + modulate -> half ---------------------
__global__ void ln_mod_h_kernel(const float* __restrict__ x,
                                const float* __restrict__ cm,
                                int shiftOff, int scaleOff,
                                __half* __restrict__ out)
{
    int row = blockIdx.x;
    int b = row >> 10;
    const float* xr = x + (size_t)row * Hdim;
    int tid = threadIdx.x;
    int col4 = tid * 4;
    float4 t = *(const float4*)(xr + col4);
    float s  = t.x + t.y + t.z + t.w;
    float sq = t.x * t.x + t.y * t.y + t.z * t.z + t.w * t.w;
    #pragma unroll
    for (int o = 16; o > 0; o >>= 1) {
        s  += __shfl_down_sync(0xffffffffu, s,  o);
        sq += __shfl_down_sync(0xffffffffu, sq, o);
    }
    __shared__ float red[20];
    int warp = tid >> 5, lane = tid & 31;
    if (lane == 0) { red[warp] = s; red[warp + 8] = sq; }
    __syncthreads();
    if (tid == 0) {
        float S = 0.0f, SQ = 0.0f;
        #pragma unroll
        for (int w = 0; w < 8; w++) { S += red[w]; SQ += red[w + 8]; }
        float mu = S * (1.0f / Hdim);
        float var = SQ * (1.0f / Hdim) - mu * mu;
        red[16] = mu;
        red[17] = rsqrtf(var + 1e-5f);
    }
    __syncthreads();
    float mu = red[16], inv = red[17];
    const float* sh = cm + b * CM_STRIDE + shiftOff;
    const float* sc = cm + b * CM_STRIDE + scaleOff;
    float4 shv = *(const float4*)(sh + col4);
    float4 scv = *(const float4*)(sc + col4);
    float v0 = (t.x - mu) * inv * (1.0f + scv.x) + shv.x;
    float v1 = (t.y - mu) * inv * (1.0f + scv.y) + shv.y;
    float v2 = (t.z - mu) * inv * (1.0f + scv.z) + shv.z;
    float v3 = (t.w - mu) * inv * (1.0f + scv.w) + shv.w;
    uint2 o2 = make_uint2(f2h2(v0, v1), f2h2(v2, v3));
    *(uint2*)&out[(size_t)row * Hdim + col4] = o2;
}

// ------------------------- fp16 GEMM: 128x256 block, cp.async 3-stage -------
#define AS2 20      // A stage row stride (half2 units): 16 + 4 pad
#define BSTR2 264   // B stage row stride: 256 + 8 pad
#define STAGE_U32 (128 * AS2 + 16 * BSTR2)   // 6784
#define GSMEM2 (3 * STAGE_U32 * 4)           // 81408 bytes

template<int EPI>
__global__ __launch_bounds__(256, 1)
void gemm_h(const __half* __restrict__ A, const unsigned* __restrict__ Bp,
            const float* __restrict__ bias, void* __restrict__ Cout,
            int M, int N, int K,
            const float* __restrict__ gate, const float* __restrict__ resid)
{
    extern __shared__ unsigned sm[];
    int tid = threadIdx.x;
    int warp = tid >> 5, lane = tid & 31;
    int warpM = warp >> 2, warpN = warp & 3;   // 2x4 warp grid, 64x64 warp tile
    int g = lane >> 2, r = lane & 3;
    int rowBase = blockIdx.y * 128, colBase = blockIdx.x * 256;
    int kts = K / 32;

    uint32_t smBase = smem_u32(sm);

    auto loadStage = [&](int stage, int kt) {
        uint32_t sA = smBase + stage * STAGE_U32 * 4;
        uint32_t sB = sA + 128 * AS2 * 4;
        const __half* Ag = A + (size_t)rowBase * K + kt * 32;
        const unsigned* Bg = Bp + (size_t)(kt * 16) * N + colBase;
        #pragma unroll
        for (int i = 0; i < 2; i++) {
            int j = tid + i * 256;
            int row = j >> 2, c = (j & 3) * 4;
            CP_ASYNC16(sA + (row * AS2 + c) * 4, Ag + (size_t)row * K + c * 2);
        }
        #pragma unroll
        for (int i = 0; i < 4; i++) {
            int j = tid + i * 256;
            int k2 = j >> 6, c4 = (j & 63) * 4;
            CP_ASYNC16(sB + (k2 * BSTR2 + c4) * 4, Bg + (size_t)k2 * N + c4);
        }
    };

    float acc[4][8][4] = {};

    loadStage(0, 0); CP_COMMIT();
    loadStage(1, 1); CP_COMMIT();

    for (int kt = 0; kt < kts; kt++) {
        CP_WAIT1();
        __syncthreads();
        if (kt + 2 < kts) loadStage((kt + 2) % 3, kt + 2);
        CP_COMMIT();

        unsigned* sA = sm + (kt % 3) * STAGE_U32;
        unsigned* sB = sA + 128 * AS2;
        #pragma unroll
        for (int ks = 0; ks < 2; ks++) {
            unsigned af[4][4], bf[8][2];
            #pragma unroll
            for (int mi = 0; mi < 4; mi++) {
                int row = warpM * 64 + mi * 16 + g;
                af[mi][0] = sA[row * AS2 + ks * 8 + r];
                af[mi][1] = sA[(row + 8) * AS2 + ks * 8 + r];
                af[mi][2] = sA[row * AS2 + ks * 8 + r + 4];
                af[mi][3] = sA[(row + 8) * AS2 + ks * 8 + r + 4];
            }
            #pragma unroll
            for (int nj = 0; nj < 8; nj++) {
                int col = warpN * 64 + nj * 8 + g;
                bf[nj][0] = sB[(ks * 8 + r) * BSTR2 + col];
                bf[nj][1] = sB[(ks * 8 + r + 4) * BSTR2 + col];
            }
            #pragma unroll
            for (int mi = 0; mi < 4; mi++)
                #pragma unroll
                for (int nj = 0; nj < 8; nj++)
                    mma_f16(acc[mi][nj], af[mi], bf[nj]);
        }
    }

    // epilogue
    #pragma unroll
    for (int mi = 0; mi < 4; mi++) {
        #pragma unroll
        for (int rr = 0; rr < 2; rr++) {
            int row = rowBase + warpM * 64 + mi * 16 + g + rr * 8;
            int b = row >> 10;
            #pragma unroll
            for (int nj = 0; nj < 8; nj++) {
                int col = colBase + warpN * 64 + nj * 8 + r * 2;
                float v0 = acc[mi][nj][rr * 2 + 0] + __ldg(&bias[col]);
                float v1 = acc[mi][nj][rr * 2 + 1] + __ldg(&bias[col + 1]);
                if (EPI == 0) {
                    float sc = (col < Hdim) ? 0.125f : 1.0f;
                    __half* Ch = (__half*)Cout;
                    *(unsigned*)&Ch[(size_t)row * N + col] = f2h2(v0 * sc, v1 * sc);
                } else if (EPI == 1) {
                    v0 = 0.5f * v0 * (1.0f + erff(v0 * 0.70710678118654752f));
                    v1 = 0.5f * v1 * (1.0f + erff(v1 * 0.70710678118654752f));
                    __half* Ch = (__half*)Cout;
                    *(unsigned*)&Ch[(size_t)row * N + col] = f2h2(v0, v1);
                } else if (EPI == 2) {
                    v0 *= (1.0f + __ldg(&gate[b * CM_STRIDE + col]));
                    v1 *= (1.0f + __ldg(&gate[b * CM_STRIDE + col + 1]));
                    *(float2*)&((float*)Cout)[(size_t)row * N + col] = make_float2(v0, v1);
                } else {
                    v0 = resid[(size_t)row * N + col]     + __ldg(&gate[b * CM_STRIDE + col])     * v0;
                    v1 = resid[(size_t)row * N + col + 1] + __ldg(&gate[b * CM_STRIDE + col + 1]) * v1;
                    *(float2*)&((float*)Cout)[(size_t)row * N + col] = make_float2(v0, v1);
                }
            }
        }
    }
}

// ------------------------- flash attention (double-buffered K/V) ------------
#define PSTR2 36
#define KSTR2 36
#define VSTR2 72
#define FPS_U32 (128 * PSTR2)            // 4608
#define FKB_U32 (64 * KSTR2)             // 2304 per buffer
#define FVB_U32 (32 * VSTR2)             // 2304 per buffer
#define FSMEM ((FPS_U32 + 2 * FKB_U32 + 2 * FVB_U32) * 4)   // 55296 bytes

__global__ __launch_bounds__(256)
void flash_attn(const __half* __restrict__ qkv, __half* __restrict__ out)
{
    extern __shared__ unsigned fsm[];
    unsigned* Ps2 = fsm;
    unsigned* KsB = fsm + FPS_U32;                 // [2][FKB_U32]
    unsigned* VsB = fsm + FPS_U32 + 2 * FKB_U32;   // [2][FVB_U32]

    int tid = threadIdx.x;
    int warp = tid >> 5, lane = tid & 31;
    int g = lane >> 2, r = lane & 3;
    int bh = blockIdx.y;
    int b = bh >> 4, h = bh & 15;
    int q0 = blockIdx.x * 128;

    // ---- stage Q (pre-scaled in qkv epilogue) ----
    #pragma unroll
    for (int i = 0; i < 4; i++) {
        int j = tid + i * 256;
        int row = j >> 3, d8 = (j & 7) * 8;
        uint4 v = *(const uint4*)(qkv + (size_t)(b * Ntok + q0 + row) * 3 * Hdim
                                  + h * HD + d8);
        *(uint4*)&Ps2[row * PSTR2 + (j & 7) * 4] = v;
    }

    // ---- load K/V tile 0 into buffer 0 ----
    {
        unsigned* Ks2 = KsB;
        unsigned* Vs2 = VsB;
        #pragma unroll
        for (int i = 0; i < 2; i++) {
            int j = tid + i * 256;
            int key = j >> 3, d8 = (j & 7) * 8;
            uint4 v = *(const uint4*)(qkv + (size_t)(b * Ntok + key) * 3 * Hdim
                                      + Hdim + h * HD + d8);
            *(uint4*)&Ks2[key * KSTR2 + (j & 7) * 4] = v;
        }
        int k2 = tid >> 3, d8 = (tid & 7) * 8;
        const __half* vp = qkv + (size_t)(b * Ntok + 2 * k2) * 3 * Hdim
                           + 2 * Hdim + h * HD + d8;
        uint4 a = *(const uint4*)vp;
        uint4 c = *(const uint4*)(vp + 3 * Hdim);
        unsigned* q = &Vs2[k2 * VSTR2 + d8];
        q[0] = __byte_perm(a.x, c.x, 0x5410); q[1] = __byte_perm(a.x, c.x, 0x7632);
        q[2] = __byte_perm(a.y, c.y, 0x5410); q[3] = __byte_perm(a.y, c.y, 0x7632);
        q[4] = __byte_perm(a.z, c.z, 0x5410); q[5] = __byte_perm(a.z, c.z, 0x7632);
        q[6] = __byte_perm(a.w, c.w, 0x5410); q[7] = __byte_perm(a.w, c.w, 0x7632);
    }
    __syncthreads();

    int qrow = warp * 16 + g;
    unsigned qf[4][4];
    #pragma unroll
    for (int ks = 0; ks < 4; ks++) {
        qf[ks][0] = Ps2[qrow * PSTR2 + ks * 8 + r];
        qf[ks][1] = Ps2[(qrow + 8) * PSTR2 + ks * 8 + r];
        qf[ks][2] = Ps2[qrow * PSTR2 + ks * 8 + r + 4];
        qf[ks][3] = Ps2[(qrow + 8) * PSTR2 + ks * 8 + r + 4];
    }
    __syncwarp();

    float oacc[8][4] = {};
    float m0 = -1e30f, m1 = -1e30f, l0 = 0.0f, l1 = 0.0f;

    const int NIT = Ntok / 64;   // 16
    for (int it = 0; it < NIT; it++) {
        int cur = it & 1, nxt = cur ^ 1;
        unsigned* Ks2 = KsB + cur * FKB_U32;
        unsigned* Vs2 = VsB + cur * FVB_U32;

        // ---- prefetch next tile (gmem -> regs), overlapped with compute ----
        uint4 pk0, pk1, pva, pvc;
        int pk2 = tid >> 3, pd8 = (tid & 7) * 8;
        if (it + 1 < NIT) {
            int n1 = (it + 1) * 64;
            {
                int j = tid;
                int key = j >> 3, d8 = (j & 7) * 8;
                pk0 = *(const uint4*)(qkv + (size_t)(b * Ntok + n1 + key) * 3 * Hdim
                                      + Hdim + h * HD + d8);
                j = tid + 256;
                key = j >> 3; d8 = (j & 7) * 8;
                pk1 = *(const uint4*)(qkv + (size_t)(b * Ntok + n1 + key) * 3 * Hdim
                                      + Hdim + h * HD + d8);
            }
            const __half* vp = qkv + (size_t)(b * Ntok + n1 + 2 * pk2) * 3 * Hdim
                               + 2 * Hdim + h * HD + pd8;
            pva = *(const uint4*)vp;
            pvc = *(const uint4*)(vp + 3 * Hdim);
        }

        // ---- S = Q K^T ----
        float sacc[8][4] = {};
        #pragma unroll
        for (int ks = 0; ks < 4; ks++) {
            #pragma unroll
            for (int nj = 0; nj < 8; nj++) {
                int key = nj * 8 + g;
                unsigned bf[2];
                bf[0] = Ks2[key * KSTR2 + ks * 8 + r];
                bf[1] = Ks2[key * KSTR2 + ks * 8 + r + 4];
                mma_f16(sacc[nj], qf[ks], bf);
            }
        }

        // ---- online softmax ----
        float mc0 = -1e30f, mc1 = -1e30f;
        #pragma unroll
        for (int nj = 0; nj < 8; nj++) {
            mc0 = fmaxf(mc0, fmaxf(sacc[nj][0], sacc[nj][1]));
            mc1 = fmaxf(mc1, fmaxf(sacc[nj][2], sacc[nj][3]));
        }
        mc0 = fmaxf(mc0, __shfl_xor_sync(0xffffffffu, mc0, 1));
        mc0 = fmaxf(mc0, __shfl_xor_sync(0xffffffffu, mc0, 2));
        mc1 = fmaxf(mc1, __shfl_xor_sync(0xffffffffu, mc1, 1));
        mc1 = fmaxf(mc1, __shfl_xor_sync(0xffffffffu, mc1, 2));
        float mn0 = fmaxf(m0, mc0), mn1 = fmaxf(m1, mc1);
        float a0 = __expf(m0 - mn0), a1 = __expf(m1 - mn1);
        float rs0 = 0.0f, rs1 = 0.0f;
        #pragma unroll
        for (int nj = 0; nj < 8; nj++) {
            float p0 = __expf(sacc[nj][0] - mn0);
            float p1 = __expf(sacc[nj][1] - mn0);
            float p2 = __expf(sacc[nj][2] - mn1);
            float p3 = __expf(sacc[nj][3] - mn1);
            rs0 += p0 + p1; rs1 += p2 + p3;
            Ps2[qrow * PSTR2 + nj * 4 + r]       = f2h2(p0, p1);
            Ps2[(qrow + 8) * PSTR2 + nj * 4 + r] = f2h2(p2, p3);
        }
        rs0 += __shfl_xor_sync(0xffffffffu, rs0, 1);
        rs0 += __shfl_xor_sync(0xffffffffu, rs0, 2);
        rs1 += __shfl_xor_sync(0xffffffffu, rs1, 1);
        rs1 += __shfl_xor_sync(0xffffffffu, rs1, 2);
        l0 = l0 * a0 + rs0;
        l1 = l1 * a1 + rs1;
        m0 = mn0; m1 = mn1;
        #pragma unroll
        for (int nj = 0; nj < 8; nj++) {
            oacc[nj][0] *= a0; oacc[nj][1] *= a0;
            oacc[nj][2] *= a1; oacc[nj][3] *= a1;
        }
        __syncwarp();

        // ---- O += P V ----
        #pragma unroll
        for (int ks = 0; ks < 4; ks++) {
            unsigned af[4];
            af[0] = Ps2[qrow * PSTR2 + ks * 8 + r];
            af[1] = Ps2[(qrow + 8) * PSTR2 + ks * 8 + r];
            af[2] = Ps2[qrow * PSTR2 + ks * 8 + r + 4];
            af[3] = Ps2[(qrow + 8) * PSTR2 + ks * 8 + r + 4];
            #pragma unroll
            for (int nj = 0; nj < 8; nj++) {
                unsigned bf[2];
                bf[0] = Vs2[(ks * 8 + r) * VSTR2 + nj * 8 + g];
                bf[1] = Vs2[(ks * 8 + r + 4) * VSTR2 + nj * 8 + g];
                mma_f16(oacc[nj], af, bf);
            }
        }

        // ---- store prefetched tile into the other buffer ----
        if (it + 1 < NIT) {
            unsigned* Kn = KsB + nxt * FKB_U32;
            unsigned* Vn = VsB + nxt * FVB_U32;
            {
                int j = tid;
                int key = j >> 3;
                *(uint4*)&Kn[key * KSTR2 + (j & 7) * 4] = pk0;
                j = tid + 256;
                key = j >> 3;
                *(uint4*)&Kn[key * KSTR2 + (j & 7) * 4] = pk1;
            }
            unsigned* q = &Vn[pk2 * VSTR2 + pd8];
            q[0] = __byte_perm(pva.x, pvc.x, 0x5410); q[1] = __byte_perm(pva.x, pvc.x, 0x7632);
            q[2] = __byte_perm(pva.y, pvc.y, 0x5410); q[3] = __byte_perm(pva.y, pvc.y, 0x7632);
            q[4] = __byte_perm(pva.z, pvc.z, 0x5410); q[5] = __byte_perm(pva.z, pvc.z, 0x7632);
            q[6] = __byte_perm(pva.w, pvc.w, 0x5410); q[7] = __byte_perm(pva.w, pvc.w, 0x7632);
        }
        __syncthreads();
    }

    float i0 = 1.0f / l0, i1 = 1.0f / l1;
    #pragma unroll
    for (int nj = 0; nj < 8; nj++) {
        int col = h * HD + nj * 8 + 2 * r;
        *(unsigned*)&out[(size_t)(b * Ntok + q0 + qrow) * Hdim + col]
            = f2h2(oacc[nj][0] * i0, oacc[nj][1] * i0);
        *(unsigned*)&out[(size_t)(b * Ntok + q0 + qrow + 8) * Hdim + col]
            = f2h2(oacc[nj][2] * i1, oacc[nj][3] * i1);
    }
}

// ------------------------- launch ------------------------------------------
extern "C" void kernel_launch(void* const* d_in, const int* in_sizes, int n_in,
                              void* d_out, int out_size)
{
    const float* x      = (const float*)d_in[0];
    const float* c      = (const float*)d_in[1];
    const float* w_mod  = (const float*)d_in[2];
    const float* b_mod  = (const float*)d_in[3];
    const float* w_qkv  = (const float*)d_in[4];
    const float* b_qkv  = (const float*)d_in[5];
    const float* w_proj = (const float*)d_in[6];
    const float* b_proj = (const float*)d_in[7];
    const float* w1     = (const float*)d_in[8];
    const float* b1     = (const float*)d_in[9];
    const float* w2     = (const float*)d_in[10];
    const float* b2     = (const float*)d_in[11];
    float* out = (float*)d_out;

    float *cm, *cpart, *x2;
    __half *xmh, *qkvh, *attnh, *xm2h, *hidh;
    unsigned *wqkvh, *w1h, *w2h, *wph;
    cudaGetSymbolAddress((void**)&cm,    g_cm);
    cudaGetSymbolAddress((void**)&cpart, g_cpart);
    cudaGetSymbolAddress((void**)&xmh,   g_xmh);
    cudaGetSymbolAddress((void**)&qkvh,  g_qkvh);
    cudaGetSymbolAddress((void**)&attnh, g_attnh);
    cudaGetSymbolAddress((void**)&x2,    g_x2);
    cudaGetSymbolAddress((void**)&xm2h,  g_xm2h);
    cudaGetSymbolAddress((void**)&hidh,  g_hidh);
    cudaGetSymbolAddress((void**)&wqkvh, g_wqkvh);
    cudaGetSymbolAddress((void**)&w1h,   g_w1h);
    cudaGetSymbolAddress((void**)&w2h,   g_w2h);
    cudaGetSymbolAddress((void**)&wph,   g_wph);

    cudaFuncSetAttribute(gemm_h<0>, cudaFuncAttributeMaxDynamicSharedMemorySize, GSMEM2);
    cudaFuncSetAttribute(gemm_h<1>, cudaFuncAttributeMaxDynamicSharedMemorySize, GSMEM2);
    cudaFuncSetAttribute(gemm_h<2>, cudaFuncAttributeMaxDynamicSharedMemorySize, GSMEM2);
    cudaFuncSetAttribute(gemm_h<3>, cudaFuncAttributeMaxDynamicSharedMemorySize, GSMEM2);
    cudaFuncSetAttribute(flash_attn, cudaFuncAttributeMaxDynamicSharedMemorySize, FSMEM);

    // 0. weight conversions (pair-interleaved half2)
    wpair_kernel<<<dim3(3 * Hdim / 256, Hdim / 2), 256>>>(w_qkv, wqkvh, 3 * Hdim);
    wpair_kernel<<<dim3(DFF / 256, Hdim / 2), 256>>>(w1, w1h, DFF);
    wpair_kernel<<<dim3(Hdim / 256, DFF / 2), 256>>>(w2, w2h, Hdim);
    wpair_kernel<<<dim3(Hdim / 256, Hdim / 2), 256>>>(w_proj, wph, Hdim);

    // 1. conditioning -> modulation params (split-K)
    cond_part_kernel<<<dim3(24, 4, 8), 256>>>(c, w_mod, cpart);
    cond_reduce_kernel<<<dim3(24, 4), 256>>>(cpart, b_mod, cm);

    // 2. LN + modulate (msa) -> half
    ln_mod_h_kernel<<<ROWS, 256>>>(x, cm, 0, Hdim, xmh);

    // 3. qkv (half out, Q pre-scaled by 1/8)
    gemm_h<0><<<dim3(3 * Hdim / 256, ROWS / 128), 256, GSMEM2>>>(
        xmh, wqkvh, b_qkv, qkvh, ROWS, 3 * Hdim, Hdim, nullptr, nullptr);

    // 4. flash attention -> half attnout
    flash_attn<<<dim3(Ntok / 128, Bsz * NH), 256, FSMEM>>>(qkvh, attnh);

    // 5. x2 = (attnout @ w_proj + b_proj) * (1 + gate_msa)   (float out)
    gemm_h<2><<<dim3(Hdim / 256, ROWS / 128), 256, GSMEM2>>>(
        attnh, wph, b_proj, x2, ROWS, Hdim, Hdim, cm + 2 * Hdim, nullptr);

    // 6. LN + modulate (mlp) -> half
    ln_mod_h_kernel<<<ROWS, 256>>>(x2, cm, 3 * Hdim, 4 * Hdim, xm2h);

    // 7. hid = gelu(xm2 @ w1 + b1)  (half out)
    gemm_h<1><<<dim3(DFF / 256, ROWS / 128), 256, GSMEM2>>>(
        xm2h, w1h, b1, hidh, ROWS, DFF, Hdim, nullptr, nullptr);

    // 8. out = x2 + gate_mlp * (hid @ w2 + b2)  (float out)
    gemm_h<3><<<dim3(Hdim / 256, ROWS / 128), 256, GSMEM2>>>(
        hidh, w2h, b2, out, ROWS, Hdim, DFF, cm + 5 * Hdim, x2);
}

// round 11
// speedup vs baseline: 6.5487x; 1.0008x over previous
#include <cuda_runtime.h>
#include <cuda_fp16.h>
#include <cstdint>
#include <math.h>

// ---------------------------------------------------------------------------
// DiT block: fp16 mma.sync GEMMs (cp.async 3-stage + ldmatrix fragments)
//            + double-buffered flash attention + split-K cond modulation.
// B=4, N=1024, H=1024, heads=16, d=64, D_FF=4096
// ---------------------------------------------------------------------------

#define Bsz 4
#define Ntok 1024
#define Hdim 1024
#define NH 16
#define HD 64
#define DFF 4096
#define ROWS (Bsz * Ntok)      // 4096
#define CM_STRIDE (6 * Hdim)   // 6144

// ------------------------- scratch (device globals) ------------------------
__device__ float    g_cm[Bsz * CM_STRIDE];
__device__ float    g_cpart[Bsz * 8 * CM_STRIDE];
__device__ __half   g_xmh[ROWS * Hdim];
__device__ __half   g_qkvh[ROWS * 3 * Hdim];
__device__ __half   g_attnh[ROWS * Hdim];
__device__ float    g_x2[ROWS * Hdim];
__device__ __half   g_xm2h[ROWS * Hdim];
__device__ __half   g_hidh[ROWS * DFF];
// plain half weights [K][N]
__device__ __half   g_wqkvH[Hdim * 3 * Hdim];
__device__ __half   g_w1H[Hdim * DFF];
__device__ __half   g_w2H[DFF * Hdim];
__device__ __half   g_wpH[Hdim * Hdim];

// ------------------------- helpers -----------------------------------------
__device__ __forceinline__ unsigned f2h2(float a, float b) {
    __half2 h = __floats2half2_rn(a, b);
    return *(unsigned*)&h;
}

__device__ __forceinline__ uint32_t smem_u32(const void* p) {
    uint32_t a;
    asm("{ .reg .u64 t; cvta.to.shared.u64 t, %1; cvt.u32.u64 %0, t; }"
        : "=r"(a) : "l"(p));
    return a;
}

__device__ __forceinline__ void mma_f16(float* d, const unsigned* a, const unsigned* b) {
    asm volatile(
        "mma.sync.aligned.m16n8k16.row.col.f32.f16.f16.f32 "
        "{%0,%1,%2,%3},{%4,%5,%6,%7},{%8,%9},{%0,%1,%2,%3};\n"
        : "+f"(d[0]), "+f"(d[1]), "+f"(d[2]), "+f"(d[3])
        : "r"(a[0]), "r"(a[1]), "r"(a[2]), "r"(a[3]), "r"(b[0]), "r"(b[1]));
}

#define LDSM4(r0, r1, r2, r3, a) \
    asm volatile("ldmatrix.sync.aligned.m8n8.x4.shared.b16 {%0,%1,%2,%3}, [%4];" \
                 : "=r"(r0), "=r"(r1), "=r"(r2), "=r"(r3) : "r"(a))
#define LDSM4T(r0, r1, r2, r3, a) \
    asm volatile("ldmatrix.sync.aligned.m8n8.x4.trans.shared.b16 {%0,%1,%2,%3}, [%4];" \
                 : "=r"(r0), "=r"(r1), "=r"(r2), "=r"(r3) : "r"(a))

#define CP_ASYNC16(saddr, gptr) \
    asm volatile("cp.async.cg.shared.global [%0], [%1], 16;" \
                 :: "r"(saddr), "l"(gptr) : "memory")
#define CP_COMMIT() asm volatile("cp.async.commit_group;" ::: "memory")
#define CP_WAIT1()  asm volatile("cp.async.wait_group 1;" ::: "memory")

// ------------------------- weight -> half (vectorized) ----------------------
__global__ void whalf_kernel(const float* __restrict__ w, __half* __restrict__ o)
{
    size_t i = (size_t)blockIdx.x * 256 + threadIdx.x;
    float4 v = *(const float4*)(w + i * 4);
    uint2 h = make_uint2(f2h2(v.x, v.y), f2h2(v.z, v.w));
    *(uint2*)(o + i * 4) = h;
}

// ------------------------- cond modulation (split-K) ------------------------
__global__ void cond_part_kernel(const float* __restrict__ c,
                                 const float* __restrict__ w,
                                 float* __restrict__ part)
{
    int j = blockIdx.x * 256 + threadIdx.x;
    int b = blockIdx.y, kc = blockIdx.z;
    __shared__ float sc[128];
    if (threadIdx.x < 128) {
        float t = c[b * Hdim + kc * 128 + threadIdx.x];
        sc[threadIdx.x] = t / (1.0f + expf(-t));
    }
    __syncthreads();
    float acc = 0.0f;
    const float* wp = w + (size_t)(kc * 128) * CM_STRIDE + j;
    #pragma unroll 8
    for (int k = 0; k < 128; k++)
        acc += sc[k] * wp[(size_t)k * CM_STRIDE];
    part[(size_t)(b * 8 + kc) * CM_STRIDE + j] = acc;
}

__global__ void cond_reduce_kernel(const float* __restrict__ part,
                                   const float* __restrict__ bmod,
                                   float* __restrict__ cm)
{
    int j = blockIdx.x * 256 + threadIdx.x;
    int b = blockIdx.y;
    float acc = bmod[j];
    #pragma unroll
    for (int s = 0; s < 8; s++)
        acc += part[(size_t)(b * 8 + s) * CM_STRIDE + j];
    cm[b * CM_STRIDE + j] = acc;
}

// ------------------------- LayerNorm + modulate -> half ---------------------
__global__ void ln_mod_h_kernel(const float* __restrict__ x,
                                const float* __restrict__ cm,
                                int shiftOff, int scaleOff,
                                __half* __restrict__ out)
{
    int row = blockIdx.x;
    int b = row >> 10;
    const float* xr = x + (size_t)row * Hdim;
    int tid = threadIdx.x;
    int col4 = tid * 4;
    float4 t = *(const float4*)(xr + col4);
    float s  = t.x + t.y + t.z + t.w;
    float sq = t.x * t.x + t.y * t.y + t.z * t.z + t.w * t.w;
    #pragma unroll
    for (int o = 16; o > 0; o >>= 1) {
        s  += __shfl_down_sync(0xffffffffu, s,  o);
        sq += __shfl_down_sync(0xffffffffu, sq, o);
    }
    __shared__ float red[20];
    int warp = tid >> 5, lane = tid & 31;
    if (lane == 0) { red[warp] = s; red[warp + 8] = sq; }
    __syncthreads();
    if (tid == 0) {
        float S = 0.0f, SQ = 0.0f;
        #pragma unroll
        for (int w = 0; w < 8; w++) { S += red[w]; SQ += red[w + 8]; }
        float mu = S * (1.0f / Hdim);
        float var = SQ * (1.0f / Hdim) - mu * mu;
        red[16] = mu;
        red[17] = rsqrtf(var + 1e-5f);
    }
    __syncthreads();
    float mu = red[16], inv = red[17];
    const float* sh = cm + b * CM_STRIDE + shiftOff;
    const float* sc = cm + b * CM_STRIDE + scaleOff;
    float4 shv = *(const float4*)(sh + col4);
    float4 scv = *(const float4*)(sc + col4);
    float v0 = (t.x - mu) * inv * (1.0f + scv.x) + shv.x;
    float v1 = (t.y - mu) * inv * (1.0f + scv.y) + shv.y;
    float v2 = (t.z - mu) * inv * (1.0f + scv.z) + shv.z;
    float v3 = (t.w - mu) * inv * (1.0f + scv.w) + shv.w;
    uint2 o2 = make_uint2(f2h2(v0, v1), f2h2(v2, v3));
    *(uint2*)&out[(size_t)row * Hdim + col4] = o2;
}

// ------------------------- fp16 GEMM: 128x256, cp.async + ldmatrix ----------
// A smem: [row][k], stride 20 half2-words (80B/row, 32 halves data + pad)
// B smem: [k][n],  stride 132 words (528B/row, 256 halves data + pad)
#define AS2 20
#define BW 132
#define STAGE_U32 (128 * AS2 + 32 * BW)   // 2560 + 4224 = 6784
#define GSMEM2 (3 * STAGE_U32 * 4)        // 81408 bytes

template<int EPI>
__global__ __launch_bounds__(256, 1)
void gemm_h(const __half* __restrict__ A, const __half* __restrict__ Bh,
            const float* __restrict__ bias, void* __restrict__ Cout,
            int M, int N, int K,
            const float* __restrict__ gate, const float* __restrict__ resid)
{
    extern __shared__ unsigned sm[];
    int tid = threadIdx.x;
    int warp = tid >> 5, lane = tid & 31;
    int warpM = warp >> 2, warpN = warp & 3;   // 2x4 warp grid, 64x64 warp tile
    int g = lane >> 2, r = lane & 3;
    int rowBase = blockIdx.y * 128, colBase = blockIdx.x * 256;
    int kts = K / 32;

    uint32_t smBase = smem_u32(sm);

    auto loadStage = [&](int stage, int kt) {
        uint32_t sA = smBase + stage * STAGE_U32 * 4;
        uint32_t sB = sA + 128 * AS2 * 4;
        const __half* Ag = A + (size_t)rowBase * K + kt * 32;
        const __half* Bg = Bh + (size_t)(kt * 32) * N + colBase;
        // A: 128 rows x 64B (4 x 16B each), 512 cp.async
        #pragma unroll
        for (int i = 0; i < 2; i++) {
            int j = tid + i * 256;
            int row = j >> 2, seg = j & 3;
            CP_ASYNC16(sA + row * 80 + seg * 16, Ag + (size_t)row * K + seg * 8);
        }
        // B: 32 rows x 512B (32 x 16B each), 1024 cp.async
        #pragma unroll
        for (int i = 0; i < 4; i++) {
            int j = tid + i * 256;
            int row = j >> 5, seg = j & 31;
            CP_ASYNC16(sB + row * 528 + seg * 16, Bg + (size_t)row * N + seg * 8);
        }
    };

    float acc[4][8][4] = {};

    loadStage(0, 0); CP_COMMIT();
    loadStage(1, 1); CP_COMMIT();

    int lrow = lane & 15, lhi = lane >> 4;

    for (int kt = 0; kt < kts; kt++) {
        CP_WAIT1();
        __syncthreads();
        if (kt + 2 < kts) loadStage((kt + 2) % 3, kt + 2);
        CP_COMMIT();

        uint32_t sA = smBase + (kt % 3) * STAGE_U32 * 4;
        uint32_t sB = sA + 128 * AS2 * 4;
        #pragma unroll
        for (int ks = 0; ks < 2; ks++) {
            unsigned af[4][4], bf[8][2];
            #pragma unroll
            for (int mi = 0; mi < 4; mi++) {
                uint32_t a = sA + ((warpM * 64 + mi * 16 + lrow) * AS2
                                   + ks * 8 + lhi * 4) * 4;
                LDSM4(af[mi][0], af[mi][1], af[mi][2], af[mi][3], a);
            }
            #pragma unroll
            for (int p = 0; p < 4; p++) {
                uint32_t bAddr = sB + ((ks * 16 + lrow) * BW
                                       + warpN * 32 + p * 8 + lhi * 4) * 4;
                LDSM4T(bf[2 * p][0], bf[2 * p][1], bf[2 * p + 1][0], bf[2 * p + 1][1], bAddr);
            }
            #pragma unroll
            for (int mi = 0; mi < 4; mi++)
                #pragma unroll
                for (int nj = 0; nj < 8; nj++)
                    mma_f16(acc[mi][nj], af[mi], bf[nj]);
        }
    }

    // epilogue
    #pragma unroll
    for (int mi = 0; mi < 4; mi++) {
        #pragma unroll
        for (int rr = 0; rr < 2; rr++) {
            int row = rowBase + warpM * 64 + mi * 16 + g + rr * 8;
            int b = row >> 10;
            #pragma unroll
            for (int nj = 0; nj < 8; nj++) {
                int col = colBase + warpN * 64 + nj * 8 + r * 2;
                float v0 = acc[mi][nj][rr * 2 + 0] + __ldg(&bias[col]);
                float v1 = acc[mi][nj][rr * 2 + 1] + __ldg(&bias[col + 1]);
                if (EPI == 0) {
                    float sc = (col < Hdim) ? 0.125f : 1.0f;
                    __half* Ch = (__half*)Cout;
                    *(unsigned*)&Ch[(size_t)row * N + col] = f2h2(v0 * sc, v1 * sc);
                } else if (EPI == 1) {
                    v0 = 0.5f * v0 * (1.0f + erff(v0 * 0.70710678118654752f));
                    v1 = 0.5f * v1 * (1.0f + erff(v1 * 0.70710678118654752f));
                    __half* Ch = (__half*)Cout;
                    *(unsigned*)&Ch[(size_t)row * N + col] = f2h2(v0, v1);
                } else if (EPI == 2) {
                    v0 *= (1.0f + __ldg(&gate[b * CM_STRIDE + col]));
                    v1 *= (1.0f + __ldg(&gate[b * CM_STRIDE + col + 1]));
                    *(float2*)&((float*)Cout)[(size_t)row * N + col] = make_float2(v0, v1);
                } else {
                    v0 = resid[(size_t)row * N + col]     + __ldg(&gate[b * CM_STRIDE + col])     * v0;
                    v1 = resid[(size_t)row * N + col + 1] + __ldg(&gate[b * CM_STRIDE + col + 1]) * v1;
                    *(float2*)&((float*)Cout)[(size_t)row * N + col] = make_float2(v0, v1);
                }
            }
        }
    }
}

// ------------------------- flash attention (double-buffered K/V) ------------
#define PSTR2 36
#define KSTR2 36
#define VSTR2 72
#define FPS_U32 (128 * PSTR2)
#define FKB_U32 (64 * KSTR2)
#define FVB_U32 (32 * VSTR2)
#define FSMEM ((FPS_U32 + 2 * FKB_U32 + 2 * FVB_U32) * 4)   // 55296 bytes

__global__ __launch_bounds__(256)
void flash_attn(const __half* __restrict__ qkv, __half* __restrict__ out)
{
    extern __shared__ unsigned fsm[];
    unsigned* Ps2 = fsm;
    unsigned* KsB = fsm + FPS_U32;
    unsigned* VsB = fsm + FPS_U32 + 2 * FKB_U32;

    int tid = threadIdx.x;
    int warp = tid >> 5, lane = tid & 31;
    int g = lane >> 2, r = lane & 3;
    int bh = blockIdx.y;
    int b = bh >> 4, h = bh & 15;
    int q0 = blockIdx.x * 128;

    #pragma unroll
    for (int i = 0; i < 4; i++) {
        int j = tid + i * 256;
        int row = j >> 3, d8 = (j & 7) * 8;
        uint4 v = *(const uint4*)(qkv + (size_t)(b * Ntok + q0 + row) * 3 * Hdim
                                  + h * HD + d8);
        *(uint4*)&Ps2[row * PSTR2 + (j & 7) * 4] = v;
    }

    {
        unsigned* Ks2 = KsB;
        unsigned* Vs2 = VsB;
        #pragma unroll
        for (int i = 0; i < 2; i++) {
            int j = tid + i * 256;
            int key = j >> 3, d8 = (j & 7) * 8;
            uint4 v = *(const uint4*)(qkv + (size_t)(b * Ntok + key) * 3 * Hdim
                                      + Hdim + h * HD + d8);
            *(uint4*)&Ks2[key * KSTR2 + (j & 7) * 4] = v;
        }
        int k2 = tid >> 3, d8 = (tid & 7) * 8;
        const __half* vp = qkv + (size_t)(b * Ntok + 2 * k2) * 3 * Hdim
                           + 2 * Hdim + h * HD + d8;
        uint4 a = *(const uint4*)vp;
        uint4 c = *(const uint4*)(vp + 3 * Hdim);
        unsigned* q = &Vs2[k2 * VSTR2 + d8];
        q[0] = __byte_perm(a.x, c.x, 0x5410); q[1] = __byte_perm(a.x, c.x, 0x7632);
        q[2] = __byte_perm(a.y, c.y, 0x5410); q[3] = __byte_perm(a.y, c.y, 0x7632);
        q[4] = __byte_perm(a.z, c.z, 0x5410); q[5] = __byte_perm(a.z, c.z, 0x7632);
        q[6] = __byte_perm(a.w, c.w, 0x5410); q[7] = __byte_perm(a.w, c.w, 0x7632);
    }
    __syncthreads();

    int qrow = warp * 16 + g;
    unsigned qf[4][4];
    #pragma unroll
    for (int ks = 0; ks < 4; ks++) {
        qf[ks][0] = Ps2[qrow * PSTR2 + ks * 8 + r];
        qf[ks][1] = Ps2[(qrow + 8) * PSTR2 + ks * 8 + r];
        qf[ks][2] = Ps2[qrow * PSTR2 + ks * 8 + r + 4];
        qf[ks][3] = Ps2[(qrow + 8) * PSTR2 + ks * 8 + r + 4];
    }
    __syncwarp();

    float oacc[8][4] = {};
    float m0 = -1e30f, m1 = -1e30f, l0 = 0.0f, l1 = 0.0f;

    const int NIT = Ntok / 64;
    for (int it = 0; it < NIT; it++) {
        int cur = it & 1, nxt = cur ^ 1;
        unsigned* Ks2 = KsB + cur * FKB_U32;
        unsigned* Vs2 = VsB + cur * FVB_U32;

        uint4 pk0, pk1, pva, pvc;
        int pk2 = tid >> 3, pd8 = (tid & 7) * 8;
        if (it + 1 < NIT) {
            int n1 = (it + 1) * 64;
            {
                int j = tid;
                int key = j >> 3, d8 = (j & 7) * 8;
                pk0 = *(const uint4*)(qkv + (size_t)(b * Ntok + n1 + key) * 3 * Hdim
                                      + Hdim + h * HD + d8);
                j = tid + 256;
                key = j >> 3; d8 = (j & 7) * 8;
                pk1 = *(const uint4*)(qkv + (size_t)(b * Ntok + n1 + key) * 3 * Hdim
                                      + Hdim + h * HD + d8);
            }
            const __half* vp = qkv + (size_t)(b * Ntok + n1 + 2 * pk2) * 3 * Hdim
                               + 2 * Hdim + h * HD + pd8;
            pva = *(const uint4*)vp;
            pvc = *(const uint4*)(vp + 3 * Hdim);
        }

        float sacc[8][4] = {};
        #pragma unroll
        for (int ks = 0; ks < 4; ks++) {
            #pragma unroll
            for (int nj = 0; nj < 8; nj++) {
                int key = nj * 8 + g;
                unsigned bf[2];
                bf[0] = Ks2[key * KSTR2 + ks * 8 + r];
                bf[1] = Ks2[key * KSTR2 + ks * 8 + r + 4];
                mma_f16(sacc[nj], qf[ks], bf);
            }
        }

        float mc0 = -1e30f, mc1 = -1e30f;
        #pragma unroll
        for (int nj = 0; nj < 8; nj++) {
            mc0 = fmaxf(mc0, fmaxf(sacc[nj][0], sacc[nj][1]));
            mc1 = fmaxf(mc1, fmaxf(sacc[nj][2], sacc[nj][3]));
        }
        mc0 = fmaxf(mc0, __shfl_xor_sync(0xffffffffu, mc0, 1));
        mc0 = fmaxf(mc0, __shfl_xor_sync(0xffffffffu, mc0, 2));
        mc1 = fmaxf(mc1, __shfl_xor_sync(0xffffffffu, mc1, 1));
        mc1 = fmaxf(mc1, __shfl_xor_sync(0xffffffffu, mc1, 2));
        float mn0 = fmaxf(m0, mc0), mn1 = fmaxf(m1, mc1);
        float a0 = __expf(m0 - mn0), a1 = __expf(m1 - mn1);
        float rs0 = 0.0f, rs1 = 0.0f;
        #pragma unroll
        for (int nj = 0; nj < 8; nj++) {
            float p0 = __expf(sacc[nj][0] - mn0);
            float p1 = __expf(sacc[nj][1] - mn0);
            float p2 = __expf(sacc[nj][2] - mn1);
            float p3 = __expf(sacc[nj][3] - mn1);
            rs0 += p0 + p1; rs1 += p2 + p3;
            Ps2[qrow * PSTR2 + nj * 4 + r]       = f2h2(p0, p1);
            Ps2[(qrow + 8) * PSTR2 + nj * 4 + r] = f2h2(p2, p3);
        }
        rs0 += __shfl_xor_sync(0xffffffffu, rs0, 1);
        rs0 += __shfl_xor_sync(0xffffffffu, rs0, 2);
        rs1 += __shfl_xor_sync(0xffffffffu, rs1, 1);
        rs1 += __shfl_xor_sync(0xffffffffu, rs1, 2);
        l0 = l0 * a0 + rs0;
        l1 = l1 * a1 + rs1;
        m0 = mn0; m1 = mn1;
        #pragma unroll
        for (int nj = 0; nj < 8; nj++) {
            oacc[nj][0] *= a0; oacc[nj][1] *= a0;
            oacc[nj][2] *= a1; oacc[nj][3] *= a1;
        }
        __syncwarp();

        #pragma unroll
        for (int ks = 0; ks < 4; ks++) {
            unsigned af[4];
            af[0] = Ps2[qrow * PSTR2 + ks * 8 + r];
            af[1] = Ps2[(qrow + 8) * PSTR2 + ks * 8 + r];
            af[2] = Ps2[qrow * PSTR2 + ks * 8 + r + 4];
            af[3] = Ps2[(qrow + 8) * PSTR2 + ks * 8 + r + 4];
            #pragma unroll
            for (int nj = 0; nj < 8; nj++) {
                unsigned bf[2];
                bf[0] = Vs2[(ks * 8 + r) * VSTR2 + nj * 8 + g];
                bf[1] = Vs2[(ks * 8 + r + 4) * VSTR2 + nj * 8 + g];
                mma_f16(oacc[nj], af, bf);
            }
        }

        if (it + 1 < NIT) {
            unsigned* Kn = KsB + nxt * FKB_U32;
            unsigned* Vn = VsB + nxt * FVB_U32;
            {
                int j = tid;
                int key = j >> 3;
                *(uint4*)&Kn[key * KSTR2 + (j & 7) * 4] = pk0;
                j = tid + 256;
                key = j >> 3;
                *(uint4*)&Kn[key * KSTR2 + (j & 7) * 4] = pk1;
            }
            unsigned* q = &Vn[pk2 * VSTR2 + pd8];
            q[0] = __byte_perm(pva.x, pvc.x, 0x5410); q[1] = __byte_perm(pva.x, pvc.x, 0x7632);
            q[2] = __byte_perm(pva.y, pvc.y, 0x5410); q[3] = __byte_perm(pva.y, pvc.y, 0x7632);
            q[4] = __byte_perm(pva.z, pvc.z, 0x5410); q[5] = __byte_perm(pva.z, pvc.z, 0x7632);
            q[6] = __byte_perm(pva.w, pvc.w, 0x5410); q[7] = __byte_perm(pva.w, pvc.w, 0x7632);
        }
        __syncthreads();
    }

    float i0 = 1.0f / l0, i1 = 1.0f / l1;
    #pragma unroll
    for (int nj = 0; nj < 8; nj++) {
        int col = h * HD + nj * 8 + 2 * r;
        *(unsigned*)&out[(size_t)(b * Ntok + q0 + qrow) * Hdim + col]
            = f2h2(oacc[nj][0] * i0, oacc[nj][1] * i0);
        *(unsigned*)&out[(size_t)(b * Ntok + q0 + qrow + 8) * Hdim + col]
            = f2h2(oacc[nj][2] * i1, oacc[nj][3] * i1);
    }
}

// ------------------------- launch ------------------------------------------
extern "C" void kernel_launch(void* const* d_in, const int* in_sizes, int n_in,
                              void* d_out, int out_size)
{
    const float* x      = (const float*)d_in[0];
    const float* c      = (const float*)d_in[1];
    const float* w_mod  = (const float*)d_in[2];
    const float* b_mod  = (const float*)d_in[3];
    const float* w_qkv  = (const float*)d_in[4];
    const float* b_qkv  = (const float*)d_in[5];
    const float* w_proj = (const float*)d_in[6];
    const float* b_proj = (const float*)d_in[7];
    const float* w1     = (const float*)d_in[8];
    const float* b1     = (const float*)d_in[9];
    const float* w2     = (const float*)d_in[10];
    const float* b2     = (const float*)d_in[11];
    float* out = (float*)d_out;

    float *cm, *cpart, *x2;
    __half *xmh, *qkvh, *attnh, *xm2h, *hidh, *wqkvH, *w1H, *w2H, *wpH;
    cudaGetSymbolAddress((void**)&cm,    g_cm);
    cudaGetSymbolAddress((void**)&cpart, g_cpart);
    cudaGetSymbolAddress((void**)&xmh,   g_xmh);
    cudaGetSymbolAddress((void**)&qkvh,  g_qkvh);
    cudaGetSymbolAddress((void**)&attnh, g_attnh);
    cudaGetSymbolAddress((void**)&x2,    g_x2);
    cudaGetSymbolAddress((void**)&xm2h,  g_xm2h);
    cudaGetSymbolAddress((void**)&hidh,  g_hidh);
    cudaGetSymbolAddress((void**)&wqkvH, g_wqkvH);
    cudaGetSymbolAddress((void**)&w1H,   g_w1H);
    cudaGetSymbolAddress((void**)&w2H,   g_w2H);
    cudaGetSymbolAddress((void**)&wpH,   g_wpH);

    cudaFuncSetAttribute(gemm_h<0>, cudaFuncAttributeMaxDynamicSharedMemorySize, GSMEM2);
    cudaFuncSetAttribute(gemm_h<1>, cudaFuncAttributeMaxDynamicSharedMemorySize, GSMEM2);
    cudaFuncSetAttribute(gemm_h<2>, cudaFuncAttributeMaxDynamicSharedMemorySize, GSMEM2);
    cudaFuncSetAttribute(gemm_h<3>, cudaFuncAttributeMaxDynamicSharedMemorySize, GSMEM2);
    cudaFuncSetAttribute(flash_attn, cudaFuncAttributeMaxDynamicSharedMemorySize, FSMEM);

    // 0. weight conversions (plain half [K][N], vectorized)
    whalf_kernel<<<(3 * Hdim * Hdim) / 1024, 256>>>(w_qkv, wqkvH);
    whalf_kernel<<<(Hdim * (size_t)DFF) / 1024, 256>>>(w1, w1H);
    whalf_kernel<<<((size_t)DFF * Hdim) / 1024, 256>>>(w2, w2H);
    whalf_kernel<<<(Hdim * Hdim) / 1024, 256>>>(w_proj, wpH);

    // 1. conditioning -> modulation params (split-K)
    cond_part_kernel<<<dim3(24, 4, 8), 256>>>(c, w_mod, cpart);
    cond_reduce_kernel<<<dim3(24, 4), 256>>>(cpart, b_mod, cm);

    // 2. LN + modulate (msa) -> half
    ln_mod_h_kernel<<<ROWS, 256>>>(x, cm, 0, Hdim, xmh);

    // 3. qkv (half out, Q pre-scaled by 1/8)
    gemm_h<0><<<dim3(3 * Hdim / 256, ROWS / 128), 256, GSMEM2>>>(
        xmh, wqkvH, b_qkv, qkvh, ROWS, 3 * Hdim, Hdim, nullptr, nullptr);

    // 4. flash attention -> half attnout
    flash_attn<<<dim3(Ntok / 128, Bsz * NH), 256, FSMEM>>>(qkvh, attnh);

    // 5. x2 = (attnout @ w_proj + b_proj) * (1 + gate_msa)   (float out)
    gemm_h<2><<<dim3(Hdim / 256, ROWS / 128), 256, GSMEM2>>>(
        attnh, wpH, b_proj, x2, ROWS, Hdim, Hdim, cm + 2 * Hdim, nullptr);

    // 6. LN + modulate (mlp) -> half
    ln_mod_h_kernel<<<ROWS, 256>>>(x2, cm, 3 * Hdim, 4 * Hdim, xm2h);

    // 7. hid = gelu(xm2 @ w1 + b1)  (half out)
    gemm_h<1><<<dim3(DFF / 256, ROWS / 128), 256, GSMEM2>>>(
        xm2h, w1H, b1, hidh, ROWS, DFF, Hdim, nullptr, nullptr);

    // 8. out = x2 + gate_mlp * (hid @ w2 + b2)  (float out)
    gemm_h<3><<<dim3(Hdim / 256, ROWS / 128), 256, GSMEM2>>>(
        hidh, w2H, b2, out, ROWS, Hdim, DFF, cm + 5 * Hdim, x2);
}

// round 12
// speedup vs baseline: 7.3121x; 1.1166x over previous
#include <cuda_runtime.h>
#include <cuda_fp16.h>
#include <cstdint>
#include <math.h>

// ---------------------------------------------------------------------------
// DiT block: fp16 mma.sync GEMMs (128x128, cp.async 3-stage, ldmatrix,
// 2 CTAs/SM) + double-buffered flash attention + split-K cond modulation.
// B=4, N=1024, H=1024, heads=16, d=64, D_FF=4096
// ---------------------------------------------------------------------------

#define Bsz 4
#define Ntok 1024
#define Hdim 1024
#define NH 16
#define HD 64
#define DFF 4096
#define ROWS (Bsz * Ntok)      // 4096
#define CM_STRIDE (6 * Hdim)   // 6144

// ------------------------- scratch (device globals) ------------------------
__device__ float    g_cm[Bsz * CM_STRIDE];
__device__ float    g_cpart[Bsz * 8 * CM_STRIDE];
__device__ __half   g_xmh[ROWS * Hdim];
__device__ __half   g_qkvh[ROWS * 3 * Hdim];
__device__ __half   g_attnh[ROWS * Hdim];
__device__ float    g_x2[ROWS * Hdim];
__device__ __half   g_xm2h[ROWS * Hdim];
__device__ __half   g_hidh[ROWS * DFF];
// plain half weights [K][N]
__device__ __half   g_wqkvH[Hdim * 3 * Hdim];
__device__ __half   g_w1H[Hdim * DFF];
__device__ __half   g_w2H[DFF * Hdim];
__device__ __half   g_wpH[Hdim * Hdim];

// ------------------------- helpers -----------------------------------------
__device__ __forceinline__ unsigned f2h2(float a, float b) {
    __half2 h = __floats2half2_rn(a, b);
    return *(unsigned*)&h;
}

__device__ __forceinline__ uint32_t smem_u32(const void* p) {
    uint32_t a;
    asm("{ .reg .u64 t; cvta.to.shared.u64 t, %1; cvt.u32.u64 %0, t; }"
        : "=r"(a) : "l"(p));
    return a;
}

__device__ __forceinline__ void mma_f16(float* d, const unsigned* a, const unsigned* b) {
    asm volatile(
        "mma.sync.aligned.m16n8k16.row.col.f32.f16.f16.f32 "
        "{%0,%1,%2,%3},{%4,%5,%6,%7},{%8,%9},{%0,%1,%2,%3};\n"
        : "+f"(d[0]), "+f"(d[1]), "+f"(d[2]), "+f"(d[3])
        : "r"(a[0]), "r"(a[1]), "r"(a[2]), "r"(a[3]), "r"(b[0]), "r"(b[1]));
}

#define LDSM4(r0, r1, r2, r3, a) \
    asm volatile("ldmatrix.sync.aligned.m8n8.x4.shared.b16 {%0,%1,%2,%3}, [%4];" \
                 : "=r"(r0), "=r"(r1), "=r"(r2), "=r"(r3) : "r"(a))
#define LDSM4T(r0, r1, r2, r3, a) \
    asm volatile("ldmatrix.sync.aligned.m8n8.x4.trans.shared.b16 {%0,%1,%2,%3}, [%4];" \
                 : "=r"(r0), "=r"(r1), "=r"(r2), "=r"(r3) : "r"(a))

#define CP_ASYNC16(saddr, gptr) \
    asm volatile("cp.async.cg.shared.global [%0], [%1], 16;" \
                 :: "r"(saddr), "l"(gptr) : "memory")
#define CP_COMMIT() asm volatile("cp.async.commit_group;" ::: "memory")
#define CP_WAIT1()  asm volatile("cp.async.wait_group 1;" ::: "memory")

// ------------------------- weight -> half (vectorized) ----------------------
__global__ void whalf_kernel(const float* __restrict__ w, __half* __restrict__ o)
{
    size_t i = (size_t)blockIdx.x * 256 + threadIdx.x;
    float4 v = *(const float4*)(w + i * 4);
    uint2 h = make_uint2(f2h2(v.x, v.y), f2h2(v.z, v.w));
    *(uint2*)(o + i * 4) = h;
}

// ------------------------- cond modulation (split-K) ------------------------
__global__ void cond_part_kernel(const float* __restrict__ c,
                                 const float* __restrict__ w,
                                 float* __restrict__ part)
{
    int j = blockIdx.x * 256 + threadIdx.x;
    int b = blockIdx.y, kc = blockIdx.z;
    __shared__ float sc[128];
    if (threadIdx.x < 128) {
        float t = c[b * Hdim + kc * 128 + threadIdx.x];
        sc[threadIdx.x] = t / (1.0f + expf(-t));
    }
    __syncthreads();
    float acc = 0.0f;
    const float* wp = w + (size_t)(kc * 128) * CM_STRIDE + j;
    #pragma unroll 8
    for (int k = 0; k < 128; k++)
        acc += sc[k] * wp[(size_t)k * CM_STRIDE];
    part[(size_t)(b * 8 + kc) * CM_STRIDE + j] = acc;
}

__global__ void cond_reduce_kernel(const float* __restrict__ part,
                                   const float* __restrict__ bmod,
                                   float* __restrict__ cm)
{
    int j = blockIdx.x * 256 + threadIdx.x;
    int b = blockIdx.y;
    float acc = bmod[j];
    #pragma unroll
    for (int s = 0; s < 8; s++)
        acc += part[(size_t)(b * 8 + s) * CM_STRIDE + j];
    cm[b * CM_STRIDE + j] = acc;
}

// ------------------------- LayerNorm + modulate -> half ---------------------
__global__ void ln_mod_h_kernel(const float* __restrict__ x,
                                const float* __restrict__ cm,
                                int shiftOff, int scaleOff,
                                __half* __restrict__ out)
{
    int row = blockIdx.x;
    int b = row >> 10;
    const float* xr = x + (size_t)row * Hdim;
    int tid = threadIdx.x;
    int col4 = tid * 4;
    float4 t = *(const float4*)(xr + col4);
    float s  = t.x + t.y + t.z + t.w;
    float sq = t.x * t.x + t.y * t.y + t.z * t.z + t.w * t.w;
    #pragma unroll
    for (int o = 16; o > 0; o >>= 1) {
        s  += __shfl_down_sync(0xffffffffu, s,  o);
        sq += __shfl_down_sync(0xffffffffu, sq, o);
    }
    __shared__ float red[20];
    int warp = tid >> 5, lane = tid & 31;
    if (lane == 0) { red[warp] = s; red[warp + 8] = sq; }
    __syncthreads();
    if (tid == 0) {
        float S = 0.0f, SQ = 0.0f;
        #pragma unroll
        for (int w = 0; w < 8; w++) { S += red[w]; SQ += red[w + 8]; }
        float mu = S * (1.0f / Hdim);
        float var = SQ * (1.0f / Hdim) - mu * mu;
        red[16] = mu;
        red[17] = rsqrtf(var + 1e-5f);
    }
    __syncthreads();
    float mu = red[16], inv = red[17];
    const float* sh = cm + b * CM_STRIDE + shiftOff;
    const float* sc = cm + b * CM_STRIDE + scaleOff;
    float4 shv = *(const float4*)(sh + col4);
    float4 scv = *(const float4*)(sc + col4);
    float v0 = (t.x - mu) * inv * (1.0f + scv.x) + shv.x;
    float v1 = (t.y - mu) * inv * (1.0f + scv.y) + shv.y;
    float v2 = (t.z - mu) * inv * (1.0f + scv.z) + shv.z;
    float v3 = (t.w - mu) * inv * (1.0f + scv.w) + shv.w;
    uint2 o2 = make_uint2(f2h2(v0, v1), f2h2(v2, v3));
    *(uint2*)&out[(size_t)row * Hdim + col4] = o2;
}

// ------------------------- fp16 GEMM: 128x128, 3-stage, 2 CTAs/SM -----------
// A smem: [row][k], 80B/row (64B data + 16B pad), stride 20 words
// B smem: [k][n],  272B/row (256B data + 16B pad), stride 68 words
#define AS2 20
#define BW 68
#define STAGE_U32 (128 * AS2 + 32 * BW)   // 2560 + 2176 = 4736
#define GSMEM2 (3 * STAGE_U32 * 4)        // 56832 bytes

template<int EPI>
__global__ __launch_bounds__(256, 2)
void gemm_h(const __half* __restrict__ A, const __half* __restrict__ Bh,
            const float* __restrict__ bias, void* __restrict__ Cout,
            int M, int N, int K,
            const float* __restrict__ gate, const float* __restrict__ resid)
{
    extern __shared__ unsigned sm[];
    int tid = threadIdx.x;
    int warp = tid >> 5, lane = tid & 31;
    int warpM = warp >> 2, warpN = warp & 3;   // 2x4 warp grid, 64x32 warp tile
    int g = lane >> 2, r = lane & 3;
    int rowBase = blockIdx.y * 128, colBase = blockIdx.x * 128;
    int kts = K / 32;

    uint32_t smBase = smem_u32(sm);

    auto loadStage = [&](int stage, int kt) {
        uint32_t sA = smBase + stage * STAGE_U32 * 4;
        uint32_t sB = sA + 128 * AS2 * 4;
        const __half* Ag = A + (size_t)rowBase * K + kt * 32;
        const __half* Bg = Bh + (size_t)(kt * 32) * N + colBase;
        // A: 128 rows x 64B (4 x 16B), 512 cp.async
        #pragma unroll
        for (int i = 0; i < 2; i++) {
            int j = tid + i * 256;
            int row = j >> 2, seg = j & 3;
            CP_ASYNC16(sA + row * 80 + seg * 16, Ag + (size_t)row * K + seg * 8);
        }
        // B: 32 rows x 256B (16 x 16B), 512 cp.async
        #pragma unroll
        for (int i = 0; i < 2; i++) {
            int j = tid + i * 256;
            int row = j >> 4, seg = j & 15;
            CP_ASYNC16(sB + row * 272 + seg * 16, Bg + (size_t)row * N + seg * 8);
        }
    };

    float acc[4][4][4] = {};

    loadStage(0, 0); CP_COMMIT();
    loadStage(1, 1); CP_COMMIT();

    int lrow = lane & 15, lhi = lane >> 4;

    for (int kt = 0; kt < kts; kt++) {
        CP_WAIT1();
        __syncthreads();
        if (kt + 2 < kts) loadStage((kt + 2) % 3, kt + 2);
        CP_COMMIT();

        uint32_t sA = smBase + (kt % 3) * STAGE_U32 * 4;
        uint32_t sB = sA + 128 * AS2 * 4;
        #pragma unroll
        for (int ks = 0; ks < 2; ks++) {
            unsigned af[4][4], bf[4][2];
            #pragma unroll
            for (int mi = 0; mi < 4; mi++) {
                uint32_t a = sA + ((warpM * 64 + mi * 16 + lrow) * AS2
                                   + ks * 8 + lhi * 4) * 4;
                LDSM4(af[mi][0], af[mi][1], af[mi][2], af[mi][3], a);
            }
            #pragma unroll
            for (int p = 0; p < 2; p++) {
                uint32_t bAddr = sB + ((ks * 16 + lrow) * BW
                                       + warpN * 16 + p * 8 + lhi * 4) * 4;
                LDSM4T(bf[2 * p][0], bf[2 * p][1], bf[2 * p + 1][0], bf[2 * p + 1][1], bAddr);
            }
            #pragma unroll
            for (int mi = 0; mi < 4; mi++)
                #pragma unroll
                for (int nj = 0; nj < 4; nj++)
                    mma_f16(acc[mi][nj], af[mi], bf[nj]);
        }
    }

    // epilogue
    #pragma unroll
    for (int mi = 0; mi < 4; mi++) {
        #pragma unroll
        for (int rr = 0; rr < 2; rr++) {
            int row = rowBase + warpM * 64 + mi * 16 + g + rr * 8;
            int b = row >> 10;
            #pragma unroll
            for (int nj = 0; nj < 4; nj++) {
                int col = colBase + warpN * 32 + nj * 8 + r * 2;
                float v0 = acc[mi][nj][rr * 2 + 0] + __ldg(&bias[col]);
                float v1 = acc[mi][nj][rr * 2 + 1] + __ldg(&bias[col + 1]);
                if (EPI == 0) {
                    float sc = (col < Hdim) ? 0.125f : 1.0f;
                    __half* Ch = (__half*)Cout;
                    *(unsigned*)&Ch[(size_t)row * N + col] = f2h2(v0 * sc, v1 * sc);
                } else if (EPI == 1) {
                    v0 = 0.5f * v0 * (1.0f + erff(v0 * 0.70710678118654752f));
                    v1 = 0.5f * v1 * (1.0f + erff(v1 * 0.70710678118654752f));
                    __half* Ch = (__half*)Cout;
                    *(unsigned*)&Ch[(size_t)row * N + col] = f2h2(v0, v1);
                } else if (EPI == 2) {
                    v0 *= (1.0f + __ldg(&gate[b * CM_STRIDE + col]));
                    v1 *= (1.0f + __ldg(&gate[b * CM_STRIDE + col + 1]));
                    *(float2*)&((float*)Cout)[(size_t)row * N + col] = make_float2(v0, v1);
                } else {
                    v0 = resid[(size_t)row * N + col]     + __ldg(&gate[b * CM_STRIDE + col])     * v0;
                    v1 = resid[(size_t)row * N + col + 1] + __ldg(&gate[b * CM_STRIDE + col + 1]) * v1;
                    *(float2*)&((float*)Cout)[(size_t)row * N + col] = make_float2(v0, v1);
                }
            }
        }
    }
}

// ------------------------- flash attention (double-buffered K/V) ------------
#define PSTR2 36
#define KSTR2 36
#define VSTR2 72
#define FPS_U32 (128 * PSTR2)
#define FKB_U32 (64 * KSTR2)
#define FVB_U32 (32 * VSTR2)
#define FSMEM ((FPS_U32 + 2 * FKB_U32 + 2 * FVB_U32) * 4)   // 55296 bytes

__global__ __launch_bounds__(256)
void flash_attn(const __half* __restrict__ qkv, __half* __restrict__ out)
{
    extern __shared__ unsigned fsm[];
    unsigned* Ps2 = fsm;
    unsigned* KsB = fsm + FPS_U32;
    unsigned* VsB = fsm + FPS_U32 + 2 * FKB_U32;

    int tid = threadIdx.x;
    int warp = tid >> 5, lane = tid & 31;
    int g = lane >> 2, r = lane & 3;
    int bh = blockIdx.y;
    int b = bh >> 4, h = bh & 15;
    int q0 = blockIdx.x * 128;

    #pragma unroll
    for (int i = 0; i < 4; i++) {
        int j = tid + i * 256;
        int row = j >> 3, d8 = (j & 7) * 8;
        uint4 v = *(const uint4*)(qkv + (size_t)(b * Ntok + q0 + row) * 3 * Hdim
                                  + h * HD + d8);
        *(uint4*)&Ps2[row * PSTR2 + (j & 7) * 4] = v;
    }

    {
        unsigned* Ks2 = KsB;
        unsigned* Vs2 = VsB;
        #pragma unroll
        for (int i = 0; i < 2; i++) {
            int j = tid + i * 256;
            int key = j >> 3, d8 = (j & 7) * 8;
            uint4 v = *(const uint4*)(qkv + (size_t)(b * Ntok + key) * 3 * Hdim
                                      + Hdim + h * HD + d8);
            *(uint4*)&Ks2[key * KSTR2 + (j & 7) * 4] = v;
        }
        int k2 = tid >> 3, d8 = (tid & 7) * 8;
        const __half* vp = qkv + (size_t)(b * Ntok + 2 * k2) * 3 * Hdim
                           + 2 * Hdim + h * HD + d8;
        uint4 a = *(const uint4*)vp;
        uint4 c = *(const uint4*)(vp + 3 * Hdim);
        unsigned* q = &Vs2[k2 * VSTR2 + d8];
        q[0] = __byte_perm(a.x, c.x, 0x5410); q[1] = __byte_perm(a.x, c.x, 0x7632);
        q[2] = __byte_perm(a.y, c.y, 0x5410); q[3] = __byte_perm(a.y, c.y, 0x7632);
        q[4] = __byte_perm(a.z, c.z, 0x5410); q[5] = __byte_perm(a.z, c.z, 0x7632);
        q[6] = __byte_perm(a.w, c.w, 0x5410); q[7] = __byte_perm(a.w, c.w, 0x7632);
    }
    __syncthreads();

    int qrow = warp * 16 + g;
    unsigned qf[4][4];
    #pragma unroll
    for (int ks = 0; ks < 4; ks++) {
        qf[ks][0] = Ps2[qrow * PSTR2 + ks * 8 + r];
        qf[ks][1] = Ps2[(qrow + 8) * PSTR2 + ks * 8 + r];
        qf[ks][2] = Ps2[qrow * PSTR2 + ks * 8 + r + 4];
        qf[ks][3] = Ps2[(qrow + 8) * PSTR2 + ks * 8 + r + 4];
    }
    __syncwarp();

    float oacc[8][4] = {};
    float m0 = -1e30f, m1 = -1e30f, l0 = 0.0f, l1 = 0.0f;

    const int NIT = Ntok / 64;
    for (int it = 0; it < NIT; it++) {
        int cur = it & 1, nxt = cur ^ 1;
        unsigned* Ks2 = KsB + cur * FKB_U32;
        unsigned* Vs2 = VsB + cur * FVB_U32;

        uint4 pk0, pk1, pva, pvc;
        int pk2 = tid >> 3, pd8 = (tid & 7) * 8;
        if (it + 1 < NIT) {
            int n1 = (it + 1) * 64;
            {
                int j = tid;
                int key = j >> 3, d8 = (j & 7) * 8;
                pk0 = *(const uint4*)(qkv + (size_t)(b * Ntok + n1 + key) * 3 * Hdim
                                      + Hdim + h * HD + d8);
                j = tid + 256;
                key = j >> 3; d8 = (j & 7) * 8;
                pk1 = *(const uint4*)(qkv + (size_t)(b * Ntok + n1 + key) * 3 * Hdim
                                      + Hdim + h * HD + d8);
            }
            const __half* vp = qkv + (size_t)(b * Ntok + n1 + 2 * pk2) * 3 * Hdim
                               + 2 * Hdim + h * HD + pd8;
            pva = *(const uint4*)vp;
            pvc = *(const uint4*)(vp + 3 * Hdim);
        }

        float sacc[8][4] = {};
        #pragma unroll
        for (int ks = 0; ks < 4; ks++) {
            #pragma unroll
            for (int nj = 0; nj < 8; nj++) {
                int key = nj * 8 + g;
                unsigned bf[2];
                bf[0] = Ks2[key * KSTR2 + ks * 8 + r];
                bf[1] = Ks2[key * KSTR2 + ks * 8 + r + 4];
                mma_f16(sacc[nj], qf[ks], bf);
            }
        }

        float mc0 = -1e30f, mc1 = -1e30f;
        #pragma unroll
        for (int nj = 0; nj < 8; nj++) {
            mc0 = fmaxf(mc0, fmaxf(sacc[nj][0], sacc[nj][1]));
            mc1 = fmaxf(mc1, fmaxf(sacc[nj][2], sacc[nj][3]));
        }
        mc0 = fmaxf(mc0, __shfl_xor_sync(0xffffffffu, mc0, 1));
        mc0 = fmaxf(mc0, __shfl_xor_sync(0xffffffffu, mc0, 2));
        mc1 = fmaxf(mc1, __shfl_xor_sync(0xffffffffu, mc1, 1));
        mc1 = fmaxf(mc1, __shfl_xor_sync(0xffffffffu, mc1, 2));
        float mn0 = fmaxf(m0, mc0), mn1 = fmaxf(m1, mc1);
        float a0 = __expf(m0 - mn0), a1 = __expf(m1 - mn1);
        float rs0 = 0.0f, rs1 = 0.0f;
        #pragma unroll
        for (int nj = 0; nj < 8; nj++) {
            float p0 = __expf(sacc[nj][0] - mn0);
            float p1 = __expf(sacc[nj][1] - mn0);
            float p2 = __expf(sacc[nj][2] - mn1);
            float p3 = __expf(sacc[nj][3] - mn1);
            rs0 += p0 + p1; rs1 += p2 + p3;
            Ps2[qrow * PSTR2 + nj * 4 + r]       = f2h2(p0, p1);
            Ps2[(qrow + 8) * PSTR2 + nj * 4 + r] = f2h2(p2, p3);
        }
        rs0 += __shfl_xor_sync(0xffffffffu, rs0, 1);
        rs0 += __shfl_xor_sync(0xffffffffu, rs0, 2);
        rs1 += __shfl_xor_sync(0xffffffffu, rs1, 1);
        rs1 += __shfl_xor_sync(0xffffffffu, rs1, 2);
        l0 = l0 * a0 + rs0;
        l1 = l1 * a1 + rs1;
        m0 = mn0; m1 = mn1;
        #pragma unroll
        for (int nj = 0; nj < 8; nj++) {
            oacc[nj][0] *= a0; oacc[nj][1] *= a0;
            oacc[nj][2] *= a1; oacc[nj][3] *= a1;
        }
        __syncwarp();

        #pragma unroll
        for (int ks = 0; ks < 4; ks++) {
            unsigned af[4];
            af[0] = Ps2[qrow * PSTR2 + ks * 8 + r];
            af[1] = Ps2[(qrow + 8) * PSTR2 + ks * 8 + r];
            af[2] = Ps2[qrow * PSTR2 + ks * 8 + r + 4];
            af[3] = Ps2[(qrow + 8) * PSTR2 + ks * 8 + r + 4];
            #pragma unroll
            for (int nj = 0; nj < 8; nj++) {
                unsigned bf[2];
                bf[0] = Vs2[(ks * 8 + r) * VSTR2 + nj * 8 + g];
                bf[1] = Vs2[(ks * 8 + r + 4) * VSTR2 + nj * 8 + g];
                mma_f16(oacc[nj], af, bf);
            }
        }

        if (it + 1 < NIT) {
            unsigned* Kn = KsB + nxt * FKB_U32;
            unsigned* Vn = VsB + nxt * FVB_U32;
            {
                int j = tid;
                int key = j >> 3;
                *(uint4*)&Kn[key * KSTR2 + (j & 7) * 4] = pk0;
                j = tid + 256;
                key = j >> 3;
                *(uint4*)&Kn[key * KSTR2 + (j & 7) * 4] = pk1;
            }
            unsigned* q = &Vn[pk2 * VSTR2 + pd8];
            q[0] = __byte_perm(pva.x, pvc.x, 0x5410); q[1] = __byte_perm(pva.x, pvc.x, 0x7632);
            q[2] = __byte_perm(pva.y, pvc.y, 0x5410); q[3] = __byte_perm(pva.y, pvc.y, 0x7632);
            q[4] = __byte_perm(pva.z, pvc.z, 0x5410); q[5] = __byte_perm(pva.z, pvc.z, 0x7632);
            q[6] = __byte_perm(pva.w, pvc.w, 0x5410); q[7] = __byte_perm(pva.w, pvc.w, 0x7632);
        }
        __syncthreads();
    }

    float i0 = 1.0f / l0, i1 = 1.0f / l1;
    #pragma unroll
    for (int nj = 0; nj < 8; nj++) {
        int col = h * HD + nj * 8 + 2 * r;
        *(unsigned*)&out[(size_t)(b * Ntok + q0 + qrow) * Hdim + col]
            = f2h2(oacc[nj][0] * i0, oacc[nj][1] * i0);
        *(unsigned*)&out[(size_t)(b * Ntok + q0 + qrow + 8) * Hdim + col]
            = f2h2(oacc[nj][2] * i1, oacc[nj][3] * i1);
    }
}

// ------------------------- launch ------------------------------------------
extern "C" void kernel_launch(void* const* d_in, const int* in_sizes, int n_in,
                              void* d_out, int out_size)
{
    const float* x      = (const float*)d_in[0];
    const float* c      = (const float*)d_in[1];
    const float* w_mod  = (const float*)d_in[2];
    const float* b_mod  = (const float*)d_in[3];
    const float* w_qkv  = (const float*)d_in[4];
    const float* b_qkv  = (const float*)d_in[5];
    const float* w_proj = (const float*)d_in[6];
    const float* b_proj = (const float*)d_in[7];
    const float* w1     = (const float*)d_in[8];
    const float* b1     = (const float*)d_in[9];
    const float* w2     = (const float*)d_in[10];
    const float* b2     = (const float*)d_in[11];
    float* out = (float*)d_out;

    float *cm, *cpart, *x2;
    __half *xmh, *qkvh, *attnh, *xm2h, *hidh, *wqkvH, *w1H, *w2H, *wpH;
    cudaGetSymbolAddress((void**)&cm,    g_cm);
    cudaGetSymbolAddress((void**)&cpart, g_cpart);
    cudaGetSymbolAddress((void**)&xmh,   g_xmh);
    cudaGetSymbolAddress((void**)&qkvh,  g_qkvh);
    cudaGetSymbolAddress((void**)&attnh, g_attnh);
    cudaGetSymbolAddress((void**)&x2,    g_x2);
    cudaGetSymbolAddress((void**)&xm2h,  g_xm2h);
    cudaGetSymbolAddress((void**)&hidh,  g_hidh);
    cudaGetSymbolAddress((void**)&wqkvH, g_wqkvH);
    cudaGetSymbolAddress((void**)&w1H,   g_w1H);
    cudaGetSymbolAddress((void**)&w2H,   g_w2H);
    cudaGetSymbolAddress((void**)&wpH,   g_wpH);

    cudaFuncSetAttribute(gemm_h<0>, cudaFuncAttributeMaxDynamicSharedMemorySize, GSMEM2);
    cudaFuncSetAttribute(gemm_h<1>, cudaFuncAttributeMaxDynamicSharedMemorySize, GSMEM2);
    cudaFuncSetAttribute(gemm_h<2>, cudaFuncAttributeMaxDynamicSharedMemorySize, GSMEM2);
    cudaFuncSetAttribute(gemm_h<3>, cudaFuncAttributeMaxDynamicSharedMemorySize, GSMEM2);
    cudaFuncSetAttribute(flash_attn, cudaFuncAttributeMaxDynamicSharedMemorySize, FSMEM);

    // 0. weight conversions (plain half [K][N], vectorized)
    whalf_kernel<<<(3 * Hdim * Hdim) / 1024, 256>>>(w_qkv, wqkvH);
    whalf_kernel<<<(Hdim * (size_t)DFF) / 1024, 256>>>(w1, w1H);
    whalf_kernel<<<((size_t)DFF * Hdim) / 1024, 256>>>(w2, w2H);
    whalf_kernel<<<(Hdim * Hdim) / 1024, 256>>>(w_proj, wpH);

    // 1. conditioning -> modulation params (split-K)
    cond_part_kernel<<<dim3(24, 4, 8), 256>>>(c, w_mod, cpart);
    cond_reduce_kernel<<<dim3(24, 4), 256>>>(cpart, b_mod, cm);

    // 2. LN + modulate (msa) -> half
    ln_mod_h_kernel<<<ROWS, 256>>>(x, cm, 0, Hdim, xmh);

    // 3. qkv (half out, Q pre-scaled by 1/8)
    gemm_h<0><<<dim3(3 * Hdim / 128, ROWS / 128), 256, GSMEM2>>>(
        xmh, wqkvH, b_qkv, qkvh, ROWS, 3 * Hdim, Hdim, nullptr, nullptr);

    // 4. flash attention -> half attnout
    flash_attn<<<dim3(Ntok / 128, Bsz * NH), 256, FSMEM>>>(qkvh, attnh);

    // 5. x2 = (attnout @ w_proj + b_proj) * (1 + gate_msa)   (float out)
    gemm_h<2><<<dim3(Hdim / 128, ROWS / 128), 256, GSMEM2>>>(
        attnh, wpH, b_proj, x2, ROWS, Hdim, Hdim, cm + 2 * Hdim, nullptr);

    // 6. LN + modulate (mlp) -> half
    ln_mod_h_kernel<<<ROWS, 256>>>(x2, cm, 3 * Hdim, 4 * Hdim, xm2h);

    // 7. hid = gelu(xm2 @ w1 + b1)  (half out)
    gemm_h<1><<<dim3(DFF / 128, ROWS / 128), 256, GSMEM2>>>(
        xm2h, w1H, b1, hidh, ROWS, DFF, Hdim, nullptr, nullptr);

    // 8. out = x2 + gate_mlp * (hid @ w2 + b2)  (float out)
    gemm_h<3><<<dim3(Hdim / 128, ROWS / 128), 256, GSMEM2>>>(
        hidh, w2H, b2, out, ROWS, Hdim, DFF, cm + 5 * Hdim, x2);
}

// round 13
// speedup vs baseline: 7.3910x; 1.0108x over previous
#include <cuda_runtime.h>
#include <cuda_fp16.h>
#include <cstdint>
#include <math.h>

// ---------------------------------------------------------------------------
// DiT block: fp16 mma.sync GEMMs (128x128, BK=64, cp.async 3-stage, ldmatrix,
// 2 CTAs/SM) + double-buffered flash attention + split-K cond modulation.
// B=4, N=1024, H=1024, heads=16, d=64, D_FF=4096
// ---------------------------------------------------------------------------

#define Bsz 4
#define Ntok 1024
#define Hdim 1024
#define NH 16
#define HD 64
#define DFF 4096
#define ROWS (Bsz * Ntok)      // 4096
#define CM_STRIDE (6 * Hdim)   // 6144

// ------------------------- scratch (device globals) ------------------------
__device__ float    g_cm[Bsz * CM_STRIDE];
__device__ float    g_cpart[Bsz * 8 * CM_STRIDE];
__device__ __half   g_xmh[ROWS * Hdim];
__device__ __half   g_qkvh[ROWS * 3 * Hdim];
__device__ __half   g_attnh[ROWS * Hdim];
__device__ float    g_x2[ROWS * Hdim];
__device__ __half   g_xm2h[ROWS * Hdim];
__device__ __half   g_hidh[ROWS * DFF];
// plain half weights [K][N]
__device__ __half   g_wqkvH[Hdim * 3 * Hdim];
__device__ __half   g_w1H[Hdim * DFF];
__device__ __half   g_w2H[DFF * Hdim];
__device__ __half   g_wpH[Hdim * Hdim];

// ------------------------- helpers -----------------------------------------
__device__ __forceinline__ unsigned f2h2(float a, float b) {
    __half2 h = __floats2half2_rn(a, b);
    return *(unsigned*)&h;
}

__device__ __forceinline__ uint32_t smem_u32(const void* p) {
    uint32_t a;
    asm("{ .reg .u64 t; cvta.to.shared.u64 t, %1; cvt.u32.u64 %0, t; }"
        : "=r"(a) : "l"(p));
    return a;
}

__device__ __forceinline__ void mma_f16(float* d, const unsigned* a, const unsigned* b) {
    asm volatile(
        "mma.sync.aligned.m16n8k16.row.col.f32.f16.f16.f32 "
        "{%0,%1,%2,%3},{%4,%5,%6,%7},{%8,%9},{%0,%1,%2,%3};\n"
        : "+f"(d[0]), "+f"(d[1]), "+f"(d[2]), "+f"(d[3])
        : "r"(a[0]), "r"(a[1]), "r"(a[2]), "r"(a[3]), "r"(b[0]), "r"(b[1]));
}

#define LDSM4(r0, r1, r2, r3, a) \
    asm volatile("ldmatrix.sync.aligned.m8n8.x4.shared.b16 {%0,%1,%2,%3}, [%4];" \
                 : "=r"(r0), "=r"(r1), "=r"(r2), "=r"(r3) : "r"(a))
#define LDSM4T(r0, r1, r2, r3, a) \
    asm volatile("ldmatrix.sync.aligned.m8n8.x4.trans.shared.b16 {%0,%1,%2,%3}, [%4];" \
                 : "=r"(r0), "=r"(r1), "=r"(r2), "=r"(r3) : "r"(a))

#define CP_ASYNC16(saddr, gptr) \
    asm volatile("cp.async.cg.shared.global [%0], [%1], 16;" \
                 :: "r"(saddr), "l"(gptr) : "memory")
#define CP_COMMIT() asm volatile("cp.async.commit_group;" ::: "memory")
#define CP_WAIT1()  asm volatile("cp.async.wait_group 1;" ::: "memory")

// ------------------------- fused weight -> half ----------------------------
// all four weights converted by one grid-stride kernel (float4 granular)
#define WQKV_F4 (3 * Hdim * Hdim / 4)          // 786432
#define W1_F4   (Hdim * DFF / 4)               // 1048576
#define W2_F4   (DFF * Hdim / 4)               // 1048576
#define WP_F4   (Hdim * Hdim / 4)              // 262144
#define TOT_F4  (WQKV_F4 + W1_F4 + W2_F4 + WP_F4)

__global__ void whalf_all_kernel(const float* __restrict__ wqkv,
                                 const float* __restrict__ w1,
                                 const float* __restrict__ w2,
                                 const float* __restrict__ wp,
                                 __half* __restrict__ oqkv,
                                 __half* __restrict__ o1,
                                 __half* __restrict__ o2,
                                 __half* __restrict__ op)
{
    size_t i = (size_t)blockIdx.x * 256 + threadIdx.x;
    if (i >= TOT_F4) return;
    const float* src;
    __half* dst;
    size_t off = i;
    if (off < WQKV_F4)                       { src = wqkv; dst = oqkv; }
    else if ((off -= WQKV_F4) < W1_F4)       { src = w1;   dst = o1;   }
    else if ((off -= W1_F4) < W2_F4)         { src = w2;   dst = o2;   }
    else { off -= W2_F4;                       src = wp;   dst = op;   }
    float4 v = *(const float4*)(src + off * 4);
    uint2 h = make_uint2(f2h2(v.x, v.y), f2h2(v.z, v.w));
    *(uint2*)(dst + off * 4) = h;
}

// ------------------------- cond modulation (split-K) ------------------------
__global__ void cond_part_kernel(const float* __restrict__ c,
                                 const float* __restrict__ w,
                                 float* __restrict__ part)
{
    int j = blockIdx.x * 256 + threadIdx.x;
    int b = blockIdx.y, kc = blockIdx.z;
    __shared__ float sc[128];
    if (threadIdx.x < 128) {
        float t = c[b * Hdim + kc * 128 + threadIdx.x];
        sc[threadIdx.x] = t / (1.0f + expf(-t));
    }
    __syncthreads();
    float acc = 0.0f;
    const float* wp = w + (size_t)(kc * 128) * CM_STRIDE + j;
    #pragma unroll 8
    for (int k = 0; k < 128; k++)
        acc += sc[k] * wp[(size_t)k * CM_STRIDE];
    part[(size_t)(b * 8 + kc) * CM_STRIDE + j] = acc;
}

__global__ void cond_reduce_kernel(const float* __restrict__ part,
                                   const float* __restrict__ bmod,
                                   float* __restrict__ cm)
{
    int j = blockIdx.x * 256 + threadIdx.x;
    int b = blockIdx.y;
    float acc = bmod[j];
    #pragma unroll
    for (int s = 0; s < 8; s++)
        acc += part[(size_t)(b * 8 + s) * CM_STRIDE + j];
    cm[b * CM_STRIDE + j] = acc;
}

// ------------------------- LayerNorm + modulate -> half ---------------------
__global__ void ln_mod_h_kernel(const float* __restrict__ x,
                                const float* __restrict__ cm,
                                int shiftOff, int scaleOff,
                                __half* __restrict__ out)
{
    int row = blockIdx.x;
    int b = row >> 10;
    const float* xr = x + (size_t)row * Hdim;
    int tid = threadIdx.x;
    int col4 = tid * 4;
    float4 t = *(const float4*)(xr + col4);
    float s  = t.x + t.y + t.z + t.w;
    float sq = t.x * t.x + t.y * t.y + t.z * t.z + t.w * t.w;
    #pragma unroll
    for (int o = 16; o > 0; o >>= 1) {
        s  += __shfl_down_sync(0xffffffffu, s,  o);
        sq += __shfl_down_sync(0xffffffffu, sq, o);
    }
    __shared__ float red[20];
    int warp = tid >> 5, lane = tid & 31;
    if (lane == 0) { red[warp] = s; red[warp + 8] = sq; }
    __syncthreads();
    if (tid == 0) {
        float S = 0.0f, SQ = 0.0f;
        #pragma unroll
        for (int w = 0; w < 8; w++) { S += red[w]; SQ += red[w + 8]; }
        float mu = S * (1.0f / Hdim);
        float var = SQ * (1.0f / Hdim) - mu * mu;
        red[16] = mu;
        red[17] = rsqrtf(var + 1e-5f);
    }
    __syncthreads();
    float mu = red[16], inv = red[17];
    const float* sh = cm + b * CM_STRIDE + shiftOff;
    const float* sc = cm + b * CM_STRIDE + scaleOff;
    float4 shv = *(const float4*)(sh + col4);
    float4 scv = *(const float4*)(sc + col4);
    float v0 = (t.x - mu) * inv * (1.0f + scv.x) + shv.x;
    float v1 = (t.y - mu) * inv * (1.0f + scv.y) + shv.y;
    float v2 = (t.z - mu) * inv * (1.0f + scv.z) + shv.z;
    float v3 = (t.w - mu) * inv * (1.0f + scv.w) + shv.w;
    uint2 o2 = make_uint2(f2h2(v0, v1), f2h2(v2, v3));
    *(uint2*)&out[(size_t)row * Hdim + col4] = o2;
}

// ------------------------- fp16 GEMM: 128x128, BK=64, 3-stage, 2 CTAs/SM ----
// A smem: [row][k], 144B/row (128B data + 16B pad), stride 36 words
// B smem: [k][n],  272B/row (256B data + 16B pad), stride 68 words
#define AW 36
#define BW 68
#define STAGE_U32 (128 * AW + 64 * BW)    // 4608 + 4352 = 8960
#define GSMEM2 (3 * STAGE_U32 * 4)        // 107520 bytes

template<int EPI>
__global__ __launch_bounds__(256, 2)
void gemm_h(const __half* __restrict__ A, const __half* __restrict__ Bh,
            const float* __restrict__ bias, void* __restrict__ Cout,
            int M, int N, int K,
            const float* __restrict__ gate, const float* __restrict__ resid)
{
    extern __shared__ unsigned sm[];
    int tid = threadIdx.x;
    int warp = tid >> 5, lane = tid & 31;
    int warpM = warp >> 2, warpN = warp & 3;   // 2x4 warp grid, 64x32 warp tile
    int g = lane >> 2, r = lane & 3;
    int rowBase = blockIdx.y * 128, colBase = blockIdx.x * 128;
    int kts = K / 64;

    uint32_t smBase = smem_u32(sm);

    auto loadStage = [&](int stage, int kt) {
        uint32_t sA = smBase + stage * STAGE_U32 * 4;
        uint32_t sB = sA + 128 * AW * 4;
        const __half* Ag = A + (size_t)rowBase * K + kt * 64;
        const __half* Bg = Bh + (size_t)(kt * 64) * N + colBase;
        // A: 128 rows x 128B (8 x 16B), 1024 cp.async
        #pragma unroll
        for (int i = 0; i < 4; i++) {
            int j = tid + i * 256;
            int row = j >> 3, seg = j & 7;
            CP_ASYNC16(sA + row * 144 + seg * 16, Ag + (size_t)row * K + seg * 8);
        }
        // B: 64 rows x 256B (16 x 16B), 1024 cp.async
        #pragma unroll
        for (int i = 0; i < 4; i++) {
            int j = tid + i * 256;
            int row = j >> 4, seg = j & 15;
            CP_ASYNC16(sB + row * 272 + seg * 16, Bg + (size_t)row * N + seg * 8);
        }
    };

    float acc[4][4][4] = {};

    loadStage(0, 0); CP_COMMIT();
    loadStage(1, 1); CP_COMMIT();

    int lrow = lane & 15, lhi = lane >> 4;

    for (int kt = 0; kt < kts; kt++) {
        CP_WAIT1();
        __syncthreads();
        if (kt + 2 < kts) loadStage((kt + 2) % 3, kt + 2);
        CP_COMMIT();

        uint32_t sA = smBase + (kt % 3) * STAGE_U32 * 4;
        uint32_t sB = sA + 128 * AW * 4;
        #pragma unroll
        for (int ks = 0; ks < 4; ks++) {
            unsigned af[4][4], bf[4][2];
            #pragma unroll
            for (int mi = 0; mi < 4; mi++) {
                uint32_t a = sA + ((warpM * 64 + mi * 16 + lrow) * AW
                                   + ks * 8 + lhi * 4) * 4;
                LDSM4(af[mi][0], af[mi][1], af[mi][2], af[mi][3], a);
            }
            #pragma unroll
            for (int p = 0; p < 2; p++) {
                uint32_t bAddr = sB + ((ks * 16 + lrow) * BW
                                       + warpN * 16 + p * 8 + lhi * 4) * 4;
                LDSM4T(bf[2 * p][0], bf[2 * p][1], bf[2 * p + 1][0], bf[2 * p + 1][1], bAddr);
            }
            #pragma unroll
            for (int mi = 0; mi < 4; mi++)
                #pragma unroll
                for (int nj = 0; nj < 4; nj++)
                    mma_f16(acc[mi][nj], af[mi], bf[nj]);
        }
    }

    // epilogue
    #pragma unroll
    for (int mi = 0; mi < 4; mi++) {
        #pragma unroll
        for (int rr = 0; rr < 2; rr++) {
            int row = rowBase + warpM * 64 + mi * 16 + g + rr * 8;
            int b = row >> 10;
            #pragma unroll
            for (int nj = 0; nj < 4; nj++) {
                int col = colBase + warpN * 32 + nj * 8 + r * 2;
                float v0 = acc[mi][nj][rr * 2 + 0] + __ldg(&bias[col]);
                float v1 = acc[mi][nj][rr * 2 + 1] + __ldg(&bias[col + 1]);
                if (EPI == 0) {
                    float sc = (col < Hdim) ? 0.125f : 1.0f;
                    __half* Ch = (__half*)Cout;
                    *(unsigned*)&Ch[(size_t)row * N + col] = f2h2(v0 * sc, v1 * sc);
                } else if (EPI == 1) {
                    v0 = 0.5f * v0 * (1.0f + erff(v0 * 0.70710678118654752f));
                    v1 = 0.5f * v1 * (1.0f + erff(v1 * 0.70710678118654752f));
                    __half* Ch = (__half*)Cout;
                    *(unsigned*)&Ch[(size_t)row * N + col] = f2h2(v0, v1);
                } else if (EPI == 2) {
                    v0 *= (1.0f + __ldg(&gate[b * CM_STRIDE + col]));
                    v1 *= (1.0f + __ldg(&gate[b * CM_STRIDE + col + 1]));
                    *(float2*)&((float*)Cout)[(size_t)row * N + col] = make_float2(v0, v1);
                } else {
                    v0 = resid[(size_t)row * N + col]     + __ldg(&gate[b * CM_STRIDE + col])     * v0;
                    v1 = resid[(size_t)row * N + col + 1] + __ldg(&gate[b * CM_STRIDE + col + 1]) * v1;
                    *(float2*)&((float*)Cout)[(size_t)row * N + col] = make_float2(v0, v1);
                }
            }
        }
    }
}

// ------------------------- flash attention (double-buffered K/V) ------------
#define PSTR2 36
#define KSTR2 36
#define VSTR2 72
#define FPS_U32 (128 * PSTR2)
#define FKB_U32 (64 * KSTR2)
#define FVB_U32 (32 * VSTR2)
#define FSMEM ((FPS_U32 + 2 * FKB_U32 + 2 * FVB_U32) * 4)   // 55296 bytes

__global__ __launch_bounds__(256)
void flash_attn(const __half* __restrict__ qkv, __half* __restrict__ out)
{
    extern __shared__ unsigned fsm[];
    unsigned* Ps2 = fsm;
    unsigned* KsB = fsm + FPS_U32;
    unsigned* VsB = fsm + FPS_U32 + 2 * FKB_U32;

    int tid = threadIdx.x;
    int warp = tid >> 5, lane = tid & 31;
    int g = lane >> 2, r = lane & 3;
    int bh = blockIdx.y;
    int b = bh >> 4, h = bh & 15;
    int q0 = blockIdx.x * 128;

    #pragma unroll
    for (int i = 0; i < 4; i++) {
        int j = tid + i * 256;
        int row = j >> 3, d8 = (j & 7) * 8;
        uint4 v = *(const uint4*)(qkv + (size_t)(b * Ntok + q0 + row) * 3 * Hdim
                                  + h * HD + d8);
        *(uint4*)&Ps2[row * PSTR2 + (j & 7) * 4] = v;
    }

    {
        unsigned* Ks2 = KsB;
        unsigned* Vs2 = VsB;
        #pragma unroll
        for (int i = 0; i < 2; i++) {
            int j = tid + i * 256;
            int key = j >> 3, d8 = (j & 7) * 8;
            uint4 v = *(const uint4*)(qkv + (size_t)(b * Ntok + key) * 3 * Hdim
                                      + Hdim + h * HD + d8);
            *(uint4*)&Ks2[key * KSTR2 + (j & 7) * 4] = v;
        }
        int k2 = tid >> 3, d8 = (tid & 7) * 8;
        const __half* vp = qkv + (size_t)(b * Ntok + 2 * k2) * 3 * Hdim
                           + 2 * Hdim + h * HD + d8;
        uint4 a = *(const uint4*)vp;
        uint4 c = *(const uint4*)(vp + 3 * Hdim);
        unsigned* q = &Vs2[k2 * VSTR2 + d8];
        q[0] = __byte_perm(a.x, c.x, 0x5410); q[1] = __byte_perm(a.x, c.x, 0x7632);
        q[2] = __byte_perm(a.y, c.y, 0x5410); q[3] = __byte_perm(a.y, c.y, 0x7632);
        q[4] = __byte_perm(a.z, c.z, 0x5410); q[5] = __byte_perm(a.z, c.z, 0x7632);
        q[6] = __byte_perm(a.w, c.w, 0x5410); q[7] = __byte_perm(a.w, c.w, 0x7632);
    }
    __syncthreads();

    int qrow = warp * 16 + g;
    unsigned qf[4][4];
    #pragma unroll
    for (int ks = 0; ks < 4; ks++) {
        qf[ks][0] = Ps2[qrow * PSTR2 + ks * 8 + r];
        qf[ks][1] = Ps2[(qrow + 8) * PSTR2 + ks * 8 + r];
        qf[ks][2] = Ps2[qrow * PSTR2 + ks * 8 + r + 4];
        qf[ks][3] = Ps2[(qrow + 8) * PSTR2 + ks * 8 + r + 4];
    }
    __syncwarp();

    float oacc[8][4] = {};
    float m0 = -1e30f, m1 = -1e30f, l0 = 0.0f, l1 = 0.0f;

    const int NIT = Ntok / 64;
    for (int it = 0; it < NIT; it++) {
        int cur = it & 1, nxt = cur ^ 1;
        unsigned* Ks2 = KsB + cur * FKB_U32;
        unsigned* Vs2 = VsB + cur * FVB_U32;

        uint4 pk0, pk1, pva, pvc;
        int pk2 = tid >> 3, pd8 = (tid & 7) * 8;
        if (it + 1 < NIT) {
            int n1 = (it + 1) * 64;
            {
                int j = tid;
                int key = j >> 3, d8 = (j & 7) * 8;
                pk0 = *(const uint4*)(qkv + (size_t)(b * Ntok + n1 + key) * 3 * Hdim
                                      + Hdim + h * HD + d8);
                j = tid + 256;
                key = j >> 3; d8 = (j & 7) * 8;
                pk1 = *(const uint4*)(qkv + (size_t)(b * Ntok + n1 + key) * 3 * Hdim
                                      + Hdim + h * HD + d8);
            }
            const __half* vp = qkv + (size_t)(b * Ntok + n1 + 2 * pk2) * 3 * Hdim
                               + 2 * Hdim + h * HD + pd8;
            pva = *(const uint4*)vp;
            pvc = *(const uint4*)(vp + 3 * Hdim);
        }

        float sacc[8][4] = {};
        #pragma unroll
        for (int ks = 0; ks < 4; ks++) {
            #pragma unroll
            for (int nj = 0; nj < 8; nj++) {
                int key = nj * 8 + g;
                unsigned bf[2];
                bf[0] = Ks2[key * KSTR2 + ks * 8 + r];
                bf[1] = Ks2[key * KSTR2 + ks * 8 + r + 4];
                mma_f16(sacc[nj], qf[ks], bf);
            }
        }

        float mc0 = -1e30f, mc1 = -1e30f;
        #pragma unroll
        for (int nj = 0; nj < 8; nj++) {
            mc0 = fmaxf(mc0, fmaxf(sacc[nj][0], sacc[nj][1]));
            mc1 = fmaxf(mc1, fmaxf(sacc[nj][2], sacc[nj][3]));
        }
        mc0 = fmaxf(mc0, __shfl_xor_sync(0xffffffffu, mc0, 1));
        mc0 = fmaxf(mc0, __shfl_xor_sync(0xffffffffu, mc0, 2));
        mc1 = fmaxf(mc1, __shfl_xor_sync(0xffffffffu, mc1, 1));
        mc1 = fmaxf(mc1, __shfl_xor_sync(0xffffffffu, mc1, 2));
        float mn0 = fmaxf(m0, mc0), mn1 = fmaxf(m1, mc1);
        float a0 = __expf(m0 - mn0), a1 = __expf(m1 - mn1);
        float rs0 = 0.0f, rs1 = 0.0f;
        #pragma unroll
        for (int nj = 0; nj < 8; nj++) {
            float p0 = __expf(sacc[nj][0] - mn0);
            float p1 = __expf(sacc[nj][1] - mn0);
            float p2 = __expf(sacc[nj][2] - mn1);
            float p3 = __expf(sacc[nj][3] - mn1);
            rs0 += p0 + p1; rs1 += p2 + p3;
            Ps2[qrow * PSTR2 + nj * 4 + r]       = f2h2(p0, p1);
            Ps2[(qrow + 8) * PSTR2 + nj * 4 + r] = f2h2(p2, p3);
        }
        rs0 += __shfl_xor_sync(0xffffffffu, rs0, 1);
        rs0 += __shfl_xor_sync(0xffffffffu, rs0, 2);
        rs1 += __shfl_xor_sync(0xffffffffu, rs1, 1);
        rs1 += __shfl_xor_sync(0xffffffffu, rs1, 2);
        l0 = l0 * a0 + rs0;
        l1 = l1 * a1 + rs1;
        m0 = mn0; m1 = mn1;
        #pragma unroll
        for (int nj = 0; nj < 8; nj++) {
            oacc[nj][0] *= a0; oacc[nj][1] *= a0;
            oacc[nj][2] *= a1; oacc[nj][3] *= a1;
        }
        __syncwarp();

        #pragma unroll
        for (int ks = 0; ks < 4; ks++) {
            unsigned af[4];
            af[0] = Ps2[qrow * PSTR2 + ks * 8 + r];
            af[1] = Ps2[(qrow + 8) * PSTR2 + ks * 8 + r];
            af[2] = Ps2[qrow * PSTR2 + ks * 8 + r + 4];
            af[3] = Ps2[(qrow + 8) * PSTR2 + ks * 8 + r + 4];
            #pragma unroll
            for (int nj = 0; nj < 8; nj++) {
                unsigned bf[2];
                bf[0] = Vs2[(ks * 8 + r) * VSTR2 + nj * 8 + g];
                bf[1] = Vs2[(ks * 8 + r + 4) * VSTR2 + nj * 8 + g];
                mma_f16(oacc[nj], af, bf);
            }
        }

        if (it + 1 < NIT) {
            unsigned* Kn = KsB + nxt * FKB_U32;
            unsigned* Vn = VsB + nxt * FVB_U32;
            {
                int j = tid;
                int key = j >> 3;
                *(uint4*)&Kn[key * KSTR2 + (j & 7) * 4] = pk0;
                j = tid + 256;
                key = j >> 3;
                *(uint4*)&Kn[key * KSTR2 + (j & 7) * 4] = pk1;
            }
            unsigned* q = &Vn[pk2 * VSTR2 + pd8];
            q[0] = __byte_perm(pva.x, pvc.x, 0x5410); q[1] = __byte_perm(pva.x, pvc.x, 0x7632);
            q[2] = __byte_perm(pva.y, pvc.y, 0x5410); q[3] = __byte_perm(pva.y, pvc.y, 0x7632);
            q[4] = __byte_perm(pva.z, pvc.z, 0x5410); q[5] = __byte_perm(pva.z, pvc.z, 0x7632);
            q[6] = __byte_perm(pva.w, pvc.w, 0x5410); q[7] = __byte_perm(pva.w, pvc.w, 0x7632);
        }
        __syncthreads();
    }

    float i0 = 1.0f / l0, i1 = 1.0f / l1;
    #pragma unroll
    for (int nj = 0; nj < 8; nj++) {
        int col = h * HD + nj * 8 + 2 * r;
        *(unsigned*)&out[(size_t)(b * Ntok + q0 + qrow) * Hdim + col]
            = f2h2(oacc[nj][0] * i0, oacc[nj][1] * i0);
        *(unsigned*)&out[(size_t)(b * Ntok + q0 + qrow + 8) * Hdim + col]
            = f2h2(oacc[nj][2] * i1, oacc[nj][3] * i1);
    }
}

// ------------------------- launch ------------------------------------------
extern "C" void kernel_launch(void* const* d_in, const int* in_sizes, int n_in,
                              void* d_out, int out_size)
{
    const float* x      = (const float*)d_in[0];
    const float* c      = (const float*)d_in[1];
    const float* w_mod  = (const float*)d_in[2];
    const float* b_mod  = (const float*)d_in[3];
    const float* w_qkv  = (const float*)d_in[4];
    const float* b_qkv  = (const float*)d_in[5];
    const float* w_proj = (const float*)d_in[6];
    const float* b_proj = (const float*)d_in[7];
    const float* w1     = (const float*)d_in[8];
    const float* b1     = (const float*)d_in[9];
    const float* w2     = (const float*)d_in[10];
    const float* b2     = (const float*)d_in[11];
    float* out = (float*)d_out;

    float *cm, *cpart, *x2;
    __half *xmh, *qkvh, *attnh, *xm2h, *hidh, *wqkvH, *w1H, *w2H, *wpH;
    cudaGetSymbolAddress((void**)&cm,    g_cm);
    cudaGetSymbolAddress((void**)&cpart, g_cpart);
    cudaGetSymbolAddress((void**)&xmh,   g_xmh);
    cudaGetSymbolAddress((void**)&qkvh,  g_qkvh);
    cudaGetSymbolAddress((void**)&attnh, g_attnh);
    cudaGetSymbolAddress((void**)&x2,    g_x2);
    cudaGetSymbolAddress((void**)&xm2h,  g_xm2h);
    cudaGetSymbolAddress((void**)&hidh,  g_hidh);
    cudaGetSymbolAddress((void**)&wqkvH, g_wqkvH);
    cudaGetSymbolAddress((void**)&w1H,   g_w1H);
    cudaGetSymbolAddress((void**)&w2H,   g_w2H);
    cudaGetSymbolAddress((void**)&wpH,   g_wpH);

    cudaFuncSetAttribute(gemm_h<0>, cudaFuncAttributeMaxDynamicSharedMemorySize, GSMEM2);
    cudaFuncSetAttribute(gemm_h<1>, cudaFuncAttributeMaxDynamicSharedMemorySize, GSMEM2);
    cudaFuncSetAttribute(gemm_h<2>, cudaFuncAttributeMaxDynamicSharedMemorySize, GSMEM2);
    cudaFuncSetAttribute(gemm_h<3>, cudaFuncAttributeMaxDynamicSharedMemorySize, GSMEM2);
    cudaFuncSetAttribute(flash_attn, cudaFuncAttributeMaxDynamicSharedMemorySize, FSMEM);

    // 0. all weight conversions in one fused kernel
    whalf_all_kernel<<<(TOT_F4 + 255) / 256, 256>>>(
        w_qkv, w1, w2, w_proj, wqkvH, w1H, w2H, wpH);

    // 1. conditioning -> modulation params (split-K)
    cond_part_kernel<<<dim3(24, 4, 8), 256>>>(c, w_mod, cpart);
    cond_reduce_kernel<<<dim3(24, 4), 256>>>(cpart, b_mod, cm);

    // 2. LN + modulate (msa) -> half
    ln_mod_h_kernel<<<ROWS, 256>>>(x, cm, 0, Hdim, xmh);

    // 3. qkv (half out, Q pre-scaled by 1/8)
    gemm_h<0><<<dim3(3 * Hdim / 128, ROWS / 128), 256, GSMEM2>>>(
        xmh, wqkvH, b_qkv, qkvh, ROWS, 3 * Hdim, Hdim, nullptr, nullptr);

    // 4. flash attention -> half attnout
    flash_attn<<<dim3(Ntok / 128, Bsz * NH), 256, FSMEM>>>(qkvh, attnh);

    // 5. x2 = (attnout @ w_proj + b_proj) * (1 + gate_msa)   (float out)
    gemm_h<2><<<dim3(Hdim / 128, ROWS / 128), 256, GSMEM2>>>(
        attnh, wpH, b_proj, x2, ROWS, Hdim, Hdim, cm + 2 * Hdim, nullptr);

    // 6. LN + modulate (mlp) -> half
    ln_mod_h_kernel<<<ROWS, 256>>>(x2, cm, 3 * Hdim, 4 * Hdim, xm2h);

    // 7. hid = gelu(xm2 @ w1 + b1)  (half out)
    gemm_h<1><<<dim3(DFF / 128, ROWS / 128), 256, GSMEM2>>>(
        xm2h, w1H, b1, hidh, ROWS, DFF, Hdim, nullptr, nullptr);

    // 8. out = x2 + gate_mlp * (hid @ w2 + b2)  (float out)
    gemm_h<3><<<dim3(Hdim / 128, ROWS / 128), 256, GSMEM2>>>(
        hidh, w2H, b2, out, ROWS, Hdim, DFF, cm + 5 * Hdim, x2);
}

// round 14
// speedup vs baseline: 7.4941x; 1.0139x over previous
#include <cuda_runtime.h>
#include <cuda_fp16.h>
#include <cstdint>
#include <math.h>

// ---------------------------------------------------------------------------
// DiT block: fp16 mma.sync GEMMs (128x128, BK=64, cp.async 3-stage, ldmatrix,
// 2 CTAs/SM) + cp.async 3-stage flash attention + split-K cond modulation.
// B=4, N=1024, H=1024, heads=16, d=64, D_FF=4096
// ---------------------------------------------------------------------------

#define Bsz 4
#define Ntok 1024
#define Hdim 1024
#define NH 16
#define HD 64
#define DFF 4096
#define ROWS (Bsz * Ntok)      // 4096
#define CM_STRIDE (6 * Hdim)   // 6144

// ------------------------- scratch (device globals) ------------------------
__device__ float    g_cm[Bsz * CM_STRIDE];
__device__ float    g_cpart[Bsz * 8 * CM_STRIDE];
__device__ __half   g_xmh[ROWS * Hdim];
__device__ __half   g_qkvh[ROWS * 3 * Hdim];
__device__ __half   g_attnh[ROWS * Hdim];
__device__ float    g_x2[ROWS * Hdim];
__device__ __half   g_xm2h[ROWS * Hdim];
__device__ __half   g_hidh[ROWS * DFF];
// plain half weights [K][N]
__device__ __half   g_wqkvH[Hdim * 3 * Hdim];
__device__ __half   g_w1H[Hdim * DFF];
__device__ __half   g_w2H[DFF * Hdim];
__device__ __half   g_wpH[Hdim * Hdim];

// ------------------------- helpers -----------------------------------------
__device__ __forceinline__ unsigned f2h2(float a, float b) {
    __half2 h = __floats2half2_rn(a, b);
    return *(unsigned*)&h;
}

__device__ __forceinline__ uint32_t smem_u32(const void* p) {
    uint32_t a;
    asm("{ .reg .u64 t; cvta.to.shared.u64 t, %1; cvt.u32.u64 %0, t; }"
        : "=r"(a) : "l"(p));
    return a;
}

__device__ __forceinline__ void mma_f16(float* d, const unsigned* a, const unsigned* b) {
    asm volatile(
        "mma.sync.aligned.m16n8k16.row.col.f32.f16.f16.f32 "
        "{%0,%1,%2,%3},{%4,%5,%6,%7},{%8,%9},{%0,%1,%2,%3};\n"
        : "+f"(d[0]), "+f"(d[1]), "+f"(d[2]), "+f"(d[3])
        : "r"(a[0]), "r"(a[1]), "r"(a[2]), "r"(a[3]), "r"(b[0]), "r"(b[1]));
}

#define LDSM4(r0, r1, r2, r3, a) \
    asm volatile("ldmatrix.sync.aligned.m8n8.x4.shared.b16 {%0,%1,%2,%3}, [%4];" \
                 : "=r"(r0), "=r"(r1), "=r"(r2), "=r"(r3) : "r"(a))
#define LDSM4T(r0, r1, r2, r3, a) \
    asm volatile("ldmatrix.sync.aligned.m8n8.x4.trans.shared.b16 {%0,%1,%2,%3}, [%4];" \
                 : "=r"(r0), "=r"(r1), "=r"(r2), "=r"(r3) : "r"(a))

#define CP_ASYNC16(saddr, gptr) \
    asm volatile("cp.async.cg.shared.global [%0], [%1], 16;" \
                 :: "r"(saddr), "l"(gptr) : "memory")
#define CP_COMMIT() asm volatile("cp.async.commit_group;" ::: "memory")
#define CP_WAIT1()  asm volatile("cp.async.wait_group 1;" ::: "memory")

// ------------------------- fused weight -> half ----------------------------
#define WQKV_F4 (3 * Hdim * Hdim / 4)
#define W1_F4   (Hdim * DFF / 4)
#define W2_F4   (DFF * Hdim / 4)
#define WP_F4   (Hdim * Hdim / 4)
#define TOT_F4  (WQKV_F4 + W1_F4 + W2_F4 + WP_F4)

__global__ void whalf_all_kernel(const float* __restrict__ wqkv,
                                 const float* __restrict__ w1,
                                 const float* __restrict__ w2,
                                 const float* __restrict__ wp,
                                 __half* __restrict__ oqkv,
                                 __half* __restrict__ o1,
                                 __half* __restrict__ o2,
                                 __half* __restrict__ op)
{
    size_t i = (size_t)blockIdx.x * 256 + threadIdx.x;
    if (i >= TOT_F4) return;
    const float* src;
    __half* dst;
    size_t off = i;
    if (off < WQKV_F4)                       { src = wqkv; dst = oqkv; }
    else if ((off -= WQKV_F4) < W1_F4)       { src = w1;   dst = o1;   }
    else if ((off -= W1_F4) < W2_F4)         { src = w2;   dst = o2;   }
    else { off -= W2_F4;                       src = wp;   dst = op;   }
    float4 v = *(const float4*)(src + off * 4);
    uint2 h = make_uint2(f2h2(v.x, v.y), f2h2(v.z, v.w));
    *(uint2*)(dst + off * 4) = h;
}

// ------------------------- cond modulation (split-K) ------------------------
__global__ void cond_part_kernel(const float* __restrict__ c,
                                 const float* __restrict__ w,
                                 float* __restrict__ part)
{
    int j = blockIdx.x * 256 + threadIdx.x;
    int b = blockIdx.y, kc = blockIdx.z;
    __shared__ float sc[128];
    if (threadIdx.x < 128) {
        float t = c[b * Hdim + kc * 128 + threadIdx.x];
        sc[threadIdx.x] = t / (1.0f + expf(-t));
    }
    __syncthreads();
    float acc = 0.0f;
    const float* wp = w + (size_t)(kc * 128) * CM_STRIDE + j;
    #pragma unroll 8
    for (int k = 0; k < 128; k++)
        acc += sc[k] * wp[(size_t)k * CM_STRIDE];
    part[(size_t)(b * 8 + kc) * CM_STRIDE + j] = acc;
}

__global__ void cond_reduce_kernel(const float* __restrict__ part,
                                   const float* __restrict__ bmod,
                                   float* __restrict__ cm)
{
    int j = blockIdx.x * 256 + threadIdx.x;
    int b = blockIdx.y;
    float acc = bmod[j];
    #pragma unroll
    for (int s = 0; s < 8; s++)
        acc += part[(size_t)(b * 8 + s) * CM_STRIDE + j];
    cm[b * CM_STRIDE + j] = acc;
}

// ------------------------- LayerNorm + modulate -> half ---------------------
__global__ void ln_mod_h_kernel(const float* __restrict__ x,
                                const float* __restrict__ cm,
                                int shiftOff, int scaleOff,
                                __half* __restrict__ out)
{
    int row = blockIdx.x;
    int b = row >> 10;
    const float* xr = x + (size_t)row * Hdim;
    int tid = threadIdx.x;
    int col4 = tid * 4;
    float4 t = *(const float4*)(xr + col4);
    float s  = t.x + t.y + t.z + t.w;
    float sq = t.x * t.x + t.y * t.y + t.z * t.z + t.w * t.w;
    #pragma unroll
    for (int o = 16; o > 0; o >>= 1) {
        s  += __shfl_down_sync(0xffffffffu, s,  o);
        sq += __shfl_down_sync(0xffffffffu, sq, o);
    }
    __shared__ float red[20];
    int warp = tid >> 5, lane = tid & 31;
    if (lane == 0) { red[warp] = s; red[warp + 8] = sq; }
    __syncthreads();
    if (tid == 0) {
        float S = 0.0f, SQ = 0.0f;
        #pragma unroll
        for (int w = 0; w < 8; w++) { S += red[w]; SQ += red[w + 8]; }
        float mu = S * (1.0f / Hdim);
        float var = SQ * (1.0f / Hdim) - mu * mu;
        red[16] = mu;
        red[17] = rsqrtf(var + 1e-5f);
    }
    __syncthreads();
    float mu = red[16], inv = red[17];
    const float* sh = cm + b * CM_STRIDE + shiftOff;
    const float* sc = cm + b * CM_STRIDE + scaleOff;
    float4 shv = *(const float4*)(sh + col4);
    float4 scv = *(const float4*)(sc + col4);
    float v0 = (t.x - mu) * inv * (1.0f + scv.x) + shv.x;
    float v1 = (t.y - mu) * inv * (1.0f + scv.y) + shv.y;
    float v2 = (t.z - mu) * inv * (1.0f + scv.z) + shv.z;
    float v3 = (t.w - mu) * inv * (1.0f + scv.w) + shv.w;
    uint2 o2 = make_uint2(f2h2(v0, v1), f2h2(v2, v3));
    *(uint2*)&out[(size_t)row * Hdim + col4] = o2;
}

// ------------------------- fp16 GEMM: 128x128, BK=64, 3-stage, 2 CTAs/SM ----
#define AW 36
#define BW 68
#define STAGE_U32 (128 * AW + 64 * BW)    // 8960
#define GSMEM2 (3 * STAGE_U32 * 4)        // 107520 bytes

template<int EPI>
__global__ __launch_bounds__(256, 2)
void gemm_h(const __half* __restrict__ A, const __half* __restrict__ Bh,
            const float* __restrict__ bias, void* __restrict__ Cout,
            int M, int N, int K,
            const float* __restrict__ gate, const float* __restrict__ resid)
{
    extern __shared__ unsigned sm[];
    int tid = threadIdx.x;
    int warp = tid >> 5, lane = tid & 31;
    int warpM = warp >> 2, warpN = warp & 3;
    int g = lane >> 2, r = lane & 3;
    int rowBase = blockIdx.y * 128, colBase = blockIdx.x * 128;
    int kts = K / 64;

    uint32_t smBase = smem_u32(sm);

    auto loadStage = [&](int stage, int kt) {
        uint32_t sA = smBase + stage * STAGE_U32 * 4;
        uint32_t sB = sA + 128 * AW * 4;
        const __half* Ag = A + (size_t)rowBase * K + kt * 64;
        const __half* Bg = Bh + (size_t)(kt * 64) * N + colBase;
        #pragma unroll
        for (int i = 0; i < 4; i++) {
            int j = tid + i * 256;
            int row = j >> 3, seg = j & 7;
            CP_ASYNC16(sA + row * 144 + seg * 16, Ag + (size_t)row * K + seg * 8);
        }
        #pragma unroll
        for (int i = 0; i < 4; i++) {
            int j = tid + i * 256;
            int row = j >> 4, seg = j & 15;
            CP_ASYNC16(sB + row * 272 + seg * 16, Bg + (size_t)row * N + seg * 8);
        }
    };

    float acc[4][4][4] = {};

    loadStage(0, 0); CP_COMMIT();
    loadStage(1, 1); CP_COMMIT();

    int lrow = lane & 15, lhi = lane >> 4;

    for (int kt = 0; kt < kts; kt++) {
        CP_WAIT1();
        __syncthreads();
        if (kt + 2 < kts) loadStage((kt + 2) % 3, kt + 2);
        CP_COMMIT();

        uint32_t sA = smBase + (kt % 3) * STAGE_U32 * 4;
        uint32_t sB = sA + 128 * AW * 4;
        #pragma unroll
        for (int ks = 0; ks < 4; ks++) {
            unsigned af[4][4], bf[4][2];
            #pragma unroll
            for (int mi = 0; mi < 4; mi++) {
                uint32_t a = sA + ((warpM * 64 + mi * 16 + lrow) * AW
                                   + ks * 8 + lhi * 4) * 4;
                LDSM4(af[mi][0], af[mi][1], af[mi][2], af[mi][3], a);
            }
            #pragma unroll
            for (int p = 0; p < 2; p++) {
                uint32_t bAddr = sB + ((ks * 16 + lrow) * BW
                                       + warpN * 16 + p * 8 + lhi * 4) * 4;
                LDSM4T(bf[2 * p][0], bf[2 * p][1], bf[2 * p + 1][0], bf[2 * p + 1][1], bAddr);
            }
            #pragma unroll
            for (int mi = 0; mi < 4; mi++)
                #pragma unroll
                for (int nj = 0; nj < 4; nj++)
                    mma_f16(acc[mi][nj], af[mi], bf[nj]);
        }
    }

    #pragma unroll
    for (int mi = 0; mi < 4; mi++) {
        #pragma unroll
        for (int rr = 0; rr < 2; rr++) {
            int row = rowBase + warpM * 64 + mi * 16 + g + rr * 8;
            int b = row >> 10;
            #pragma unroll
            for (int nj = 0; nj < 4; nj++) {
                int col = colBase + warpN * 32 + nj * 8 + r * 2;
                float v0 = acc[mi][nj][rr * 2 + 0] + __ldg(&bias[col]);
                float v1 = acc[mi][nj][rr * 2 + 1] + __ldg(&bias[col + 1]);
                if (EPI == 0) {
                    float sc = (col < Hdim) ? 0.125f : 1.0f;
                    __half* Ch = (__half*)Cout;
                    *(unsigned*)&Ch[(size_t)row * N + col] = f2h2(v0 * sc, v1 * sc);
                } else if (EPI == 1) {
                    v0 = 0.5f * v0 * (1.0f + erff(v0 * 0.70710678118654752f));
                    v1 = 0.5f * v1 * (1.0f + erff(v1 * 0.70710678118654752f));
                    __half* Ch = (__half*)Cout;
                    *(unsigned*)&Ch[(size_t)row * N + col] = f2h2(v0, v1);
                } else if (EPI == 2) {
                    v0 *= (1.0f + __ldg(&gate[b * CM_STRIDE + col]));
                    v1 *= (1.0f + __ldg(&gate[b * CM_STRIDE + col + 1]));
                    *(float2*)&((float*)Cout)[(size_t)row * N + col] = make_float2(v0, v1);
                } else {
                    v0 = resid[(size_t)row * N + col]     + __ldg(&gate[b * CM_STRIDE + col])     * v0;
                    v1 = resid[(size_t)row * N + col + 1] + __ldg(&gate[b * CM_STRIDE + col + 1]) * v1;
                    *(float2*)&((float*)Cout)[(size_t)row * N + col] = make_float2(v0, v1);
                }
            }
        }
    }
}

// ------------------------- flash attention (cp.async 3-stage) ---------------
// K, V tiles stored natural [key][d]: 64 rows x 128B data + 16B pad (36 words)
// K fragments: scalar LDS (pairs along d). V fragments: LDSM4T ([k][n] case,
// identical bank pattern to the GEMM B operand). P staged in Ps2 per warp.
#define PSTR2 36
#define KVW 36
#define FPS_U32 (128 * PSTR2)          // 4608
#define FKV_U32 (64 * KVW)             // 2304 per buffer
#define FSMEM ((FPS_U32 + 6 * FKV_U32) * 4)   // 73728 bytes

__global__ __launch_bounds__(256, 2)
void flash_attn(const __half* __restrict__ qkv, __half* __restrict__ out)
{
    extern __shared__ unsigned fsm[];
    unsigned* Ps2 = fsm;
    uint32_t psBase = smem_u32(fsm);
    uint32_t kBase = psBase + FPS_U32 * 4;            // 3 K buffers
    uint32_t vBase = kBase + 3 * FKV_U32 * 4;         // 3 V buffers

    int tid = threadIdx.x;
    int warp = tid >> 5, lane = tid & 31;
    int g = lane >> 2, r = lane & 3;
    int lrow = lane & 15, lhi = lane >> 4;
    int bh = blockIdx.y;
    int b = bh >> 4, h = bh & 15;
    int q0 = blockIdx.x * 128;

    const int NIT = Ntok / 64;   // 16

    // issue K/V loads for a tile into stage s
    auto loadKV = [&](int s, int n0) {
        uint32_t kS = kBase + s * FKV_U32 * 4;
        uint32_t vS = vBase + s * FKV_U32 * 4;
        #pragma unroll
        for (int i = 0; i < 2; i++) {
            int j = tid + i * 256;                     // 512 slots
            int key = j >> 3, seg = j & 7;
            const __half* kp = qkv + (size_t)(b * Ntok + n0 + key) * 3 * Hdim
                               + Hdim + h * HD + seg * 8;
            CP_ASYNC16(kS + key * 144 + seg * 16, kp);
            CP_ASYNC16(vS + key * 144 + seg * 16, kp + Hdim);
        }
    };

    // prologue: tiles 0 and 1 in flight; stage Q meanwhile
    loadKV(0, 0); CP_COMMIT();
    loadKV(1, 64); CP_COMMIT();

    #pragma unroll
    for (int i = 0; i < 4; i++) {
        int j = tid + i * 256;
        int row = j >> 3, d8 = (j & 7) * 8;
        uint4 v = *(const uint4*)(qkv + (size_t)(b * Ntok + q0 + row) * 3 * Hdim
                                  + h * HD + d8);
        *(uint4*)&Ps2[row * PSTR2 + (j & 7) * 4] = v;
    }
    __syncthreads();

    int qrow = warp * 16 + g;
    unsigned qf[4][4];
    #pragma unroll
    for (int ks = 0; ks < 4; ks++) {
        qf[ks][0] = Ps2[qrow * PSTR2 + ks * 8 + r];
        qf[ks][1] = Ps2[(qrow + 8) * PSTR2 + ks * 8 + r];
        qf[ks][2] = Ps2[qrow * PSTR2 + ks * 8 + r + 4];
        qf[ks][3] = Ps2[(qrow + 8) * PSTR2 + ks * 8 + r + 4];
    }

    float oacc[8][4] = {};
    float m0 = -1e30f, m1 = -1e30f, l0 = 0.0f, l1 = 0.0f;

    for (int it = 0; it < NIT; it++) {
        int s = it % 3;
        CP_WAIT1();
        __syncthreads();
        if (it + 2 < NIT) loadKV((it + 2) % 3, (it + 2) * 64);
        CP_COMMIT();

        unsigned* Ks2 = fsm + FPS_U32 + s * FKV_U32;
        uint32_t vS = vBase + s * FKV_U32 * 4;

        // ---- S = Q K^T (K natural layout: pairs along d) ----
        float sacc[8][4] = {};
        #pragma unroll
        for (int ks = 0; ks < 4; ks++) {
            #pragma unroll
            for (int nj = 0; nj < 8; nj++) {
                int key = nj * 8 + g;
                unsigned bf[2];
                bf[0] = Ks2[key * KVW + ks * 8 + r];
                bf[1] = Ks2[key * KVW + ks * 8 + r + 4];
                mma_f16(sacc[nj], qf[ks], bf);
            }
        }

        // ---- online softmax ----
        float mc0 = -1e30f, mc1 = -1e30f;
        #pragma unroll
        for (int nj = 0; nj < 8; nj++) {
            mc0 = fmaxf(mc0, fmaxf(sacc[nj][0], sacc[nj][1]));
            mc1 = fmaxf(mc1, fmaxf(sacc[nj][2], sacc[nj][3]));
        }
        mc0 = fmaxf(mc0, __shfl_xor_sync(0xffffffffu, mc0, 1));
        mc0 = fmaxf(mc0, __shfl_xor_sync(0xffffffffu, mc0, 2));
        mc1 = fmaxf(mc1, __shfl_xor_sync(0xffffffffu, mc1, 1));
        mc1 = fmaxf(mc1, __shfl_xor_sync(0xffffffffu, mc1, 2));
        float mn0 = fmaxf(m0, mc0), mn1 = fmaxf(m1, mc1);
        float a0 = __expf(m0 - mn0), a1 = __expf(m1 - mn1);
        float rs0 = 0.0f, rs1 = 0.0f;
        #pragma unroll
        for (int nj = 0; nj < 8; nj++) {
            float p0 = __expf(sacc[nj][0] - mn0);
            float p1 = __expf(sacc[nj][1] - mn0);
            float p2 = __expf(sacc[nj][2] - mn1);
            float p3 = __expf(sacc[nj][3] - mn1);
            rs0 += p0 + p1; rs1 += p2 + p3;
            Ps2[qrow * PSTR2 + nj * 4 + r]       = f2h2(p0, p1);
            Ps2[(qrow + 8) * PSTR2 + nj * 4 + r] = f2h2(p2, p3);
        }
        rs0 += __shfl_xor_sync(0xffffffffu, rs0, 1);
        rs0 += __shfl_xor_sync(0xffffffffu, rs0, 2);
        rs1 += __shfl_xor_sync(0xffffffffu, rs1, 1);
        rs1 += __shfl_xor_sync(0xffffffffu, rs1, 2);
        l0 = l0 * a0 + rs0;
        l1 = l1 * a1 + rs1;
        m0 = mn0; m1 = mn1;
        #pragma unroll
        for (int nj = 0; nj < 8; nj++) {
            oacc[nj][0] *= a0; oacc[nj][1] *= a0;
            oacc[nj][2] *= a1; oacc[nj][3] *= a1;
        }
        __syncwarp();

        // ---- O += P V  (V natural layout, LDSM4T fragments) ----
        #pragma unroll
        for (int ks = 0; ks < 4; ks++) {
            unsigned af[4], bf[8][2];
            af[0] = Ps2[qrow * PSTR2 + ks * 8 + r];
            af[1] = Ps2[(qrow + 8) * PSTR2 + ks * 8 + r];
            af[2] = Ps2[qrow * PSTR2 + ks * 8 + r + 4];
            af[3] = Ps2[(qrow + 8) * PSTR2 + ks * 8 + r + 4];
            #pragma unroll
            for (int p = 0; p < 4; p++) {
                uint32_t vAddr = vS + ((ks * 16 + lrow) * KVW + p * 8 + lhi * 4) * 4;
                LDSM4T(bf[2 * p][0], bf[2 * p][1], bf[2 * p + 1][0], bf[2 * p + 1][1], vAddr);
            }
            #pragma unroll
            for (int nj = 0; nj < 8; nj++)
                mma_f16(oacc[nj], af, bf[nj]);
        }
    }

    float i0 = 1.0f / l0, i1 = 1.0f / l1;
    #pragma unroll
    for (int nj = 0; nj < 8; nj++) {
        int col = h * HD + nj * 8 + 2 * r;
        *(unsigned*)&out[(size_t)(b * Ntok + q0 + qrow) * Hdim + col]
            = f2h2(oacc[nj][0] * i0, oacc[nj][1] * i0);
        *(unsigned*)&out[(size_t)(b * Ntok + q0 + qrow + 8) * Hdim + col]
            = f2h2(oacc[nj][2] * i1, oacc[nj][3] * i1);
    }
}

// ------------------------- launch ------------------------------------------
extern "C" void kernel_launch(void* const* d_in, const int* in_sizes, int n_in,
                              void* d_out, int out_size)
{
    const float* x      = (const float*)d_in[0];
    const float* c      = (const float*)d_in[1];
    const float* w_mod  = (const float*)d_in[2];
    const float* b_mod  = (const float*)d_in[3];
    const float* w_qkv  = (const float*)d_in[4];
    const float* b_qkv  = (const float*)d_in[5];
    const float* w_proj = (const float*)d_in[6];
    const float* b_proj = (const float*)d_in[7];
    const float* w1     = (const float*)d_in[8];
    const float* b1     = (const float*)d_in[9];
    const float* w2     = (const float*)d_in[10];
    const float* b2     = (const float*)d_in[11];
    float* out = (float*)d_out;

    float *cm, *cpart, *x2;
    __half *xmh, *qkvh, *attnh, *xm2h, *hidh, *wqkvH, *w1H, *w2H, *wpH;
    cudaGetSymbolAddress((void**)&cm,    g_cm);
    cudaGetSymbolAddress((void**)&cpart, g_cpart);
    cudaGetSymbolAddress((void**)&xmh,   g_xmh);
    cudaGetSymbolAddress((void**)&qkvh,  g_qkvh);
    cudaGetSymbolAddress((void**)&attnh, g_attnh);
    cudaGetSymbolAddress((void**)&x2,    g_x2);
    cudaGetSymbolAddress((void**)&xm2h,  g_xm2h);
    cudaGetSymbolAddress((void**)&hidh,  g_hidh);
    cudaGetSymbolAddress((void**)&wqkvH, g_wqkvH);
    cudaGetSymbolAddress((void**)&w1H,   g_w1H);
    cudaGetSymbolAddress((void**)&w2H,   g_w2H);
    cudaGetSymbolAddress((void**)&wpH,   g_wpH);

    cudaFuncSetAttribute(gemm_h<0>, cudaFuncAttributeMaxDynamicSharedMemorySize, GSMEM2);
    cudaFuncSetAttribute(gemm_h<1>, cudaFuncAttributeMaxDynamicSharedMemorySize, GSMEM2);
    cudaFuncSetAttribute(gemm_h<2>, cudaFuncAttributeMaxDynamicSharedMemorySize, GSMEM2);
    cudaFuncSetAttribute(gemm_h<3>, cudaFuncAttributeMaxDynamicSharedMemorySize, GSMEM2);
    cudaFuncSetAttribute(flash_attn, cudaFuncAttributeMaxDynamicSharedMemorySize, FSMEM);

    // 0. all weight conversions in one fused kernel
    whalf_all_kernel<<<(TOT_F4 + 255) / 256, 256>>>(
        w_qkv, w1, w2, w_proj, wqkvH, w1H, w2H, wpH);

    // 1. conditioning -> modulation params (split-K)
    cond_part_kernel<<<dim3(24, 4, 8), 256>>>(c, w_mod, cpart);
    cond_reduce_kernel<<<dim3(24, 4), 256>>>(cpart, b_mod, cm);

    // 2. LN + modulate (msa) -> half
    ln_mod_h_kernel<<<ROWS, 256>>>(x, cm, 0, Hdim, xmh);

    // 3. qkv (half out, Q pre-scaled by 1/8)
    gemm_h<0><<<dim3(3 * Hdim / 128, ROWS / 128), 256, GSMEM2>>>(
        xmh, wqkvH, b_qkv, qkvh, ROWS, 3 * Hdim, Hdim, nullptr, nullptr);

    // 4. flash attention -> half attnout
    flash_attn<<<dim3(Ntok / 128, Bsz * NH), 256, FSMEM>>>(qkvh, attnh);

    // 5. x2 = (attnout @ w_proj + b_proj) * (1 + gate_msa)   (float out)
    gemm_h<2><<<dim3(Hdim / 128, ROWS / 128), 256, GSMEM2>>>(
        attnh, wpH, b_proj, x2, ROWS, Hdim, Hdim, cm + 2 * Hdim, nullptr);

    // 6. LN + modulate (mlp) -> half
    ln_mod_h_kernel<<<ROWS, 256>>>(x2, cm, 3 * Hdim, 4 * Hdim, xm2h);

    // 7. hid = gelu(xm2 @ w1 + b1)  (half out)
    gemm_h<1><<<dim3(DFF / 128, ROWS / 128), 256, GSMEM2>>>(
        xm2h, w1H, b1, hidh, ROWS, DFF, Hdim, nullptr, nullptr);

    // 8. out = x2 + gate_mlp * (hid @ w2 + b2)  (float out)
    gemm_h<3><<<dim3(Hdim / 128, ROWS / 128), 256, GSMEM2>>>(
        hidh, w2H, b2, out, ROWS, Hdim, DFF, cm + 5 * Hdim, x2);
}

// round 15
// speedup vs baseline: 7.6248x; 1.0174x over previous
#include <cuda_runtime.h>
#include <cuda_fp16.h>
#include <cstdint>
#include <math.h>

// ---------------------------------------------------------------------------
// DiT block: fp16 mma.sync GEMMs (128x128, BK=64, cp.async 3-stage, ldmatrix,
// 2 CTAs/SM) + cp.async flash attention with register-resident P.
// B=4, N=1024, H=1024, heads=16, d=64, D_FF=4096
// ---------------------------------------------------------------------------

#define Bsz 4
#define Ntok 1024
#define Hdim 1024
#define NH 16
#define HD 64
#define DFF 4096
#define ROWS (Bsz * Ntok)      // 4096
#define CM_STRIDE (6 * Hdim)   // 6144

// ------------------------- scratch (device globals) ------------------------
__device__ float    g_cm[Bsz * CM_STRIDE];
__device__ float    g_cpart[Bsz * 8 * CM_STRIDE];
__device__ __half   g_xmh[ROWS * Hdim];
__device__ __half   g_qkvh[ROWS * 3 * Hdim];
__device__ __half   g_attnh[ROWS * Hdim];
__device__ float    g_x2[ROWS * Hdim];
__device__ __half   g_xm2h[ROWS * Hdim];
__device__ __half   g_hidh[ROWS * DFF];
// plain half weights [K][N]
__device__ __half   g_wqkvH[Hdim * 3 * Hdim];
__device__ __half   g_w1H[Hdim * DFF];
__device__ __half   g_w2H[DFF * Hdim];
__device__ __half   g_wpH[Hdim * Hdim];

// ------------------------- helpers -----------------------------------------
__device__ __forceinline__ unsigned f2h2(float a, float b) {
    __half2 h = __floats2half2_rn(a, b);
    return *(unsigned*)&h;
}

__device__ __forceinline__ uint32_t smem_u32(const void* p) {
    uint32_t a;
    asm("{ .reg .u64 t; cvta.to.shared.u64 t, %1; cvt.u32.u64 %0, t; }"
        : "=r"(a) : "l"(p));
    return a;
}

__device__ __forceinline__ void mma_f16(float* d, const unsigned* a, const unsigned* b) {
    asm volatile(
        "mma.sync.aligned.m16n8k16.row.col.f32.f16.f16.f32 "
        "{%0,%1,%2,%3},{%4,%5,%6,%7},{%8,%9},{%0,%1,%2,%3};\n"
        : "+f"(d[0]), "+f"(d[1]), "+f"(d[2]), "+f"(d[3])
        : "r"(a[0]), "r"(a[1]), "r"(a[2]), "r"(a[3]), "r"(b[0]), "r"(b[1]));
}

#define LDSM4(r0, r1, r2, r3, a) \
    asm volatile("ldmatrix.sync.aligned.m8n8.x4.shared.b16 {%0,%1,%2,%3}, [%4];" \
                 : "=r"(r0), "=r"(r1), "=r"(r2), "=r"(r3) : "r"(a))
#define LDSM4T(r0, r1, r2, r3, a) \
    asm volatile("ldmatrix.sync.aligned.m8n8.x4.trans.shared.b16 {%0,%1,%2,%3}, [%4];" \
                 : "=r"(r0), "=r"(r1), "=r"(r2), "=r"(r3) : "r"(a))

#define CP_ASYNC16(saddr, gptr) \
    asm volatile("cp.async.cg.shared.global [%0], [%1], 16;" \
                 :: "r"(saddr), "l"(gptr) : "memory")
#define CP_COMMIT() asm volatile("cp.async.commit_group;" ::: "memory")
#define CP_WAIT1()  asm volatile("cp.async.wait_group 1;" ::: "memory")

// ------------------------- fused weight -> half ----------------------------
#define WQKV_F4 (3 * Hdim * Hdim / 4)
#define W1_F4   (Hdim * DFF / 4)
#define W2_F4   (DFF * Hdim / 4)
#define WP_F4   (Hdim * Hdim / 4)
#define TOT_F4  (WQKV_F4 + W1_F4 + W2_F4 + WP_F4)

__global__ void whalf_all_kernel(const float* __restrict__ wqkv,
                                 const float* __restrict__ w1,
                                 const float* __restrict__ w2,
                                 const float* __restrict__ wp,
                                 __half* __restrict__ oqkv,
                                 __half* __restrict__ o1,
                                 __half* __restrict__ o2,
                                 __half* __restrict__ op)
{
    size_t i = (size_t)blockIdx.x * 256 + threadIdx.x;
    if (i >= TOT_F4) return;
    const float* src;
    __half* dst;
    size_t off = i;
    if (off < WQKV_F4)                       { src = wqkv; dst = oqkv; }
    else if ((off -= WQKV_F4) < W1_F4)       { src = w1;   dst = o1;   }
    else if ((off -= W1_F4) < W2_F4)         { src = w2;   dst = o2;   }
    else { off -= W2_F4;                       src = wp;   dst = op;   }
    float4 v = *(const float4*)(src + off * 4);
    uint2 h = make_uint2(f2h2(v.x, v.y), f2h2(v.z, v.w));
    *(uint2*)(dst + off * 4) = h;
}

// ------------------------- cond modulation (split-K) ------------------------
__global__ void cond_part_kernel(const float* __restrict__ c,
                                 const float* __restrict__ w,
                                 float* __restrict__ part)
{
    int j = blockIdx.x * 256 + threadIdx.x;
    int b = blockIdx.y, kc = blockIdx.z;
    __shared__ float sc[128];
    if (threadIdx.x < 128) {
        float t = c[b * Hdim + kc * 128 + threadIdx.x];
        sc[threadIdx.x] = t / (1.0f + expf(-t));
    }
    __syncthreads();
    float acc = 0.0f;
    const float* wp = w + (size_t)(kc * 128) * CM_STRIDE + j;
    #pragma unroll 8
    for (int k = 0; k < 128; k++)
        acc += sc[k] * wp[(size_t)k * CM_STRIDE];
    part[(size_t)(b * 8 + kc) * CM_STRIDE + j] = acc;
}

__global__ void cond_reduce_kernel(const float* __restrict__ part,
                                   const float* __restrict__ bmod,
                                   float* __restrict__ cm)
{
    int j = blockIdx.x * 256 + threadIdx.x;
    int b = blockIdx.y;
    float acc = bmod[j];
    #pragma unroll
    for (int s = 0; s < 8; s++)
        acc += part[(size_t)(b * 8 + s) * CM_STRIDE + j];
    cm[b * CM_STRIDE + j] = acc;
}

// ------------------------- LayerNorm + modulate -> half ---------------------
__global__ void ln_mod_h_kernel(const float* __restrict__ x,
                                const float* __restrict__ cm,
                                int shiftOff, int scaleOff,
                                __half* __restrict__ out)
{
    int row = blockIdx.x;
    int b = row >> 10;
    const float* xr = x + (size_t)row * Hdim;
    int tid = threadIdx.x;
    int col4 = tid * 4;
    float4 t = *(const float4*)(xr + col4);
    float s  = t.x + t.y + t.z + t.w;
    float sq = t.x * t.x + t.y * t.y + t.z * t.z + t.w * t.w;
    #pragma unroll
    for (int o = 16; o > 0; o >>= 1) {
        s  += __shfl_down_sync(0xffffffffu, s,  o);
        sq += __shfl_down_sync(0xffffffffu, sq, o);
    }
    __shared__ float red[20];
    int warp = tid >> 5, lane = tid & 31;
    if (lane == 0) { red[warp] = s; red[warp + 8] = sq; }
    __syncthreads();
    if (tid == 0) {
        float S = 0.0f, SQ = 0.0f;
        #pragma unroll
        for (int w = 0; w < 8; w++) { S += red[w]; SQ += red[w + 8]; }
        float mu = S * (1.0f / Hdim);
        float var = SQ * (1.0f / Hdim) - mu * mu;
        red[16] = mu;
        red[17] = rsqrtf(var + 1e-5f);
    }
    __syncthreads();
    float mu = red[16], inv = red[17];
    const float* sh = cm + b * CM_STRIDE + shiftOff;
    const float* sc = cm + b * CM_STRIDE + scaleOff;
    float4 shv = *(const float4*)(sh + col4);
    float4 scv = *(const float4*)(sc + col4);
    float v0 = (t.x - mu) * inv * (1.0f + scv.x) + shv.x;
    float v1 = (t.y - mu) * inv * (1.0f + scv.y) + shv.y;
    float v2 = (t.z - mu) * inv * (1.0f + scv.z) + shv.z;
    float v3 = (t.w - mu) * inv * (1.0f + scv.w) + shv.w;
    uint2 o2 = make_uint2(f2h2(v0, v1), f2h2(v2, v3));
    *(uint2*)&out[(size_t)row * Hdim + col4] = o2;
}

// ------------------------- fp16 GEMM: 128x128, BK=64, 3-stage, 2 CTAs/SM ----
#define AW 36
#define BW 68
#define STAGE_U32 (128 * AW + 64 * BW)    // 8960
#define GSMEM2 (3 * STAGE_U32 * 4)        // 107520 bytes

template<int EPI>
__global__ __launch_bounds__(256, 2)
void gemm_h(const __half* __restrict__ A, const __half* __restrict__ Bh,
            const float* __restrict__ bias, void* __restrict__ Cout,
            int M, int N, int K,
            const float* __restrict__ gate, const float* __restrict__ resid)
{
    extern __shared__ unsigned sm[];
    int tid = threadIdx.x;
    int warp = tid >> 5, lane = tid & 31;
    int warpM = warp >> 2, warpN = warp & 3;
    int g = lane >> 2, r = lane & 3;
    int rowBase = blockIdx.y * 128, colBase = blockIdx.x * 128;
    int kts = K / 64;

    uint32_t smBase = smem_u32(sm);

    auto loadStage = [&](int stage, int kt) {
        uint32_t sA = smBase + stage * STAGE_U32 * 4;
        uint32_t sB = sA + 128 * AW * 4;
        const __half* Ag = A + (size_t)rowBase * K + kt * 64;
        const __half* Bg = Bh + (size_t)(kt * 64) * N + colBase;
        #pragma unroll
        for (int i = 0; i < 4; i++) {
            int j = tid + i * 256;
            int row = j >> 3, seg = j & 7;
            CP_ASYNC16(sA + row * 144 + seg * 16, Ag + (size_t)row * K + seg * 8);
        }
        #pragma unroll
        for (int i = 0; i < 4; i++) {
            int j = tid + i * 256;
            int row = j >> 4, seg = j & 15;
            CP_ASYNC16(sB + row * 272 + seg * 16, Bg + (size_t)row * N + seg * 8);
        }
    };

    float acc[4][4][4] = {};

    loadStage(0, 0); CP_COMMIT();
    loadStage(1, 1); CP_COMMIT();

    int lrow = lane & 15, lhi = lane >> 4;

    for (int kt = 0; kt < kts; kt++) {
        CP_WAIT1();
        __syncthreads();
        if (kt + 2 < kts) loadStage((kt + 2) % 3, kt + 2);
        CP_COMMIT();

        uint32_t sA = smBase + (kt % 3) * STAGE_U32 * 4;
        uint32_t sB = sA + 128 * AW * 4;
        #pragma unroll
        for (int ks = 0; ks < 4; ks++) {
            unsigned af[4][4], bf[4][2];
            #pragma unroll
            for (int mi = 0; mi < 4; mi++) {
                uint32_t a = sA + ((warpM * 64 + mi * 16 + lrow) * AW
                                   + ks * 8 + lhi * 4) * 4;
                LDSM4(af[mi][0], af[mi][1], af[mi][2], af[mi][3], a);
            }
            #pragma unroll
            for (int p = 0; p < 2; p++) {
                uint32_t bAddr = sB + ((ks * 16 + lrow) * BW
                                       + warpN * 16 + p * 8 + lhi * 4) * 4;
                LDSM4T(bf[2 * p][0], bf[2 * p][1], bf[2 * p + 1][0], bf[2 * p + 1][1], bAddr);
            }
            #pragma unroll
            for (int mi = 0; mi < 4; mi++)
                #pragma unroll
                for (int nj = 0; nj < 4; nj++)
                    mma_f16(acc[mi][nj], af[mi], bf[nj]);
        }
    }

    #pragma unroll
    for (int mi = 0; mi < 4; mi++) {
        #pragma unroll
        for (int rr = 0; rr < 2; rr++) {
            int row = rowBase + warpM * 64 + mi * 16 + g + rr * 8;
            int b = row >> 10;
            #pragma unroll
            for (int nj = 0; nj < 4; nj++) {
                int col = colBase + warpN * 32 + nj * 8 + r * 2;
                float v0 = acc[mi][nj][rr * 2 + 0] + __ldg(&bias[col]);
                float v1 = acc[mi][nj][rr * 2 + 1] + __ldg(&bias[col + 1]);
                if (EPI == 0) {
                    float sc = (col < Hdim) ? 0.125f : 1.0f;
                    __half* Ch = (__half*)Cout;
                    *(unsigned*)&Ch[(size_t)row * N + col] = f2h2(v0 * sc, v1 * sc);
                } else if (EPI == 1) {
                    v0 = 0.5f * v0 * (1.0f + erff(v0 * 0.70710678118654752f));
                    v1 = 0.5f * v1 * (1.0f + erff(v1 * 0.70710678118654752f));
                    __half* Ch = (__half*)Cout;
                    *(unsigned*)&Ch[(size_t)row * N + col] = f2h2(v0, v1);
                } else if (EPI == 2) {
                    v0 *= (1.0f + __ldg(&gate[b * CM_STRIDE + col]));
                    v1 *= (1.0f + __ldg(&gate[b * CM_STRIDE + col + 1]));
                    *(float2*)&((float*)Cout)[(size_t)row * N + col] = make_float2(v0, v1);
                } else {
                    v0 = resid[(size_t)row * N + col]     + __ldg(&gate[b * CM_STRIDE + col])     * v0;
                    v1 = resid[(size_t)row * N + col + 1] + __ldg(&gate[b * CM_STRIDE + col + 1]) * v1;
                    *(float2*)&((float*)Cout)[(size_t)row * N + col] = make_float2(v0, v1);
                }
            }
        }
    }
}

// ------------------------- flash attention (reg-resident P) -----------------
// K, V tiles natural [key][d]: 64 rows x 128B data + 16B pad (36 words).
// K fragments: scalar LDS (pairs along d). V fragments: LDSM4T.
// P never touches smem: S-mma output fragments are repacked (f2h2) directly
// into the A-fragment layout of the PV mma (mapping verified vs smem path).
#define PSTR2 36
#define KVW 36
#define FPS_U32 (128 * PSTR2)          // Q staging only
#define FKV_U32 (64 * KVW)
#define FSMEM ((FPS_U32 + 6 * FKV_U32) * 4)   // 73728 bytes

__global__ __launch_bounds__(256, 2)
void flash_attn(const __half* __restrict__ qkv, __half* __restrict__ out)
{
    extern __shared__ unsigned fsm[];
    unsigned* Ps2 = fsm;
    uint32_t psBase = smem_u32(fsm);
    uint32_t kBase = psBase + FPS_U32 * 4;
    uint32_t vBase = kBase + 3 * FKV_U32 * 4;

    int tid = threadIdx.x;
    int warp = tid >> 5, lane = tid & 31;
    int g = lane >> 2, r = lane & 3;
    int lrow = lane & 15, lhi = lane >> 4;
    int bh = blockIdx.y;
    int b = bh >> 4, h = bh & 15;
    int q0 = blockIdx.x * 128;

    const int NIT = Ntok / 64;

    auto loadKV = [&](int s, int n0) {
        uint32_t kS = kBase + s * FKV_U32 * 4;
        uint32_t vS = vBase + s * FKV_U32 * 4;
        #pragma unroll
        for (int i = 0; i < 2; i++) {
            int j = tid + i * 256;
            int key = j >> 3, seg = j & 7;
            const __half* kp = qkv + (size_t)(b * Ntok + n0 + key) * 3 * Hdim
                               + Hdim + h * HD + seg * 8;
            CP_ASYNC16(kS + key * 144 + seg * 16, kp);
            CP_ASYNC16(vS + key * 144 + seg * 16, kp + Hdim);
        }
    };

    loadKV(0, 0); CP_COMMIT();
    loadKV(1, 64); CP_COMMIT();

    #pragma unroll
    for (int i = 0; i < 4; i++) {
        int j = tid + i * 256;
        int row = j >> 3, d8 = (j & 7) * 8;
        uint4 v = *(const uint4*)(qkv + (size_t)(b * Ntok + q0 + row) * 3 * Hdim
                                  + h * HD + d8);
        *(uint4*)&Ps2[row * PSTR2 + (j & 7) * 4] = v;
    }
    __syncthreads();

    int qrow = warp * 16 + g;
    unsigned qf[4][4];
    #pragma unroll
    for (int ks = 0; ks < 4; ks++) {
        qf[ks][0] = Ps2[qrow * PSTR2 + ks * 8 + r];
        qf[ks][1] = Ps2[(qrow + 8) * PSTR2 + ks * 8 + r];
        qf[ks][2] = Ps2[qrow * PSTR2 + ks * 8 + r + 4];
        qf[ks][3] = Ps2[(qrow + 8) * PSTR2 + ks * 8 + r + 4];
    }

    float oacc[8][4] = {};
    float m0 = -1e30f, m1 = -1e30f, l0 = 0.0f, l1 = 0.0f;

    for (int it = 0; it < NIT; it++) {
        int s = it % 3;
        CP_WAIT1();
        __syncthreads();
        if (it + 2 < NIT) loadKV((it + 2) % 3, (it + 2) * 64);
        CP_COMMIT();

        unsigned* Ks2 = fsm + FPS_U32 + s * FKV_U32;
        uint32_t vS = vBase + s * FKV_U32 * 4;

        // ---- S = Q K^T ----
        float sacc[8][4] = {};
        #pragma unroll
        for (int ks = 0; ks < 4; ks++) {
            #pragma unroll
            for (int nj = 0; nj < 8; nj++) {
                int key = nj * 8 + g;
                unsigned bf[2];
                bf[0] = Ks2[key * KVW + ks * 8 + r];
                bf[1] = Ks2[key * KVW + ks * 8 + r + 4];
                mma_f16(sacc[nj], qf[ks], bf);
            }
        }

        // ---- online softmax, pack P directly into mma A-fragments ----
        float mc0 = -1e30f, mc1 = -1e30f;
        #pragma unroll
        for (int nj = 0; nj < 8; nj++) {
            mc0 = fmaxf(mc0, fmaxf(sacc[nj][0], sacc[nj][1]));
            mc1 = fmaxf(mc1, fmaxf(sacc[nj][2], sacc[nj][3]));
        }
        mc0 = fmaxf(mc0, __shfl_xor_sync(0xffffffffu, mc0, 1));
        mc0 = fmaxf(mc0, __shfl_xor_sync(0xffffffffu, mc0, 2));
        mc1 = fmaxf(mc1, __shfl_xor_sync(0xffffffffu, mc1, 1));
        mc1 = fmaxf(mc1, __shfl_xor_sync(0xffffffffu, mc1, 2));
        float mn0 = fmaxf(m0, mc0), mn1 = fmaxf(m1, mc1);
        float a0 = __expf(m0 - mn0), a1 = __expf(m1 - mn1);
        float rs0 = 0.0f, rs1 = 0.0f;
        unsigned ph[8][2];   // ph[nj][0]: rows g cols 8nj+2r(+1); [1]: rows g+8
        #pragma unroll
        for (int nj = 0; nj < 8; nj++) {
            float p0 = __expf(sacc[nj][0] - mn0);
            float p1 = __expf(sacc[nj][1] - mn0);
            float p2 = __expf(sacc[nj][2] - mn1);
            float p3 = __expf(sacc[nj][3] - mn1);
            rs0 += p0 + p1; rs1 += p2 + p3;
            ph[nj][0] = f2h2(p0, p1);
            ph[nj][1] = f2h2(p2, p3);
        }
        rs0 += __shfl_xor_sync(0xffffffffu, rs0, 1);
        rs0 += __shfl_xor_sync(0xffffffffu, rs0, 2);
        rs1 += __shfl_xor_sync(0xffffffffu, rs1, 1);
        rs1 += __shfl_xor_sync(0xffffffffu, rs1, 2);
        l0 = l0 * a0 + rs0;
        l1 = l1 * a1 + rs1;
        m0 = mn0; m1 = mn1;
        #pragma unroll
        for (int nj = 0; nj < 8; nj++) {
            oacc[nj][0] *= a0; oacc[nj][1] *= a0;
            oacc[nj][2] *= a1; oacc[nj][3] *= a1;
        }

        // ---- O += P V  (P from registers, V via LDSM4T) ----
        #pragma unroll
        for (int ks = 0; ks < 4; ks++) {
            unsigned af[4], bf[8][2];
            af[0] = ph[2 * ks][0];
            af[1] = ph[2 * ks][1];
            af[2] = ph[2 * ks + 1][0];
            af[3] = ph[2 * ks + 1][1];
            #pragma unroll
            for (int p = 0; p < 4; p++) {
                uint32_t vAddr = vS + ((ks * 16 + lrow) * KVW + p * 8 + lhi * 4) * 4;
                LDSM4T(bf[2 * p][0], bf[2 * p][1], bf[2 * p + 1][0], bf[2 * p + 1][1], vAddr);
            }
            #pragma unroll
            for (int nj = 0; nj < 8; nj++)
                mma_f16(oacc[nj], af, bf[nj]);
        }
    }

    float i0 = 1.0f / l0, i1 = 1.0f / l1;
    #pragma unroll
    for (int nj = 0; nj < 8; nj++) {
        int col = h * HD + nj * 8 + 2 * r;
        *(unsigned*)&out[(size_t)(b * Ntok + q0 + qrow) * Hdim + col]
            = f2h2(oacc[nj][0] * i0, oacc[nj][1] * i0);
        *(unsigned*)&out[(size_t)(b * Ntok + q0 + qrow + 8) * Hdim + col]
            = f2h2(oacc[nj][2] * i1, oacc[nj][3] * i1);
    }
}

// ------------------------- launch ------------------------------------------
extern "C" void kernel_launch(void* const* d_in, const int* in_sizes, int n_in,
                              void* d_out, int out_size)
{
    const float* x      = (const float*)d_in[0];
    const float* c      = (const float*)d_in[1];
    const float* w_mod  = (const float*)d_in[2];
    const float* b_mod  = (const float*)d_in[3];
    const float* w_qkv  = (const float*)d_in[4];
    const float* b_qkv  = (const float*)d_in[5];
    const float* w_proj = (const float*)d_in[6];
    const float* b_proj = (const float*)d_in[7];
    const float* w1     = (const float*)d_in[8];
    const float* b1     = (const float*)d_in[9];
    const float* w2     = (const float*)d_in[10];
    const float* b2     = (const float*)d_in[11];
    float* out = (float*)d_out;

    float *cm, *cpart, *x2;
    __half *xmh, *qkvh, *attnh, *xm2h, *hidh, *wqkvH, *w1H, *w2H, *wpH;
    cudaGetSymbolAddress((void**)&cm,    g_cm);
    cudaGetSymbolAddress((void**)&cpart, g_cpart);
    cudaGetSymbolAddress((void**)&xmh,   g_xmh);
    cudaGetSymbolAddress((void**)&qkvh,  g_qkvh);
    cudaGetSymbolAddress((void**)&attnh, g_attnh);
    cudaGetSymbolAddress((void**)&x2,    g_x2);
    cudaGetSymbolAddress((void**)&xm2h,  g_xm2h);
    cudaGetSymbolAddress((void**)&hidh,  g_hidh);
    cudaGetSymbolAddress((void**)&wqkvH, g_wqkvH);
    cudaGetSymbolAddress((void**)&w1H,   g_w1H);
    cudaGetSymbolAddress((void**)&w2H,   g_w2H);
    cudaGetSymbolAddress((void**)&wpH,   g_wpH);

    cudaFuncSetAttribute(gemm_h<0>, cudaFuncAttributeMaxDynamicSharedMemorySize, GSMEM2);
    cudaFuncSetAttribute(gemm_h<1>, cudaFuncAttributeMaxDynamicSharedMemorySize, GSMEM2);
    cudaFuncSetAttribute(gemm_h<2>, cudaFuncAttributeMaxDynamicSharedMemorySize, GSMEM2);
    cudaFuncSetAttribute(gemm_h<3>, cudaFuncAttributeMaxDynamicSharedMemorySize, GSMEM2);
    cudaFuncSetAttribute(flash_attn, cudaFuncAttributeMaxDynamicSharedMemorySize, FSMEM);

    // 0. all weight conversions in one fused kernel
    whalf_all_kernel<<<(TOT_F4 + 255) / 256, 256>>>(
        w_qkv, w1, w2, w_proj, wqkvH, w1H, w2H, wpH);

    // 1. conditioning -> modulation params (split-K)
    cond_part_kernel<<<dim3(24, 4, 8), 256>>>(c, w_mod, cpart);
    cond_reduce_kernel<<<dim3(24, 4), 256>>>(cpart, b_mod, cm);

    // 2. LN + modulate (msa) -> half
    ln_mod_h_kernel<<<ROWS, 256>>>(x, cm, 0, Hdim, xmh);

    // 3. qkv (half out, Q pre-scaled by 1/8)
    gemm_h<0><<<dim3(3 * Hdim / 128, ROWS / 128), 256, GSMEM2>>>(
        xmh, wqkvH, b_qkv, qkvh, ROWS, 3 * Hdim, Hdim, nullptr, nullptr);

    // 4. flash attention -> half attnout
    flash_attn<<<dim3(Ntok / 128, Bsz * NH), 256, FSMEM>>>(qkvh, attnh);

    // 5. x2 = (attnout @ w_proj + b_proj) * (1 + gate_msa)   (float out)
    gemm_h<2><<<dim3(Hdim / 128, ROWS / 128), 256, GSMEM2>>>(
        attnh, wpH, b_proj, x2, ROWS, Hdim, Hdim, cm + 2 * Hdim, nullptr);

    // 6. LN + modulate (mlp) -> half
    ln_mod_h_kernel<<<ROWS, 256>>>(x2, cm, 3 * Hdim, 4 * Hdim, xm2h);

    // 7. hid = gelu(xm2 @ w1 + b1)  (half out)
    gemm_h<1><<<dim3(DFF / 128, ROWS / 128), 256, GSMEM2>>>(
        xm2h, w1H, b1, hidh, ROWS, DFF, Hdim, nullptr, nullptr);

    // 8. out = x2 + gate_mlp * (hid @ w2 + b2)  (float out)
    gemm_h<3><<<dim3(Hdim / 128, ROWS / 128), 256, GSMEM2>>>(
        hidh, w2H, b2, out, ROWS, Hdim, DFF, cm + 5 * Hdim, x2);
}

// round 16
// speedup vs baseline: 7.6969x; 1.0095x over previous
#include <cuda_runtime.h>
#include <cuda_fp16.h>
#include <cstdint>
#include <math.h>

// ---------------------------------------------------------------------------
// DiT block: fp16 mma.sync GEMMs (128x128, BK=64, cp.async 3-stage, ldmatrix,
// 2 CTAs/SM) + cp.async flash attention (register-resident P, LDSM K/V).
// B=4, N=1024, H=1024, heads=16, d=64, D_FF=4096
// ---------------------------------------------------------------------------

#define Bsz 4
#define Ntok 1024
#define Hdim 1024
#define NH 16
#define HD 64
#define DFF 4096
#define ROWS (Bsz * Ntok)      // 4096
#define CM_STRIDE (6 * Hdim)   // 6144

// ------------------------- scratch (device globals) ------------------------
__device__ float    g_cm[Bsz * CM_STRIDE];
__device__ float    g_cpart[Bsz * 8 * CM_STRIDE];
__device__ __half   g_xmh[ROWS * Hdim];
__device__ __half   g_qkvh[ROWS * 3 * Hdim];
__device__ __half   g_attnh[ROWS * Hdim];
__device__ float    g_x2[ROWS * Hdim];
__device__ __half   g_xm2h[ROWS * Hdim];
__device__ __half   g_hidh[ROWS * DFF];
// plain half weights [K][N]
__device__ __half   g_wqkvH[Hdim * 3 * Hdim];
__device__ __half   g_w1H[Hdim * DFF];
__device__ __half   g_w2H[DFF * Hdim];
__device__ __half   g_wpH[Hdim * Hdim];

// ------------------------- helpers -----------------------------------------
__device__ __forceinline__ unsigned f2h2(float a, float b) {
    __half2 h = __floats2half2_rn(a, b);
    return *(unsigned*)&h;
}

__device__ __forceinline__ uint32_t smem_u32(const void* p) {
    uint32_t a;
    asm("{ .reg .u64 t; cvta.to.shared.u64 t, %1; cvt.u32.u64 %0, t; }"
        : "=r"(a) : "l"(p));
    return a;
}

__device__ __forceinline__ void mma_f16(float* d, const unsigned* a, const unsigned* b) {
    asm volatile(
        "mma.sync.aligned.m16n8k16.row.col.f32.f16.f16.f32 "
        "{%0,%1,%2,%3},{%4,%5,%6,%7},{%8,%9},{%0,%1,%2,%3};\n"
        : "+f"(d[0]), "+f"(d[1]), "+f"(d[2]), "+f"(d[3])
        : "r"(a[0]), "r"(a[1]), "r"(a[2]), "r"(a[3]), "r"(b[0]), "r"(b[1]));
}

#define LDSM4(r0, r1, r2, r3, a) \
    asm volatile("ldmatrix.sync.aligned.m8n8.x4.shared.b16 {%0,%1,%2,%3}, [%4];" \
                 : "=r"(r0), "=r"(r1), "=r"(r2), "=r"(r3) : "r"(a))
#define LDSM4T(r0, r1, r2, r3, a) \
    asm volatile("ldmatrix.sync.aligned.m8n8.x4.trans.shared.b16 {%0,%1,%2,%3}, [%4];" \
                 : "=r"(r0), "=r"(r1), "=r"(r2), "=r"(r3) : "r"(a))

#define CP_ASYNC16(saddr, gptr) \
    asm volatile("cp.async.cg.shared.global [%0], [%1], 16;" \
                 :: "r"(saddr), "l"(gptr) : "memory")
#define CP_COMMIT() asm volatile("cp.async.commit_group;" ::: "memory")
#define CP_WAIT1()  asm volatile("cp.async.wait_group 1;" ::: "memory")

// ------------------------- fused weight -> half (MLP=2) ---------------------
#define WQKV_F4 (3 * Hdim * Hdim / 4)
#define W1_F4   (Hdim * DFF / 4)
#define W2_F4   (DFF * Hdim / 4)
#define WP_F4   (Hdim * Hdim / 4)
#define TOT_F4  (WQKV_F4 + W1_F4 + W2_F4 + WP_F4)
#define HALF_F4 (TOT_F4 / 2)

__device__ __forceinline__ void whalf_one(size_t i,
                                          const float* wqkv, const float* w1,
                                          const float* w2, const float* wp,
                                          __half* oqkv, __half* o1,
                                          __half* o2, __half* op)
{
    const float* src;
    __half* dst;
    size_t off = i;
    if (off < WQKV_F4)                       { src = wqkv; dst = oqkv; }
    else if ((off -= WQKV_F4) < W1_F4)       { src = w1;   dst = o1;   }
    else if ((off -= W1_F4) < W2_F4)         { src = w2;   dst = o2;   }
    else { off -= W2_F4;                       src = wp;   dst = op;   }
    float4 v = *(const float4*)(src + off * 4);
    uint2 h = make_uint2(f2h2(v.x, v.y), f2h2(v.z, v.w));
    *(uint2*)(dst + off * 4) = h;
}

__global__ void whalf_all_kernel(const float* __restrict__ wqkv,
                                 const float* __restrict__ w1,
                                 const float* __restrict__ w2,
                                 const float* __restrict__ wp,
                                 __half* __restrict__ oqkv,
                                 __half* __restrict__ o1,
                                 __half* __restrict__ o2,
                                 __half* __restrict__ op)
{
    size_t i = (size_t)blockIdx.x * 256 + threadIdx.x;
    whalf_one(i, wqkv, w1, w2, wp, oqkv, o1, o2, op);
    whalf_one(i + HALF_F4, wqkv, w1, w2, wp, oqkv, o1, o2, op);
}

// ------------------------- cond modulation (split-K) ------------------------
__global__ void cond_part_kernel(const float* __restrict__ c,
                                 const float* __restrict__ w,
                                 float* __restrict__ part)
{
    int j = blockIdx.x * 256 + threadIdx.x;
    int b = blockIdx.y, kc = blockIdx.z;
    __shared__ float sc[128];
    if (threadIdx.x < 128) {
        float t = c[b * Hdim + kc * 128 + threadIdx.x];
        sc[threadIdx.x] = t / (1.0f + expf(-t));
    }
    __syncthreads();
    float acc = 0.0f;
    const float* wp = w + (size_t)(kc * 128) * CM_STRIDE + j;
    #pragma unroll 8
    for (int k = 0; k < 128; k++)
        acc += sc[k] * wp[(size_t)k * CM_STRIDE];
    part[(size_t)(b * 8 + kc) * CM_STRIDE + j] = acc;
}

__global__ void cond_reduce_kernel(const float* __restrict__ part,
                                   const float* __restrict__ bmod,
                                   float* __restrict__ cm)
{
    int j = blockIdx.x * 256 + threadIdx.x;
    int b = blockIdx.y;
    float acc = bmod[j];
    #pragma unroll
    for (int s = 0; s < 8; s++)
        acc += part[(size_t)(b * 8 + s) * CM_STRIDE + j];
    cm[b * CM_STRIDE + j] = acc;
}

// ------------------------- LayerNorm + modulate -> half (2 rows/CTA) --------
__global__ void ln_mod_h_kernel(const float* __restrict__ x,
                                const float* __restrict__ cm,
                                int shiftOff, int scaleOff,
                                __half* __restrict__ out)
{
    int tid = threadIdx.x;
    int sub = tid >> 7;           // 0/1: which row of the pair
    int t = tid & 127;
    int row = blockIdx.x * 2 + sub;
    int b = row >> 10;
    const float* xr = x + (size_t)row * Hdim;
    int col8 = t * 8;

    float4 u = *(const float4*)(xr + col8);
    float4 v = *(const float4*)(xr + col8 + 4);
    float s  = u.x + u.y + u.z + u.w + v.x + v.y + v.z + v.w;
    float sq = u.x * u.x + u.y * u.y + u.z * u.z + u.w * u.w
             + v.x * v.x + v.y * v.y + v.z * v.z + v.w * v.w;
    #pragma unroll
    for (int o = 16; o > 0; o >>= 1) {
        s  += __shfl_down_sync(0xffffffffu, s,  o);
        sq += __shfl_down_sync(0xffffffffu, sq, o);
    }
    __shared__ float red[2][10];
    int warp = tid >> 5, lane = tid & 31;
    int w4 = warp & 3;
    if (lane == 0) { red[sub][w4] = s; red[sub][4 + w4] = sq; }
    __syncthreads();
    if (t == 0) {
        float S = red[sub][0] + red[sub][1] + red[sub][2] + red[sub][3];
        float SQ = red[sub][4] + red[sub][5] + red[sub][6] + red[sub][7];
        float mu = S * (1.0f / Hdim);
        float var = SQ * (1.0f / Hdim) - mu * mu;
        red[sub][8] = mu;
        red[sub][9] = rsqrtf(var + 1e-5f);
    }
    __syncthreads();
    float mu = red[sub][8], inv = red[sub][9];

    const float* sh = cm + b * CM_STRIDE + shiftOff;
    const float* sc = cm + b * CM_STRIDE + scaleOff;
    float4 shu = *(const float4*)(sh + col8);
    float4 shv = *(const float4*)(sh + col8 + 4);
    float4 scu = *(const float4*)(sc + col8);
    float4 scv = *(const float4*)(sc + col8 + 4);
    unsigned o4[4];
    o4[0] = f2h2((u.x - mu) * inv * (1.0f + scu.x) + shu.x,
                 (u.y - mu) * inv * (1.0f + scu.y) + shu.y);
    o4[1] = f2h2((u.z - mu) * inv * (1.0f + scu.z) + shu.z,
                 (u.w - mu) * inv * (1.0f + scu.w) + shu.w);
    o4[2] = f2h2((v.x - mu) * inv * (1.0f + scv.x) + shv.x,
                 (v.y - mu) * inv * (1.0f + scv.y) + shv.y);
    o4[3] = f2h2((v.z - mu) * inv * (1.0f + scv.z) + shv.z,
                 (v.w - mu) * inv * (1.0f + scv.w) + shv.w);
    *(uint4*)&out[(size_t)row * Hdim + col8] = *(uint4*)o4;
}

// ------------------------- fp16 GEMM: 128x128, BK=64, 3-stage, 2 CTAs/SM ----
#define AW 36
#define BW 68
#define STAGE_U32 (128 * AW + 64 * BW)    // 8960
#define GSMEM2 (3 * STAGE_U32 * 4)        // 107520 bytes

template<int EPI>
__global__ __launch_bounds__(256, 2)
void gemm_h(const __half* __restrict__ A, const __half* __restrict__ Bh,
            const float* __restrict__ bias, void* __restrict__ Cout,
            int M, int N, int K,
            const float* __restrict__ gate, const float* __restrict__ resid)
{
    extern __shared__ unsigned sm[];
    int tid = threadIdx.x;
    int warp = tid >> 5, lane = tid & 31;
    int warpM = warp >> 2, warpN = warp & 3;
    int g = lane >> 2, r = lane & 3;
    int rowBase = blockIdx.y * 128, colBase = blockIdx.x * 128;
    int kts = K / 64;

    uint32_t smBase = smem_u32(sm);

    auto loadStage = [&](int stage, int kt) {
        uint32_t sA = smBase + stage * STAGE_U32 * 4;
        uint32_t sB = sA + 128 * AW * 4;
        const __half* Ag = A + (size_t)rowBase * K + kt * 64;
        const __half* Bg = Bh + (size_t)(kt * 64) * N + colBase;
        #pragma unroll
        for (int i = 0; i < 4; i++) {
            int j = tid + i * 256;
            int row = j >> 3, seg = j & 7;
            CP_ASYNC16(sA + row * 144 + seg * 16, Ag + (size_t)row * K + seg * 8);
        }
        #pragma unroll
        for (int i = 0; i < 4; i++) {
            int j = tid + i * 256;
            int row = j >> 4, seg = j & 15;
            CP_ASYNC16(sB + row * 272 + seg * 16, Bg + (size_t)row * N + seg * 8);
        }
    };

    float acc[4][4][4] = {};

    loadStage(0, 0); CP_COMMIT();
    loadStage(1, 1); CP_COMMIT();

    int lrow = lane & 15, lhi = lane >> 4;

    for (int kt = 0; kt < kts; kt++) {
        CP_WAIT1();
        __syncthreads();
        if (kt + 2 < kts) loadStage((kt + 2) % 3, kt + 2);
        CP_COMMIT();

        uint32_t sA = smBase + (kt % 3) * STAGE_U32 * 4;
        uint32_t sB = sA + 128 * AW * 4;
        #pragma unroll
        for (int ks = 0; ks < 4; ks++) {
            unsigned af[4][4], bf[4][2];
            #pragma unroll
            for (int mi = 0; mi < 4; mi++) {
                uint32_t a = sA + ((warpM * 64 + mi * 16 + lrow) * AW
                                   + ks * 8 + lhi * 4) * 4;
                LDSM4(af[mi][0], af[mi][1], af[mi][2], af[mi][3], a);
            }
            #pragma unroll
            for (int p = 0; p < 2; p++) {
                uint32_t bAddr = sB + ((ks * 16 + lrow) * BW
                                       + warpN * 16 + p * 8 + lhi * 4) * 4;
                LDSM4T(bf[2 * p][0], bf[2 * p][1], bf[2 * p + 1][0], bf[2 * p + 1][1], bAddr);
            }
            #pragma unroll
            for (int mi = 0; mi < 4; mi++)
                #pragma unroll
                for (int nj = 0; nj < 4; nj++)
                    mma_f16(acc[mi][nj], af[mi], bf[nj]);
        }
    }

    #pragma unroll
    for (int mi = 0; mi < 4; mi++) {
        #pragma unroll
        for (int rr = 0; rr < 2; rr++) {
            int row = rowBase + warpM * 64 + mi * 16 + g + rr * 8;
            int b = row >> 10;
            #pragma unroll
            for (int nj = 0; nj < 4; nj++) {
                int col = colBase + warpN * 32 + nj * 8 + r * 2;
                float v0 = acc[mi][nj][rr * 2 + 0] + __ldg(&bias[col]);
                float v1 = acc[mi][nj][rr * 2 + 1] + __ldg(&bias[col + 1]);
                if (EPI == 0) {
                    float sc = (col < Hdim) ? 0.125f : 1.0f;
                    __half* Ch = (__half*)Cout;
                    *(unsigned*)&Ch[(size_t)row * N + col] = f2h2(v0 * sc, v1 * sc);
                } else if (EPI == 1) {
                    v0 = 0.5f * v0 * (1.0f + erff(v0 * 0.70710678118654752f));
                    v1 = 0.5f * v1 * (1.0f + erff(v1 * 0.70710678118654752f));
                    __half* Ch = (__half*)Cout;
                    *(unsigned*)&Ch[(size_t)row * N + col] = f2h2(v0, v1);
                } else if (EPI == 2) {
                    v0 *= (1.0f + __ldg(&gate[b * CM_STRIDE + col]));
                    v1 *= (1.0f + __ldg(&gate[b * CM_STRIDE + col + 1]));
                    *(float2*)&((float*)Cout)[(size_t)row * N + col] = make_float2(v0, v1);
                } else {
                    v0 = resid[(size_t)row * N + col]     + __ldg(&gate[b * CM_STRIDE + col])     * v0;
                    v1 = resid[(size_t)row * N + col + 1] + __ldg(&gate[b * CM_STRIDE + col + 1]) * v1;
                    *(float2*)&((float*)Cout)[(size_t)row * N + col] = make_float2(v0, v1);
                }
            }
        }
    }
}

// ------------------------- flash attention (reg P, LDSM K/V) ----------------
#define PSTR2 36
#define KVW 36
#define FPS_U32 (128 * PSTR2)
#define FKV_U32 (64 * KVW)
#define FSMEM ((FPS_U32 + 6 * FKV_U32) * 4)   // 73728 bytes

__global__ __launch_bounds__(256, 2)
void flash_attn(const __half* __restrict__ qkv, __half* __restrict__ out)
{
    extern __shared__ unsigned fsm[];
    unsigned* Ps2 = fsm;
    uint32_t psBase = smem_u32(fsm);
    uint32_t kBase = psBase + FPS_U32 * 4;
    uint32_t vBase = kBase + 3 * FKV_U32 * 4;

    int tid = threadIdx.x;
    int warp = tid >> 5, lane = tid & 31;
    int g = lane >> 2, r = lane & 3;
    int lrow = lane & 15, lhi = lane >> 4;
    int bh = blockIdx.y;
    int b = bh >> 4, h = bh & 15;
    int q0 = blockIdx.x * 128;

    const int NIT = Ntok / 64;

    auto loadKV = [&](int s, int n0) {
        uint32_t kS = kBase + s * FKV_U32 * 4;
        uint32_t vS = vBase + s * FKV_U32 * 4;
        #pragma unroll
        for (int i = 0; i < 2; i++) {
            int j = tid + i * 256;
            int key = j >> 3, seg = j & 7;
            const __half* kp = qkv + (size_t)(b * Ntok + n0 + key) * 3 * Hdim
                               + Hdim + h * HD + seg * 8;
            CP_ASYNC16(kS + key * 144 + seg * 16, kp);
            CP_ASYNC16(vS + key * 144 + seg * 16, kp + Hdim);
        }
    };

    loadKV(0, 0); CP_COMMIT();
    loadKV(1, 64); CP_COMMIT();

    #pragma unroll
    for (int i = 0; i < 4; i++) {
        int j = tid + i * 256;
        int row = j >> 3, d8 = (j & 7) * 8;
        uint4 v = *(const uint4*)(qkv + (size_t)(b * Ntok + q0 + row) * 3 * Hdim
                                  + h * HD + d8);
        *(uint4*)&Ps2[row * PSTR2 + (j & 7) * 4] = v;
    }
    __syncthreads();

    int qrow = warp * 16 + g;
    unsigned qf[4][4];
    #pragma unroll
    for (int ks = 0; ks < 4; ks++) {
        qf[ks][0] = Ps2[qrow * PSTR2 + ks * 8 + r];
        qf[ks][1] = Ps2[(qrow + 8) * PSTR2 + ks * 8 + r];
        qf[ks][2] = Ps2[qrow * PSTR2 + ks * 8 + r + 4];
        qf[ks][3] = Ps2[(qrow + 8) * PSTR2 + ks * 8 + r + 4];
    }

    // LDSM address pieces for K (B-operand, non-trans): lanes grouped by 8
    int kgrp = lane >> 3, krow = lane & 7;

    float oacc[8][4] = {};
    float m0 = -1e30f, m1 = -1e30f, l0 = 0.0f, l1 = 0.0f;

    for (int it = 0; it < NIT; it++) {
        int s = it % 3;
        CP_WAIT1();
        __syncthreads();
        if (it + 2 < NIT) loadKV((it + 2) % 3, (it + 2) * 64);
        CP_COMMIT();

        uint32_t kS = kBase + s * FKV_U32 * 4;
        uint32_t vS = vBase + s * FKV_U32 * 4;

        // ---- S = Q K^T (K fragments via ldmatrix.x4 non-trans) ----
        float sacc[8][4] = {};
        #pragma unroll
        for (int ks = 0; ks < 4; ks++) {
            #pragma unroll
            for (int njp = 0; njp < 4; njp++) {
                int nj = njp * 2 + (kgrp >> 1);
                int key = nj * 8 + krow;
                uint32_t kaddr = kS + key * 144 + (ks * 8 + (kgrp & 1) * 4) * 4;
                unsigned b0, b1, b2, b3;
                LDSM4(b0, b1, b2, b3, kaddr);
                unsigned bf0[2] = {b0, b1}, bf1[2] = {b2, b3};
                mma_f16(sacc[njp * 2 + 0], qf[ks], bf0);
                mma_f16(sacc[njp * 2 + 1], qf[ks], bf1);
            }
        }

        // ---- online softmax, P packed into mma A-fragments ----
        float mc0 = -1e30f, mc1 = -1e30f;
        #pragma unroll
        for (int nj = 0; nj < 8; nj++) {
            mc0 = fmaxf(mc0, fmaxf(sacc[nj][0], sacc[nj][1]));
            mc1 = fmaxf(mc1, fmaxf(sacc[nj][2], sacc[nj][3]));
        }
        mc0 = fmaxf(mc0, __shfl_xor_sync(0xffffffffu, mc0, 1));
        mc0 = fmaxf(mc0, __shfl_xor_sync(0xffffffffu, mc0, 2));
        mc1 = fmaxf(mc1, __shfl_xor_sync(0xffffffffu, mc1, 1));
        mc1 = fmaxf(mc1, __shfl_xor_sync(0xffffffffu, mc1, 2));
        float mn0 = fmaxf(m0, mc0), mn1 = fmaxf(m1, mc1);
        float a0 = __expf(m0 - mn0), a1 = __expf(m1 - mn1);
        float rs0 = 0.0f, rs1 = 0.0f;
        unsigned ph[8][2];
        #pragma unroll
        for (int nj = 0; nj < 8; nj++) {
            float p0 = __expf(sacc[nj][0] - mn0);
            float p1 = __expf(sacc[nj][1] - mn0);
            float p2 = __expf(sacc[nj][2] - mn1);
            float p3 = __expf(sacc[nj][3] - mn1);
            rs0 += p0 + p1; rs1 += p2 + p3;
            ph[nj][0] = f2h2(p0, p1);
            ph[nj][1] = f2h2(p2, p3);
        }
        rs0 += __shfl_xor_sync(0xffffffffu, rs0, 1);
        rs0 += __shfl_xor_sync(0xffffffffu, rs0, 2);
        rs1 += __shfl_xor_sync(0xffffffffu, rs1, 1);
        rs1 += __shfl_xor_sync(0xffffffffu, rs1, 2);
        l0 = l0 * a0 + rs0;
        l1 = l1 * a1 + rs1;
        m0 = mn0; m1 = mn1;
        #pragma unroll
        for (int nj = 0; nj < 8; nj++) {
            oacc[nj][0] *= a0; oacc[nj][1] *= a0;
            oacc[nj][2] *= a1; oacc[nj][3] *= a1;
        }

        // ---- O += P V  (P registers, V via LDSM4T) ----
        #pragma unroll
        for (int ks = 0; ks < 4; ks++) {
            unsigned af[4], bf[8][2];
            af[0] = ph[2 * ks][0];
            af[1] = ph[2 * ks][1];
            af[2] = ph[2 * ks + 1][0];
            af[3] = ph[2 * ks + 1][1];
            #pragma unroll
            for (int p = 0; p < 4; p++) {
                uint32_t vAddr = vS + ((ks * 16 + lrow) * KVW + p * 8 + lhi * 4) * 4;
                LDSM4T(bf[2 * p][0], bf[2 * p][1], bf[2 * p + 1][0], bf[2 * p + 1][1], vAddr);
            }
            #pragma unroll
            for (int nj = 0; nj < 8; nj++)
                mma_f16(oacc[nj], af, bf[nj]);
        }
    }

    float i0 = 1.0f / l0, i1 = 1.0f / l1;
    #pragma unroll
    for (int nj = 0; nj < 8; nj++) {
        int col = h * HD + nj * 8 + 2 * r;
        *(unsigned*)&out[(size_t)(b * Ntok + q0 + qrow) * Hdim + col]
            = f2h2(oacc[nj][0] * i0, oacc[nj][1] * i0);
        *(unsigned*)&out[(size_t)(b * Ntok + q0 + qrow + 8) * Hdim + col]
            = f2h2(oacc[nj][2] * i1, oacc[nj][3] * i1);
    }
}

// ------------------------- launch ------------------------------------------
extern "C" void kernel_launch(void* const* d_in, const int* in_sizes, int n_in,
                              void* d_out, int out_size)
{
    const float* x      = (const float*)d_in[0];
    const float* c      = (const float*)d_in[1];
    const float* w_mod  = (const float*)d_in[2];
    const float* b_mod  = (const float*)d_in[3];
    const float* w_qkv  = (const float*)d_in[4];
    const float* b_qkv  = (const float*)d_in[5];
    const float* w_proj = (const float*)d_in[6];
    const float* b_proj = (const float*)d_in[7];
    const float* w1     = (const float*)d_in[8];
    const float* b1     = (const float*)d_in[9];
    const float* w2     = (const float*)d_in[10];
    const float* b2     = (const float*)d_in[11];
    float* out = (float*)d_out;

    float *cm, *cpart, *x2;
    __half *xmh, *qkvh, *attnh, *xm2h, *hidh, *wqkvH, *w1H, *w2H, *wpH;
    cudaGetSymbolAddress((void**)&cm,    g_cm);
    cudaGetSymbolAddress((void**)&cpart, g_cpart);
    cudaGetSymbolAddress((void**)&xmh,   g_xmh);
    cudaGetSymbolAddress((void**)&qkvh,  g_qkvh);
    cudaGetSymbolAddress((void**)&attnh, g_attnh);
    cudaGetSymbolAddress((void**)&x2,    g_x2);
    cudaGetSymbolAddress((void**)&xm2h,  g_xm2h);
    cudaGetSymbolAddress((void**)&hidh,  g_hidh);
    cudaGetSymbolAddress((void**)&wqkvH, g_wqkvH);
    cudaGetSymbolAddress((void**)&w1H,   g_w1H);
    cudaGetSymbolAddress((void**)&w2H,   g_w2H);
    cudaGetSymbolAddress((void**)&wpH,   g_wpH);

    cudaFuncSetAttribute(gemm_h<0>, cudaFuncAttributeMaxDynamicSharedMemorySize, GSMEM2);
    cudaFuncSetAttribute(gemm_h<1>, cudaFuncAttributeMaxDynamicSharedMemorySize, GSMEM2);
    cudaFuncSetAttribute(gemm_h<2>, cudaFuncAttributeMaxDynamicSharedMemorySize, GSMEM2);
    cudaFuncSetAttribute(gemm_h<3>, cudaFuncAttributeMaxDynamicSharedMemorySize, GSMEM2);
    cudaFuncSetAttribute(flash_attn, cudaFuncAttributeMaxDynamicSharedMemorySize, FSMEM);

    // 0. all weight conversions, one kernel, 2 float4s per thread
    whalf_all_kernel<<<HALF_F4 / 256, 256>>>(
        w_qkv, w1, w2, w_proj, wqkvH, w1H, w2H, wpH);

    // 1. conditioning -> modulation params (split-K)
    cond_part_kernel<<<dim3(24, 4, 8), 256>>>(c, w_mod, cpart);
    cond_reduce_kernel<<<dim3(24, 4), 256>>>(cpart, b_mod, cm);

    // 2. LN + modulate (msa) -> half
    ln_mod_h_kernel<<<ROWS / 2, 256>>>(x, cm, 0, Hdim, xmh);

    // 3. qkv (half out, Q pre-scaled by 1/8)
    gemm_h<0><<<dim3(3 * Hdim / 128, ROWS / 128), 256, GSMEM2>>>(
        xmh, wqkvH, b_qkv, qkvh, ROWS, 3 * Hdim, Hdim, nullptr, nullptr);

    // 4. flash attention -> half attnout
    flash_attn<<<dim3(Ntok / 128, Bsz * NH), 256, FSMEM>>>(qkvh, attnh);

    // 5. x2 = (attnout @ w_proj + b_proj) * (1 + gate_msa)   (float out)
    gemm_h<2><<<dim3(Hdim / 128, ROWS / 128), 256, GSMEM2>>>(
        attnh, wpH, b_proj, x2, ROWS, Hdim, Hdim, cm + 2 * Hdim, nullptr);

    // 6. LN + modulate (mlp) -> half
    ln_mod_h_kernel<<<ROWS / 2, 256>>>(x2, cm, 3 * Hdim, 4 * Hdim, xm2h);

    // 7. hid = gelu(xm2 @ w1 + b1)  (half out)
    gemm_h<1><<<dim3(DFF / 128, ROWS / 128), 256, GSMEM2>>>(
        xm2h, w1H, b1, hidh, ROWS, DFF, Hdim, nullptr, nullptr);

    // 8. out = x2 + gate_mlp * (hid @ w2 + b2)  (float out)
    gemm_h<3><<<dim3(Hdim / 128, ROWS / 128), 256, GSMEM2>>>(
        hidh, w2H, b2, out, ROWS, Hdim, DFF, cm + 5 * Hdim, x2);
}